// round 2
// baseline (speedup 1.0000x reference)
#include <cuda_runtime.h>
#include <math.h>

// Problem constants
#define BATCH 2
#define NSEQ  2048
#define DIMF  1024
#define NH    16
#define HD    64
#define MROWS (BATCH * NSEQ)   // 4096

// Scratch (allocation-free rule: __device__ globals)
__device__ float g_q[BATCH * NH * NSEQ * HD];
__device__ float g_k[BATCH * NH * NSEQ * HD];
__device__ float g_v[BATCH * NH * NSEQ * HD];
__device__ float g_o[BATCH * NH * NSEQ * HD];

// ============================================================================
// Fused QKV SGEMM (NT): for z = blockIdx.z in {0,1,2}:
//   C_z[M,N] = x[M,K] * W_z[N,K]^T, scattered to g_q/g_k/g_v in [B,H,N,HD].
// 128x128 block tile, BK=8, 256 threads, 8x8 per thread, register prefetch.
// ============================================================================
__global__ void __launch_bounds__(256) qkv_gemm_kernel(
    const float* __restrict__ A,
    const float* __restrict__ Wq,
    const float* __restrict__ Wk,
    const float* __restrict__ Wv)
{
    const int K = DIMF;
    __shared__ float As[8][128];
    __shared__ float Bs[8][128];

    const float* B = (blockIdx.z == 0) ? Wq : (blockIdx.z == 1) ? Wk : Wv;
    float* Cdst    = (blockIdx.z == 0) ? g_q : (blockIdx.z == 1) ? g_k : g_v;

    const int tid = threadIdx.x;
    const int m0 = blockIdx.y * 128;
    const int n0 = blockIdx.x * 128;
    const int ty = tid >> 4;        // 0..15
    const int tx = tid & 15;        // 0..15

    const int arow = tid >> 1;      // 0..127
    const int akc  = (tid & 1) * 4; // 0 or 4

    float acc[8][8];
#pragma unroll
    for (int i = 0; i < 8; i++)
#pragma unroll
        for (int j = 0; j < 8; j++) acc[i][j] = 0.0f;

    float4 ra = *(const float4*)(A + (size_t)(m0 + arow) * K + akc);
    float4 rb = *(const float4*)(B + (size_t)(n0 + arow) * K + akc);

    const int NKT = K / 8;
    for (int kt = 0; kt < NKT; kt++) {
        As[akc + 0][arow] = ra.x;
        As[akc + 1][arow] = ra.y;
        As[akc + 2][arow] = ra.z;
        As[akc + 3][arow] = ra.w;
        Bs[akc + 0][arow] = rb.x;
        Bs[akc + 1][arow] = rb.y;
        Bs[akc + 2][arow] = rb.z;
        Bs[akc + 3][arow] = rb.w;
        __syncthreads();

        if (kt + 1 < NKT) {
            int k0 = (kt + 1) * 8;
            ra = *(const float4*)(A + (size_t)(m0 + arow) * K + k0 + akc);
            rb = *(const float4*)(B + (size_t)(n0 + arow) * K + k0 + akc);
        }

#pragma unroll
        for (int kk = 0; kk < 8; kk++) {
            float a[8], bq[8];
            *(float4*)&a[0]  = *(float4*)&As[kk][ty * 4];
            *(float4*)&a[4]  = *(float4*)&As[kk][64 + ty * 4];
            *(float4*)&bq[0] = *(float4*)&Bs[kk][tx * 4];
            *(float4*)&bq[4] = *(float4*)&Bs[kk][64 + tx * 4];
#pragma unroll
            for (int i = 0; i < 8; i++)
#pragma unroll
                for (int j = 0; j < 8; j++)
                    acc[i][j] += a[i] * bq[j];
        }
        __syncthreads();
    }

#pragma unroll
    for (int ih = 0; ih < 2; ih++) {
#pragma unroll
        for (int i = 0; i < 4; i++) {
            int m = m0 + ih * 64 + ty * 4 + i;
            int b = m >> 11, n = m & (NSEQ - 1);
#pragma unroll
            for (int jh = 0; jh < 2; jh++) {
                int c = n0 + jh * 64 + tx * 4;
                int h = c >> 6, d = c & (HD - 1);
                float4 vv = make_float4(acc[ih * 4 + i][jh * 4 + 0],
                                        acc[ih * 4 + i][jh * 4 + 1],
                                        acc[ih * 4 + i][jh * 4 + 2],
                                        acc[ih * 4 + i][jh * 4 + 3]);
                float* dst = Cdst + (((size_t)(b * NH + h) * NSEQ + n) << 6) + d;
                *(float4*)dst = vv;
            }
        }
    }
}

// ============================================================================
// Output SGEMM (NT): out[M,N] = gather(g_o)[M,K] * Wo[N,K]^T + bo
// ============================================================================
__global__ void __launch_bounds__(256) out_gemm_kernel(
    const float* __restrict__ B,
    const float* __restrict__ bias,
    float* __restrict__ Cout)
{
    const int K = DIMF;
    __shared__ float As[8][128];
    __shared__ float Bs[8][128];

    const int tid = threadIdx.x;
    const int m0 = blockIdx.y * 128;
    const int n0 = blockIdx.x * 128;
    const int ty = tid >> 4;
    const int tx = tid & 15;

    const int arow = tid >> 1;
    const int akc  = (tid & 1) * 4;

    auto loadA = [&](int k0) -> float4 {
        int m = m0 + arow;
        int b = m >> 11, n = m & (NSEQ - 1);
        int k = k0 + akc;
        int h = k >> 6, d = k & (HD - 1);
        const float* p = g_o + (((size_t)(b * NH + h) * NSEQ + n) << 6) + d;
        return *(const float4*)p;
    };

    float acc[8][8];
#pragma unroll
    for (int i = 0; i < 8; i++)
#pragma unroll
        for (int j = 0; j < 8; j++) acc[i][j] = 0.0f;

    float4 ra = loadA(0);
    float4 rb = *(const float4*)(B + (size_t)(n0 + arow) * K + akc);

    const int NKT = K / 8;
    for (int kt = 0; kt < NKT; kt++) {
        As[akc + 0][arow] = ra.x;
        As[akc + 1][arow] = ra.y;
        As[akc + 2][arow] = ra.z;
        As[akc + 3][arow] = ra.w;
        Bs[akc + 0][arow] = rb.x;
        Bs[akc + 1][arow] = rb.y;
        Bs[akc + 2][arow] = rb.z;
        Bs[akc + 3][arow] = rb.w;
        __syncthreads();

        if (kt + 1 < NKT) {
            int k0 = (kt + 1) * 8;
            ra = loadA(k0);
            rb = *(const float4*)(B + (size_t)(n0 + arow) * K + k0 + akc);
        }

#pragma unroll
        for (int kk = 0; kk < 8; kk++) {
            float a[8], bq[8];
            *(float4*)&a[0]  = *(float4*)&As[kk][ty * 4];
            *(float4*)&a[4]  = *(float4*)&As[kk][64 + ty * 4];
            *(float4*)&bq[0] = *(float4*)&Bs[kk][tx * 4];
            *(float4*)&bq[4] = *(float4*)&Bs[kk][64 + tx * 4];
#pragma unroll
            for (int i = 0; i < 8; i++)
#pragma unroll
                for (int j = 0; j < 8; j++)
                    acc[i][j] += a[i] * bq[j];
        }
        __syncthreads();
    }

#pragma unroll
    for (int ih = 0; ih < 2; ih++) {
#pragma unroll
        for (int i = 0; i < 4; i++) {
            int m = m0 + ih * 64 + ty * 4 + i;
#pragma unroll
            for (int jh = 0; jh < 2; jh++) {
                int c = n0 + jh * 64 + tx * 4;
                float4 bb4 = *(const float4*)(bias + c);
                float4 vv = make_float4(acc[ih * 4 + i][jh * 4 + 0] + bb4.x,
                                        acc[ih * 4 + i][jh * 4 + 1] + bb4.y,
                                        acc[ih * 4 + i][jh * 4 + 2] + bb4.z,
                                        acc[ih * 4 + i][jh * 4 + 3] + bb4.w);
                *(float4*)(Cout + (size_t)m * DIMF + c) = vv;
            }
        }
    }
}

// ============================================================================
// RMSNorm (per 64-elem head vector) + interleaved RoPE, in place on g_q / g_k.
// One warp per row; lane handles the RoPE pair (2*lane, 2*lane+1).
// ============================================================================
__global__ void __launch_bounds__(256) rmsrope_kernel()
{
    const int warp = threadIdx.x >> 5;
    const int lane = threadIdx.x & 31;
    const size_t row = (size_t)blockIdx.x * 8 + warp;   // 0 .. B*H*N-1
    float* ptr = (blockIdx.y == 0 ? g_q : g_k) + row * HD;

    float2 x = *(float2*)(ptr + lane * 2);
    float ss = x.x * x.x + x.y * x.y;
#pragma unroll
    for (int off = 16; off; off >>= 1)
        ss += __shfl_xor_sync(0xffffffffu, ss, off);
    float rn = rsqrtf(ss * (1.0f / 64.0f) + 1e-5f);

    int pos = (int)(row & (NSEQ - 1));
    // inv_freq = 10000^(-(2*lane)/64)  (fp32, matching reference)
    float ifr = exp2f((float)lane * (-2.0f / 64.0f) * 13.287712379549449f);
    float ang = (float)pos * ifr;
    float s, c;
    sincosf(ang, &s, &c);

    float x0 = x.x * rn, x1 = x.y * rn;
    float2 y;
    y.x = x0 * c - x1 * s;
    y.y = x1 * c + x0 * s;
    *(float2*)(ptr + lane * 2) = y;
}

// ============================================================================
// Flash attention, fp32. Br=64 query rows per block, Bc=32 key cols per tile.
// 256 threads: ty=tid/16 owns rows ty*4..+3; tx=tid%16 owns S-cols tx*2..+1
// and O-cols tx*4..+3. Softmax reductions stay inside 16-lane half-warps.
// ============================================================================
__global__ void __launch_bounds__(256) flash_kernel(const float* __restrict__ mask)
{
    __shared__ float Qts[HD][68];   // [kk][r]  (transposed Q tile)
    __shared__ float Kt[HD][32];    // [kk][j]  (transposed K tile)
    __shared__ float Vs[32][HD];    // [j][d]
    __shared__ float Pts[32][68];   // [j][r]   (transposed P tile)

    const int tid = threadIdx.x;
    const int bh = blockIdx.y;            // 0..31
    const int b = bh >> 4;
    const int q0 = blockIdx.x * 64;

    const float* Qg = g_q + ((size_t)bh * NSEQ + q0) * HD;
    const float* Kg = g_k + (size_t)bh * NSEQ * HD;
    const float* Vg = g_v + (size_t)bh * NSEQ * HD;
    const float* Mg = mask + (size_t)b * NSEQ * NSEQ + (size_t)q0 * NSEQ;

    // Load Q tile transposed: Qts[kk][r]
    for (int l = tid; l < 64 * 16; l += 256) {
        int r = l >> 4;
        int kk = (l & 15) << 2;
        float4 v = *(const float4*)(Qg + r * HD + kk);
        Qts[kk + 0][r] = v.x;
        Qts[kk + 1][r] = v.y;
        Qts[kk + 2][r] = v.z;
        Qts[kk + 3][r] = v.w;
    }

    const int ty = tid >> 4;
    const int tx = tid & 15;
    const float scale = 1.0f / (float)HD;

    float m_i[4], l_i[4], o[4][4];
#pragma unroll
    for (int i = 0; i < 4; i++) {
        m_i[i] = -INFINITY;
        l_i[i] = 0.0f;
#pragma unroll
        for (int j = 0; j < 4; j++) o[i][j] = 0.0f;
    }

    for (int kt = 0; kt < NSEQ / 32; kt++) {
        const int k0 = kt * 32;
        __syncthreads();
        // Load K tile transposed: Kt[kk][j]
        for (int l = tid; l < 32 * 16; l += 256) {
            int j = l >> 4;
            int kk = (l & 15) << 2;
            float4 v = *(const float4*)(Kg + (size_t)(k0 + j) * HD + kk);
            Kt[kk + 0][j] = v.x;
            Kt[kk + 1][j] = v.y;
            Kt[kk + 2][j] = v.z;
            Kt[kk + 3][j] = v.w;
        }
        // Load V tile direct: Vs[j][d]
        for (int l = tid; l < 32 * 16; l += 256) {
            int j = l >> 4;
            int d = (l & 15) << 2;
            *(float4*)&Vs[j][d] = *(const float4*)(Vg + (size_t)(k0 + j) * HD + d);
        }
        __syncthreads();

        // S = Q K^T  (64x32), per-thread 4x2 micro-tile
        float s[4][2];
#pragma unroll
        for (int i = 0; i < 4; i++) { s[i][0] = 0.0f; s[i][1] = 0.0f; }
#pragma unroll
        for (int kk = 0; kk < 64; kk++) {
            float4 a = *(float4*)&Qts[kk][ty * 4];
            float2 bb = *(float2*)&Kt[kk][tx * 2];
            s[0][0] += a.x * bb.x; s[0][1] += a.x * bb.y;
            s[1][0] += a.y * bb.x; s[1][1] += a.y * bb.y;
            s[2][0] += a.z * bb.x; s[2][1] += a.z * bb.y;
            s[3][0] += a.w * bb.x; s[3][1] += a.w * bb.y;
        }

        // mask + scale + online softmax (per row, within 16-lane half-warp)
#pragma unroll
        for (int i = 0; i < 4; i++) {
            int r = ty * 4 + i;
            float2 mk = *(const float2*)(Mg + (size_t)r * NSEQ + k0 + tx * 2);
            float s0 = s[i][0] * scale + mk.x;
            float s1 = s[i][1] * scale + mk.y;
            float tmax = fmaxf(s0, s1);
#pragma unroll
            for (int off = 8; off; off >>= 1)
                tmax = fmaxf(tmax, __shfl_xor_sync(0xffffffffu, tmax, off, 16));
            float mnew = fmaxf(m_i[i], tmax);
            float p0 = __expf(s0 - mnew);
            float p1 = __expf(s1 - mnew);
            float ps = p0 + p1;
#pragma unroll
            for (int off = 8; off; off >>= 1)
                ps += __shfl_xor_sync(0xffffffffu, ps, off, 16);
            float corr = __expf(m_i[i] - mnew);
            l_i[i] = l_i[i] * corr + ps;
            m_i[i] = mnew;
            o[i][0] *= corr; o[i][1] *= corr; o[i][2] *= corr; o[i][3] *= corr;
            Pts[tx * 2 + 0][r] = p0;
            Pts[tx * 2 + 1][r] = p1;
        }
        __syncwarp();

        // O += P V  (64x64 += 64x32 * 32x64), per-thread 4x4
#pragma unroll
        for (int j = 0; j < 32; j++) {
            float4 a = *(float4*)&Pts[j][ty * 4];
            float4 v = *(float4*)&Vs[j][tx * 4];
            o[0][0] += a.x * v.x; o[0][1] += a.x * v.y; o[0][2] += a.x * v.z; o[0][3] += a.x * v.w;
            o[1][0] += a.y * v.x; o[1][1] += a.y * v.y; o[1][2] += a.y * v.z; o[1][3] += a.y * v.w;
            o[2][0] += a.z * v.x; o[2][1] += a.z * v.y; o[2][2] += a.z * v.z; o[2][3] += a.z * v.w;
            o[3][0] += a.w * v.x; o[3][1] += a.w * v.y; o[3][2] += a.w * v.z; o[3][3] += a.w * v.w;
        }
    }

    // Final normalize + store to g_o ([B,H,N,HD])
    float* Og = g_o + ((size_t)bh * NSEQ + q0) * HD;
#pragma unroll
    for (int i = 0; i < 4; i++) {
        float inv = 1.0f / l_i[i];
        float4 vv = make_float4(o[i][0] * inv, o[i][1] * inv, o[i][2] * inv, o[i][3] * inv);
        *(float4*)(Og + (size_t)(ty * 4 + i) * HD + tx * 4) = vv;
    }
}

// ============================================================================
// Launch
// ============================================================================
extern "C" void kernel_launch(void* const* d_in, const int* in_sizes, int n_in,
                              void* d_out, int out_size)
{
    const float* x    = (const float*)d_in[0];
    const float* mask = (const float*)d_in[1];
    const float* Wq   = (const float*)d_in[2];
    const float* Wk   = (const float*)d_in[3];
    const float* Wv   = (const float*)d_in[4];
    const float* Wo   = (const float*)d_in[5];
    const float* bo   = (const float*)d_in[6];
    float* out = (float*)d_out;

    qkv_gemm_kernel<<<dim3(DIMF / 128, MROWS / 128, 3), 256>>>(x, Wq, Wk, Wv);

    rmsrope_kernel<<<dim3((BATCH * NH * NSEQ) / 8, 2), 256>>>();

    flash_kernel<<<dim3(NSEQ / 64, BATCH * NH), 256>>>(mask);

    out_gemm_kernel<<<dim3(DIMF / 128, MROWS / 128), 256>>>(Wo, bo, out);
}

// round 3
// speedup vs baseline: 1.5170x; 1.5170x over previous
#include <cuda_runtime.h>
#include <math.h>
#include <stdint.h>

#define BATCH 2
#define NSEQ  2048
#define DIMF  1024
#define NH    16
#define HD    64
#define MROWS (BATCH * NSEQ)   // 4096

// Scratch (__device__ globals per allocation rules)
__device__ float g_q [BATCH * NH * NSEQ * HD];
__device__ float g_k [BATCH * NH * NSEQ * HD];
__device__ float g_vt[BATCH * NH * HD * NSEQ];   // V TRANSPOSED: [b,h,d,seq]
__device__ float g_o [BATCH * NH * NSEQ * HD];

// ---------------------------------------------------------------------------
// helpers
// ---------------------------------------------------------------------------
__device__ __forceinline__ float tf32r(float x) {           // round-to-nearest tf32
    uint32_t u;
    asm("cvt.rna.tf32.f32 %0, %1;" : "=r"(u) : "f"(x));
    return __uint_as_float(u);
}
__device__ __forceinline__ uint32_t saddr(const void* p) {
    return (uint32_t)__cvta_generic_to_shared(p);
}
__device__ __forceinline__ void ldsm_x4(uint32_t r[4], uint32_t a) {
    asm volatile("ldmatrix.sync.aligned.m8n8.x4.shared.b16 {%0,%1,%2,%3}, [%4];"
                 : "=r"(r[0]), "=r"(r[1]), "=r"(r[2]), "=r"(r[3]) : "r"(a));
}
__device__ __forceinline__ void mma8(float c[4], const uint32_t a[4], const uint32_t b[2]) {
    asm volatile(
        "mma.sync.aligned.m16n8k8.row.col.f32.tf32.tf32.f32 "
        "{%0,%1,%2,%3}, {%4,%5,%6,%7}, {%8,%9}, {%0,%1,%2,%3};"
        : "+f"(c[0]), "+f"(c[1]), "+f"(c[2]), "+f"(c[3])
        : "r"(a[0]), "r"(a[1]), "r"(a[2]), "r"(a[3]), "r"(b[0]), "r"(b[1]));
}

// ---------------------------------------------------------------------------
// 3xTF32 GEMM (NT): C[M,N] = A[M,K] * W[N,K]^T
//  OUT=0: fused QKV (blockIdx.z selects W/dst); scatter to g_q/g_k/g_vt.
//  OUT=1: gather A from g_o; C = out + bias.
// CTA 128x128, BK=16, 256 thr (8 warps, 4x2 of 32x64), m16n8k8 tf32 mma.
// ---------------------------------------------------------------------------
template <int OUT>
__global__ void __launch_bounds__(256) gemm_tf32(
    const float* __restrict__ A,
    const float* __restrict__ W0, const float* __restrict__ W1,
    const float* __restrict__ W2,
    const float* __restrict__ bias, float* __restrict__ Cout)
{
    __shared__ float AsH[128][20], AsL[128][20], BsH[128][20], BsL[128][20];

    const int tid  = threadIdx.x;
    const int warp = tid >> 5, lane = tid & 31;
    const int m0 = blockIdx.y * 128, n0 = blockIdx.x * 128;
    const int z  = OUT ? 3 : blockIdx.z;
    const float* W = (z == 1) ? W1 : (z == 2) ? W2 : W0;

    const int mw = (warp >> 1) * 32;
    const int nw = (warp & 1) * 64;

    const int lr0 = tid >> 2;          // 0..63
    const int lc4 = (tid & 3) * 4;     // 0,4,8,12

    float4 pa[2], pb[2];
    auto fetchA = [&](int kb, int it) -> float4 {
        int r = lr0 + it * 64;
        if (!OUT) return *(const float4*)(A + (size_t)(m0 + r) * DIMF + kb + lc4);
        int m = m0 + r; int bb = m >> 11, n = m & (NSEQ - 1);
        int k = kb + lc4; int h = k >> 6, d = k & (HD - 1);
        return *(const float4*)(g_o + (((size_t)(bb * NH + h) * NSEQ + n) << 6) + d);
    };
    auto fetchB = [&](int kb, int it) -> float4 {
        int r = lr0 + it * 64;
        return *(const float4*)(W + (size_t)(n0 + r) * DIMF + kb + lc4);
    };

    float acc[2][8][4];
#pragma unroll
    for (int i = 0; i < 2; i++)
#pragma unroll
        for (int j = 0; j < 8; j++)
#pragma unroll
            for (int l = 0; l < 4; l++) acc[i][j][l] = 0.0f;

    pa[0] = fetchA(0, 0); pa[1] = fetchA(0, 1);
    pb[0] = fetchB(0, 0); pb[1] = fetchB(0, 1);

    const int NKT = DIMF / 16;   // 64
    for (int kt = 0; kt < NKT; kt++) {
#pragma unroll
        for (int it = 0; it < 2; it++) {
            int r = lr0 + it * 64;
            float va[4] = {pa[it].x, pa[it].y, pa[it].z, pa[it].w};
            float vb[4] = {pb[it].x, pb[it].y, pb[it].z, pb[it].w};
#pragma unroll
            for (int j = 0; j < 4; j++) {
                float h = tf32r(va[j]);
                AsH[r][lc4 + j] = h;
                AsL[r][lc4 + j] = tf32r(va[j] - h);
                h = tf32r(vb[j]);
                BsH[r][lc4 + j] = h;
                BsL[r][lc4 + j] = tf32r(vb[j] - h);
            }
        }
        __syncthreads();

        if (kt + 1 < NKT) {
            int kb = (kt + 1) * 16;
            pa[0] = fetchA(kb, 0); pa[1] = fetchA(kb, 1);
            pb[0] = fetchB(kb, 0); pb[1] = fetchB(kb, 1);
        }

#pragma unroll
        for (int ks = 0; ks < 2; ks++) {
            const int k0 = ks * 8;
            uint32_t ah[2][4], al[2][4];
#pragma unroll
            for (int mt = 0; mt < 2; mt++) {
                int row = mw + mt * 16 + (lane & 15);
                int col = k0 + ((lane >> 4) << 2);
                ldsm_x4(ah[mt], saddr(&AsH[row][col]));
                ldsm_x4(al[mt], saddr(&AsL[row][col]));
            }
            uint32_t bh[8][2], bl[8][2];
#pragma unroll
            for (int p = 0; p < 4; p++) {
                int row = nw + p * 16 + (lane & 7) + ((lane >> 4) << 3);
                int col = k0 + (((lane >> 3) & 1) << 2);
                uint32_t r4[4];
                ldsm_x4(r4, saddr(&BsH[row][col]));
                bh[2 * p][0] = r4[0]; bh[2 * p][1] = r4[1];
                bh[2 * p + 1][0] = r4[2]; bh[2 * p + 1][1] = r4[3];
                ldsm_x4(r4, saddr(&BsL[row][col]));
                bl[2 * p][0] = r4[0]; bl[2 * p][1] = r4[1];
                bl[2 * p + 1][0] = r4[2]; bl[2 * p + 1][1] = r4[3];
            }
#pragma unroll
            for (int mt = 0; mt < 2; mt++)
#pragma unroll
                for (int nt = 0; nt < 8; nt++) {
                    mma8(acc[mt][nt], ah[mt], bh[nt]);   // hi*hi
                    mma8(acc[mt][nt], ah[mt], bl[nt]);   // hi*lo
                    mma8(acc[mt][nt], al[mt], bh[nt]);   // lo*hi
                }
        }
        __syncthreads();
    }

    // epilogue
#pragma unroll
    for (int mt = 0; mt < 2; mt++) {
#pragma unroll
        for (int nt = 0; nt < 8; nt++) {
#pragma unroll
            for (int half = 0; half < 2; half++) {
                int m = m0 + mw + mt * 16 + (lane >> 2) + half * 8;
                int c = n0 + nw + nt * 8 + ((lane & 3) << 1);
                float2 v = make_float2(acc[mt][nt][half * 2 + 0],
                                       acc[mt][nt][half * 2 + 1]);
                if (OUT) {
                    const float2 bb2 = *(const float2*)(bias + c);
                    v.x += bb2.x; v.y += bb2.y;
                    *(float2*)(Cout + (size_t)m * DIMF + c) = v;
                } else {
                    int bb = m >> 11, n = m & (NSEQ - 1);
                    int h = c >> 6, d = c & (HD - 1);
                    if (z == 2) {
                        float* base = g_vt + (((size_t)(bb * NH + h) * HD + d) * NSEQ) + n;
                        base[0]    = v.x;
                        base[NSEQ] = v.y;
                    } else {
                        float* dst = (z == 0 ? g_q : g_k)
                                   + (((size_t)(bb * NH + h) * NSEQ + n) << 6) + d;
                        *(float2*)dst = v;
                    }
                }
            }
        }
    }
}

// ---------------------------------------------------------------------------
// RMSNorm + interleaved RoPE in place on g_q / g_k (one warp per 64-vector)
// ---------------------------------------------------------------------------
__global__ void __launch_bounds__(256) rmsrope_kernel()
{
    const int warp = threadIdx.x >> 5;
    const int lane = threadIdx.x & 31;
    const size_t row = (size_t)blockIdx.x * 8 + warp;
    float* ptr = (blockIdx.y == 0 ? g_q : g_k) + row * HD;

    float2 x = *(float2*)(ptr + lane * 2);
    float ss = x.x * x.x + x.y * x.y;
#pragma unroll
    for (int off = 16; off; off >>= 1)
        ss += __shfl_xor_sync(0xffffffffu, ss, off);
    float rn = rsqrtf(ss * (1.0f / 64.0f) + 1e-5f);

    int pos = (int)(row & (NSEQ - 1));
    float ifr = exp2f((float)lane * (-2.0f / 64.0f) * 13.287712379549449f);
    float ang = (float)pos * ifr;
    float s, c;
    sincosf(ang, &s, &c);

    float x0 = x.x * rn, x1 = x.y * rn;
    float2 y;
    y.x = x0 * c - x1 * s;
    y.y = x1 * c + x0 * s;
    *(float2*)(ptr + lane * 2) = y;
}

// ---------------------------------------------------------------------------
// Flash attention, tf32 mma. CTA: 128 q-rows, 8 warps (16 rows each).
// K-tiles of 64. S = Q K^T (B = g_k, k-major ok); PV uses g_vt (d-major).
// Dynamic smem: Ks[64][68] | Vts[64][68] | Ps[128][68] (Q stage / P stage)
// ---------------------------------------------------------------------------
__global__ void __launch_bounds__(256) flash_tf32(const float* __restrict__ mask)
{
    extern __shared__ float sm[];
    float* Ks  = sm;                // 64*68
    float* Vts = sm + 64 * 68;      // 64*68
    float* Ps  = sm + 2 * 64 * 68;  // 128*68

    const int tid = threadIdx.x, warp = tid >> 5, lane = tid & 31;
    const int bh = blockIdx.y, b = bh >> 4;
    const int q0 = blockIdx.x * 128;

    const float* Qg  = g_q  + ((size_t)bh * NSEQ + q0) * HD;
    const float* Kg  = g_k  + (size_t)bh * NSEQ * HD;
    const float* Vtg = g_vt + (size_t)bh * HD * NSEQ;
    const float* Mg  = mask + (size_t)b * NSEQ * NSEQ + (size_t)q0 * NSEQ;

    // stage Q (tf32-rounded)
#pragma unroll
    for (int i = 0; i < 8; i++) {
        int r = (tid >> 4) + i * 16;
        int c = (tid & 15) * 4;
        float4 v = *(const float4*)(Qg + (size_t)r * HD + c);
        float* d = Ps + r * 68 + c;
        d[0] = tf32r(v.x); d[1] = tf32r(v.y); d[2] = tf32r(v.z); d[3] = tf32r(v.w);
    }
    __syncthreads();
    uint32_t qf[8][4];
    {
        int row = warp * 16 + (lane & 15);
        int cb  = (lane >> 4) << 2;
#pragma unroll
        for (int t = 0; t < 8; t++)
            ldsm_x4(qf[t], saddr(Ps + row * 68 + t * 8 + cb));
    }
    __syncthreads();   // Ps now free for P staging

    const int r  = lane >> 2;     // fragment row in [0,8)
    const int cq = lane & 3;      // fragment col quad
    float* Pw = Ps + warp * 16 * 68;

    float mrow[2] = {-INFINITY, -INFINITY};
    float lrow[2] = {0.0f, 0.0f};
    float o[8][4];
#pragma unroll
    for (int nt = 0; nt < 8; nt++)
#pragma unroll
        for (int j = 0; j < 4; j++) o[nt][j] = 0.0f;

    const float scale = 1.0f / 64.0f;

    for (int kt = 0; kt < NSEQ / 64; kt++) {
        const int k0 = kt * 64;

        // load K and Vt tiles (tf32-rounded)
#pragma unroll
        for (int i = 0; i < 4; i++) {
            int rr = (tid >> 4) + i * 16;
            int cc = (tid & 15) * 4;
            float4 kv = *(const float4*)(Kg + (size_t)(k0 + rr) * HD + cc);
            float* dk = Ks + rr * 68 + cc;
            dk[0] = tf32r(kv.x); dk[1] = tf32r(kv.y); dk[2] = tf32r(kv.z); dk[3] = tf32r(kv.w);
            float4 vv = *(const float4*)(Vtg + (size_t)rr * NSEQ + k0 + cc);
            float* dv = Vts + rr * 68 + cc;
            dv[0] = tf32r(vv.x); dv[1] = tf32r(vv.y); dv[2] = tf32r(vv.z); dv[3] = tf32r(vv.w);
        }
        __syncthreads();

        // S = Q K^T   (per warp: 16 x 64)
        float s[8][4];
#pragma unroll
        for (int nt = 0; nt < 8; nt++)
#pragma unroll
            for (int j = 0; j < 4; j++) s[nt][j] = 0.0f;

#pragma unroll
        for (int t = 0; t < 8; t++) {        // hd steps
            uint32_t bb[8][2];
#pragma unroll
            for (int p = 0; p < 4; p++) {
                int row = p * 16 + (lane & 7) + ((lane >> 4) << 3);
                int col = t * 8 + (((lane >> 3) & 1) << 2);
                uint32_t r4[4];
                ldsm_x4(r4, saddr(Ks + row * 68 + col));
                bb[2 * p][0] = r4[0]; bb[2 * p][1] = r4[1];
                bb[2 * p + 1][0] = r4[2]; bb[2 * p + 1][1] = r4[3];
            }
#pragma unroll
            for (int nt = 0; nt < 8; nt++) mma8(s[nt], qf[t], bb[nt]);
        }

        // online softmax per row half
#pragma unroll
        for (int half = 0; half < 2; half++) {
            const float* mp = Mg + (size_t)(warp * 16 + r + half * 8) * NSEQ + k0;
            float sim[16];
            float vmax = -INFINITY;
#pragma unroll
            for (int nt = 0; nt < 8; nt++) {
                float2 mk = *(const float2*)(mp + nt * 8 + 2 * cq);
                sim[2 * nt]     = s[nt][half * 2 + 0] * scale + mk.x;
                sim[2 * nt + 1] = s[nt][half * 2 + 1] * scale + mk.y;
                vmax = fmaxf(vmax, fmaxf(sim[2 * nt], sim[2 * nt + 1]));
            }
            vmax = fmaxf(vmax, __shfl_xor_sync(0xffffffffu, vmax, 1, 4));
            vmax = fmaxf(vmax, __shfl_xor_sync(0xffffffffu, vmax, 2, 4));
            float mnew = fmaxf(mrow[half], vmax);
            float corr = __expf(mrow[half] - mnew);
            float sum = 0.0f;
#pragma unroll
            for (int nt = 0; nt < 8; nt++) {
                float p0 = __expf(sim[2 * nt]     - mnew);
                float p1 = __expf(sim[2 * nt + 1] - mnew);
                sum += p0 + p1;
                *(float2*)(Pw + (size_t)(r + half * 8) * 68 + nt * 8 + 2 * cq) =
                    make_float2(tf32r(p0), tf32r(p1));
            }
            sum += __shfl_xor_sync(0xffffffffu, sum, 1, 4);
            sum += __shfl_xor_sync(0xffffffffu, sum, 2, 4);
            lrow[half] = lrow[half] * corr + sum;
            mrow[half] = mnew;
#pragma unroll
            for (int nt = 0; nt < 8; nt++) {
                o[nt][half * 2 + 0] *= corr;
                o[nt][half * 2 + 1] *= corr;
            }
        }
        __syncwarp();

        // O += P V   (A = P 16xk64, B = Vts[d][key])
#pragma unroll
        for (int t = 0; t < 8; t++) {        // key steps
            uint32_t af[4];
            {
                int row = lane & 15;
                int col = t * 8 + ((lane >> 4) << 2);
                ldsm_x4(af, saddr(Pw + row * 68 + col));
            }
            uint32_t bb[8][2];
#pragma unroll
            for (int p = 0; p < 4; p++) {
                int row = p * 16 + (lane & 7) + ((lane >> 4) << 3);
                int col = t * 8 + (((lane >> 3) & 1) << 2);
                uint32_t r4[4];
                ldsm_x4(r4, saddr(Vts + row * 68 + col));
                bb[2 * p][0] = r4[0]; bb[2 * p][1] = r4[1];
                bb[2 * p + 1][0] = r4[2]; bb[2 * p + 1][1] = r4[3];
            }
#pragma unroll
            for (int nt = 0; nt < 8; nt++) mma8(o[nt], af, bb[nt]);
        }
        __syncthreads();
    }

    // normalize + store
    float inv0 = 1.0f / lrow[0], inv1 = 1.0f / lrow[1];
    float* Og = g_o + ((size_t)bh * NSEQ + q0 + warp * 16) * HD;
#pragma unroll
    for (int nt = 0; nt < 8; nt++) {
        int d = nt * 8 + 2 * cq;
        *(float2*)(Og + (size_t)r * HD + d) =
            make_float2(o[nt][0] * inv0, o[nt][1] * inv0);
        *(float2*)(Og + (size_t)(r + 8) * HD + d) =
            make_float2(o[nt][2] * inv1, o[nt][3] * inv1);
    }
}

// ---------------------------------------------------------------------------
// Launch
// ---------------------------------------------------------------------------
extern "C" void kernel_launch(void* const* d_in, const int* in_sizes, int n_in,
                              void* d_out, int out_size)
{
    const float* x    = (const float*)d_in[0];
    const float* mask = (const float*)d_in[1];
    const float* Wq   = (const float*)d_in[2];
    const float* Wk   = (const float*)d_in[3];
    const float* Wv   = (const float*)d_in[4];
    const float* Wo   = (const float*)d_in[5];
    const float* bo   = (const float*)d_in[6];
    float* out = (float*)d_out;

    const int FLASH_SMEM = (2 * 64 * 68 + 128 * 68) * 4;   // 69632 B
    cudaFuncSetAttribute(flash_tf32,
                         cudaFuncAttributeMaxDynamicSharedMemorySize, FLASH_SMEM);

    gemm_tf32<0><<<dim3(8, 32, 3), 256>>>(x, Wq, Wk, Wv, nullptr, nullptr);

    rmsrope_kernel<<<dim3((BATCH * NH * NSEQ) / 8, 2), 256>>>();

    flash_tf32<<<dim3(NSEQ / 128, BATCH * NH), 256, FLASH_SMEM>>>(mask);

    gemm_tf32<1><<<dim3(8, 32), 256>>>(nullptr, Wo, nullptr, nullptr, bo, out);
}

// round 5
// speedup vs baseline: 2.1616x; 1.4249x over previous
#include <cuda_runtime.h>
#include <cuda_bf16.h>
#include <math.h>
#include <stdint.h>

#define BATCH 2
#define NSEQ  2048
#define DIMF  1024
#define NH    16
#define HD    64
#define MROWS (BATCH * NSEQ)   // 4096

// fp32 scratch for attention path
__device__ float g_q [BATCH * NH * NSEQ * HD];
__device__ float g_k [BATCH * NH * NSEQ * HD];
__device__ float g_vt[BATCH * NH * HD * NSEQ];   // [b,h,d,seq]

// bf16 hi/lo split operands (row-major)
__device__ __nv_bfloat16 g_xh[(size_t)MROWS * DIMF];
__device__ __nv_bfloat16 g_xl[(size_t)MROWS * DIMF];
__device__ __nv_bfloat16 g_oh[(size_t)MROWS * DIMF];   // flash output, gathered layout
__device__ __nv_bfloat16 g_ol[(size_t)MROWS * DIMF];
__device__ __nv_bfloat16 g_wh[(size_t)4 * DIMF * DIMF];
__device__ __nv_bfloat16 g_wl[(size_t)4 * DIMF * DIMF];

// ---------------------------------------------------------------------------
// helpers
// ---------------------------------------------------------------------------
__device__ __forceinline__ uint32_t saddr(const void* p) {
    return (uint32_t)__cvta_generic_to_shared(p);
}
__device__ __forceinline__ float tf32r(float x) {
    uint32_t u;
    asm("cvt.rna.tf32.f32 %0, %1;" : "=r"(u) : "f"(x));
    return __uint_as_float(u);
}
__device__ __forceinline__ void ldsm_x4(uint32_t r[4], uint32_t a) {
    asm volatile("ldmatrix.sync.aligned.m8n8.x4.shared.b16 {%0,%1,%2,%3}, [%4];"
                 : "=r"(r[0]), "=r"(r[1]), "=r"(r[2]), "=r"(r[3]) : "r"(a));
}
// tf32 m16n8k8 (flash)
__device__ __forceinline__ void mma8(float c[4], const uint32_t a[4], const uint32_t b[2]) {
    asm volatile(
        "mma.sync.aligned.m16n8k8.row.col.f32.tf32.tf32.f32 "
        "{%0,%1,%2,%3}, {%4,%5,%6,%7}, {%8,%9}, {%0,%1,%2,%3};"
        : "+f"(c[0]), "+f"(c[1]), "+f"(c[2]), "+f"(c[3])
        : "r"(a[0]), "r"(a[1]), "r"(a[2]), "r"(a[3]), "r"(b[0]), "r"(b[1]));
}
// bf16 m16n8k16 (GEMMs)
__device__ __forceinline__ void mma16(float c[4], const uint32_t a[4], const uint32_t b[2]) {
    asm volatile(
        "mma.sync.aligned.m16n8k16.row.col.f32.bf16.bf16.f32 "
        "{%0,%1,%2,%3}, {%4,%5,%6,%7}, {%8,%9}, {%0,%1,%2,%3};"
        : "+f"(c[0]), "+f"(c[1]), "+f"(c[2]), "+f"(c[3])
        : "r"(a[0]), "r"(a[1]), "r"(a[2]), "r"(a[3]), "r"(b[0]), "r"(b[1]));
}
__device__ __forceinline__ void cpasync16(uint32_t s, const void* g) {
    asm volatile("cp.async.cg.shared.global [%0], [%1], 16;" :: "r"(s), "l"(g) : "memory");
}
#define CP_COMMIT()  asm volatile("cp.async.commit_group;" ::: "memory")
#define CP_WAIT(n)   asm volatile("cp.async.wait_group %0;" :: "n"(n) : "memory")

// ---------------------------------------------------------------------------
// Split fp32 -> bf16 hi/lo (row-major). 8192 rows of 1024: x then Wq/Wk/Wv/Wo.
// ---------------------------------------------------------------------------
__global__ void __launch_bounds__(256) conv_split(
    const float* __restrict__ x,
    const float* __restrict__ Wq, const float* __restrict__ Wk,
    const float* __restrict__ Wv, const float* __restrict__ Wo)
{
    const int row = blockIdx.x;
    const float* src;
    __nv_bfloat16 *dh, *dl;
    if (row < MROWS) {
        src = x + (size_t)row * DIMF;
        dh = g_xh + (size_t)row * DIMF;
        dl = g_xl + (size_t)row * DIMF;
    } else {
        int wi = (row - MROWS) >> 10, r = (row - MROWS) & 1023;
        const float* W = (wi == 0) ? Wq : (wi == 1) ? Wk : (wi == 2) ? Wv : Wo;
        src = W + (size_t)r * DIMF;
        dh = g_wh + ((size_t)wi * DIMF + r) * DIMF;
        dl = g_wl + ((size_t)wi * DIMF + r) * DIMF;
    }
    const int c = threadIdx.x * 4;
    float4 v = *(const float4*)(src + c);
    __nv_bfloat16 h0 = __float2bfloat16(v.x);
    __nv_bfloat16 h1 = __float2bfloat16(v.y);
    __nv_bfloat16 h2 = __float2bfloat16(v.z);
    __nv_bfloat16 h3 = __float2bfloat16(v.w);
    __nv_bfloat162 ph0; ph0.x = h0; ph0.y = h1;
    __nv_bfloat162 ph1; ph1.x = h2; ph1.y = h3;
    __nv_bfloat162 pl0; pl0.x = __float2bfloat16(v.x - __bfloat162float(h0));
    pl0.y = __float2bfloat16(v.y - __bfloat162float(h1));
    __nv_bfloat162 pl1; pl1.x = __float2bfloat16(v.z - __bfloat162float(h2));
    pl1.y = __float2bfloat16(v.w - __bfloat162float(h3));
    *(__nv_bfloat162*)(dh + c)     = ph0;
    *(__nv_bfloat162*)(dh + c + 2) = ph1;
    *(__nv_bfloat162*)(dl + c)     = pl0;
    *(__nv_bfloat162*)(dl + c + 2) = pl1;
}

// ---------------------------------------------------------------------------
// bf16 3-pass GEMM (NT): C[M,128-tile] = A[M,K] * W[N,K]^T
// CTA 128x128, BK=32, 256 threads (8 warps as 4x2, warp tile 32x64),
// 2-stage cp.async double buffer. Smem tile rows padded to 80B (conflict-free).
// OUT=0: A=x split, W=w[z] (z=blockIdx.z); scatter to g_q/g_k/g_vt.
// OUT=1: A=flash output split (already gathered), W=w[3]; out = C + bias.
// ---------------------------------------------------------------------------
#define TILE_B 10240              // 128 rows * 80 bytes
#define STAGE_B (4 * TILE_B)      // Ah, Al, Bh, Bl

template <int OUT>
__global__ void __launch_bounds__(256, 2) gemm_bf16(
    const float* __restrict__ bias, float* __restrict__ Cout)
{
    extern __shared__ char smem[];
    const uint32_t sbase = saddr(smem);
    const int tid = threadIdx.x, warp = tid >> 5, lane = tid & 31;
    const int m0 = blockIdx.y * 128, n0 = blockIdx.x * 128;
    const int z = OUT ? 3 : blockIdx.z;

    const __nv_bfloat16* Ah = OUT ? g_oh : g_xh;
    const __nv_bfloat16* Al = OUT ? g_ol : g_xl;
    const __nv_bfloat16* Bh = g_wh + (size_t)z * DIMF * DIMF;
    const __nv_bfloat16* Bl = g_wl + (size_t)z * DIMF * DIMF;

    const int lrow = tid >> 1;            // 0..127
    const int lq   = (tid & 1) * 2;       // quad 0 or 2

    auto load_stage = [&](int s) {
        const uint32_t d0 = sbase + (s & 1) * STAGE_B + lrow * 80 + lq * 16;
        const int kc = s * 32 + lq * 8;
        const __nv_bfloat16* pa = Ah + (size_t)(m0 + lrow) * DIMF + kc;
        const __nv_bfloat16* pl = Al + (size_t)(m0 + lrow) * DIMF + kc;
        const __nv_bfloat16* pb = Bh + (size_t)(n0 + lrow) * DIMF + kc;
        const __nv_bfloat16* pq = Bl + (size_t)(n0 + lrow) * DIMF + kc;
        cpasync16(d0,                pa);     cpasync16(d0 + 16,                pa + 8);
        cpasync16(d0 + TILE_B,       pl);     cpasync16(d0 + TILE_B + 16,       pl + 8);
        cpasync16(d0 + 2 * TILE_B,   pb);     cpasync16(d0 + 2 * TILE_B + 16,   pb + 8);
        cpasync16(d0 + 3 * TILE_B,   pq);     cpasync16(d0 + 3 * TILE_B + 16,   pq + 8);
        CP_COMMIT();
    };

    float acc[2][8][4];
#pragma unroll
    for (int i = 0; i < 2; i++)
#pragma unroll
        for (int j = 0; j < 8; j++)
#pragma unroll
            for (int l = 0; l < 4; l++) acc[i][j][l] = 0.0f;

    const int mw = (warp >> 1) * 32;
    const int nw = (warp & 1) * 64;

    load_stage(0);
    load_stage(1);

    for (int s = 0; s < 32; s++) {
        if (s == 31) CP_WAIT(0); else CP_WAIT(1);
        __syncthreads();

        const uint32_t base = sbase + (s & 1) * STAGE_B;
#pragma unroll
        for (int t = 0; t < 2; t++) {
            const int kk = t * 16;
            uint32_t ahi[2][4], alo[2][4];
#pragma unroll
            for (int mt = 0; mt < 2; mt++) {
                uint32_t addr = base + (mw + mt * 16 + (lane & 15)) * 80
                              + kk * 2 + ((lane >> 4) << 4);
                ldsm_x4(ahi[mt], addr);
                ldsm_x4(alo[mt], addr + TILE_B);
            }
#pragma unroll
            for (int p = 0; p < 4; p++) {
                uint32_t baddr = base + 2 * TILE_B
                               + (nw + p * 16 + (lane & 7) + ((lane >> 4) << 3)) * 80
                               + kk * 2 + (((lane >> 3) & 1) << 4);
                uint32_t bh4[4], bl4[4];
                ldsm_x4(bh4, baddr);
                ldsm_x4(bl4, baddr + TILE_B);
#pragma unroll
                for (int mt = 0; mt < 2; mt++) {
                    mma16(acc[mt][2 * p],     ahi[mt], bh4);
                    mma16(acc[mt][2 * p],     ahi[mt], bl4);
                    mma16(acc[mt][2 * p],     alo[mt], bh4);
                    mma16(acc[mt][2 * p + 1], ahi[mt], bh4 + 2);
                    mma16(acc[mt][2 * p + 1], ahi[mt], bl4 + 2);
                    mma16(acc[mt][2 * p + 1], alo[mt], bh4 + 2);
                }
            }
        }
        __syncthreads();
        if (s + 2 < 32) load_stage(s + 2);
    }

    // epilogue
#pragma unroll
    for (int mt = 0; mt < 2; mt++) {
#pragma unroll
        for (int nt = 0; nt < 8; nt++) {
#pragma unroll
            for (int half = 0; half < 2; half++) {
                int m = m0 + mw + mt * 16 + (lane >> 2) + half * 8;
                int c = n0 + nw + nt * 8 + ((lane & 3) << 1);
                float2 v = make_float2(acc[mt][nt][half * 2 + 0],
                                       acc[mt][nt][half * 2 + 1]);
                if (OUT) {
                    const float2 bb2 = *(const float2*)(bias + c);
                    v.x += bb2.x; v.y += bb2.y;
                    *(float2*)(Cout + (size_t)m * DIMF + c) = v;
                } else {
                    int bb = m >> 11, n = m & (NSEQ - 1);
                    int h = c >> 6, d = c & (HD - 1);
                    if (z == 2) {
                        float* basep = g_vt + (((size_t)(bb * NH + h) * HD + d) * NSEQ) + n;
                        basep[0]    = v.x;
                        basep[NSEQ] = v.y;
                    } else {
                        float* dst = (z == 0 ? g_q : g_k)
                                   + (((size_t)(bb * NH + h) * NSEQ + n) << 6) + d;
                        *(float2*)dst = v;
                    }
                }
            }
        }
    }
}

// ---------------------------------------------------------------------------
// RMSNorm + interleaved RoPE in place on g_q / g_k
// ---------------------------------------------------------------------------
__global__ void __launch_bounds__(256) rmsrope_kernel()
{
    const int warp = threadIdx.x >> 5;
    const int lane = threadIdx.x & 31;
    const size_t row = (size_t)blockIdx.x * 8 + warp;
    float* ptr = (blockIdx.y == 0 ? g_q : g_k) + row * HD;

    float2 x = *(float2*)(ptr + lane * 2);
    float ss = x.x * x.x + x.y * x.y;
#pragma unroll
    for (int off = 16; off; off >>= 1)
        ss += __shfl_xor_sync(0xffffffffu, ss, off);
    float rn = rsqrtf(ss * (1.0f / 64.0f) + 1e-5f);

    int pos = (int)(row & (NSEQ - 1));
    float ifr = exp2f((float)lane * (-2.0f / 64.0f) * 13.287712379549449f);
    float ang = (float)pos * ifr;
    float s, c;
    sincosf(ang, &s, &c);

    float x0 = x.x * rn, x1 = x.y * rn;
    float2 y;
    y.x = x0 * c - x1 * s;
    y.y = x1 * c + x0 * s;
    *(float2*)(ptr + lane * 2) = y;
}

// ---------------------------------------------------------------------------
// Flash attention (tf32 mma.sync). CTA: 128 q-rows, 8 warps (16 rows each).
// Epilogue writes bf16 hi/lo to g_oh/g_ol in the gathered [b*n, h*64+d] layout.
// ---------------------------------------------------------------------------
__global__ void __launch_bounds__(256) flash_tf32(const float* __restrict__ mask)
{
    extern __shared__ float sm[];
    float* Ks  = sm;                // 64*68
    float* Vts = sm + 64 * 68;      // 64*68
    float* Ps  = sm + 2 * 64 * 68;  // 128*68

    const int tid = threadIdx.x, warp = tid >> 5, lane = tid & 31;
    const int bh = blockIdx.y, b = bh >> 4, h = bh & 15;
    const int q0 = blockIdx.x * 128;

    const float* Qg  = g_q  + ((size_t)bh * NSEQ + q0) * HD;
    const float* Kg  = g_k  + (size_t)bh * NSEQ * HD;
    const float* Vtg = g_vt + (size_t)bh * HD * NSEQ;
    const float* Mg  = mask + (size_t)b * NSEQ * NSEQ + (size_t)q0 * NSEQ;

#pragma unroll
    for (int i = 0; i < 8; i++) {
        int r = (tid >> 4) + i * 16;
        int c = (tid & 15) * 4;
        float4 v = *(const float4*)(Qg + (size_t)r * HD + c);
        float* d = Ps + r * 68 + c;
        d[0] = tf32r(v.x); d[1] = tf32r(v.y); d[2] = tf32r(v.z); d[3] = tf32r(v.w);
    }
    __syncthreads();
    uint32_t qf[8][4];
    {
        int row = warp * 16 + (lane & 15);
        int cb  = (lane >> 4) << 2;
#pragma unroll
        for (int t = 0; t < 8; t++)
            ldsm_x4(qf[t], saddr(Ps + row * 68 + t * 8 + cb));
    }
    __syncthreads();

    const int r  = lane >> 2;
    const int cq = lane & 3;
    float* Pw = Ps + warp * 16 * 68;

    float mrow[2] = {-INFINITY, -INFINITY};
    float lrow[2] = {0.0f, 0.0f};
    float o[8][4];
#pragma unroll
    for (int nt = 0; nt < 8; nt++)
#pragma unroll
        for (int j = 0; j < 4; j++) o[nt][j] = 0.0f;

    const float scale = 1.0f / 64.0f;

    for (int kt = 0; kt < NSEQ / 64; kt++) {
        const int k0 = kt * 64;
#pragma unroll
        for (int i = 0; i < 4; i++) {
            int rr = (tid >> 4) + i * 16;
            int cc = (tid & 15) * 4;
            float4 kv = *(const float4*)(Kg + (size_t)(k0 + rr) * HD + cc);
            float* dk = Ks + rr * 68 + cc;
            dk[0] = tf32r(kv.x); dk[1] = tf32r(kv.y); dk[2] = tf32r(kv.z); dk[3] = tf32r(kv.w);
            float4 vv = *(const float4*)(Vtg + (size_t)rr * NSEQ + k0 + cc);
            float* dv = Vts + rr * 68 + cc;
            dv[0] = tf32r(vv.x); dv[1] = tf32r(vv.y); dv[2] = tf32r(vv.z); dv[3] = tf32r(vv.w);
        }
        __syncthreads();

        float s[8][4];
#pragma unroll
        for (int nt = 0; nt < 8; nt++)
#pragma unroll
            for (int j = 0; j < 4; j++) s[nt][j] = 0.0f;

#pragma unroll
        for (int t = 0; t < 8; t++) {
            uint32_t bb[8][2];
#pragma unroll
            for (int p = 0; p < 4; p++) {
                int row = p * 16 + (lane & 7) + ((lane >> 4) << 3);
                int col = t * 8 + (((lane >> 3) & 1) << 2);
                uint32_t r4[4];
                ldsm_x4(r4, saddr(Ks + row * 68 + col));
                bb[2 * p][0] = r4[0]; bb[2 * p][1] = r4[1];
                bb[2 * p + 1][0] = r4[2]; bb[2 * p + 1][1] = r4[3];
            }
#pragma unroll
            for (int nt = 0; nt < 8; nt++) mma8(s[nt], qf[t], bb[nt]);
        }

#pragma unroll
        for (int half = 0; half < 2; half++) {
            const float* mp = Mg + (size_t)(warp * 16 + r + half * 8) * NSEQ + k0;
            float sim[16];
            float vmax = -INFINITY;
#pragma unroll
            for (int nt = 0; nt < 8; nt++) {
                float2 mk = *(const float2*)(mp + nt * 8 + 2 * cq);
                sim[2 * nt]     = s[nt][half * 2 + 0] * scale + mk.x;
                sim[2 * nt + 1] = s[nt][half * 2 + 1] * scale + mk.y;
                vmax = fmaxf(vmax, fmaxf(sim[2 * nt], sim[2 * nt + 1]));
            }
            vmax = fmaxf(vmax, __shfl_xor_sync(0xffffffffu, vmax, 1, 4));
            vmax = fmaxf(vmax, __shfl_xor_sync(0xffffffffu, vmax, 2, 4));
            float mnew = fmaxf(mrow[half], vmax);
            float corr = __expf(mrow[half] - mnew);
            float sum = 0.0f;
#pragma unroll
            for (int nt = 0; nt < 8; nt++) {
                float p0 = __expf(sim[2 * nt]     - mnew);
                float p1 = __expf(sim[2 * nt + 1] - mnew);
                sum += p0 + p1;
                *(float2*)(Pw + (size_t)(r + half * 8) * 68 + nt * 8 + 2 * cq) =
                    make_float2(tf32r(p0), tf32r(p1));
            }
            sum += __shfl_xor_sync(0xffffffffu, sum, 1, 4);
            sum += __shfl_xor_sync(0xffffffffu, sum, 2, 4);
            lrow[half] = lrow[half] * corr + sum;
            mrow[half] = mnew;
#pragma unroll
            for (int nt = 0; nt < 8; nt++) {
                o[nt][half * 2 + 0] *= corr;
                o[nt][half * 2 + 1] *= corr;
            }
        }
        __syncwarp();

#pragma unroll
        for (int t = 0; t < 8; t++) {
            uint32_t af[4];
            {
                int row = lane & 15;
                int col = t * 8 + ((lane >> 4) << 2);
                ldsm_x4(af, saddr(Pw + row * 68 + col));
            }
            uint32_t bb[8][2];
#pragma unroll
            for (int p = 0; p < 4; p++) {
                int row = p * 16 + (lane & 7) + ((lane >> 4) << 3);
                int col = t * 8 + (((lane >> 3) & 1) << 2);
                uint32_t r4[4];
                ldsm_x4(r4, saddr(Vts + row * 68 + col));
                bb[2 * p][0] = r4[0]; bb[2 * p][1] = r4[1];
                bb[2 * p + 1][0] = r4[2]; bb[2 * p + 1][1] = r4[3];
            }
#pragma unroll
            for (int nt = 0; nt < 8; nt++) mma8(o[nt], af, bb[nt]);
        }
        __syncthreads();
    }

    // epilogue: write bf16 hi/lo into gathered layout [b*2048+seq][h*64+d]
    float inv0 = 1.0f / lrow[0], inv1 = 1.0f / lrow[1];
#pragma unroll
    for (int nt = 0; nt < 8; nt++) {
        int col = h * HD + nt * 8 + 2 * cq;
#pragma unroll
        for (int half = 0; half < 2; half++) {
            int m = b * NSEQ + q0 + warp * 16 + r + half * 8;
            float inv = half ? inv1 : inv0;
            float v0 = o[nt][half * 2 + 0] * inv;
            float v1 = o[nt][half * 2 + 1] * inv;
            __nv_bfloat16 h0 = __float2bfloat16(v0);
            __nv_bfloat16 h1 = __float2bfloat16(v1);
            __nv_bfloat162 ph; ph.x = h0; ph.y = h1;
            __nv_bfloat162 pl;
            pl.x = __float2bfloat16(v0 - __bfloat162float(h0));
            pl.y = __float2bfloat16(v1 - __bfloat162float(h1));
            *(__nv_bfloat162*)(g_oh + (size_t)m * DIMF + col) = ph;
            *(__nv_bfloat162*)(g_ol + (size_t)m * DIMF + col) = pl;
        }
    }
}

// ---------------------------------------------------------------------------
// Launch
// ---------------------------------------------------------------------------
extern "C" void kernel_launch(void* const* d_in, const int* in_sizes, int n_in,
                              void* d_out, int out_size)
{
    const float* x    = (const float*)d_in[0];
    const float* mask = (const float*)d_in[1];
    const float* Wq   = (const float*)d_in[2];
    const float* Wk   = (const float*)d_in[3];
    const float* Wv   = (const float*)d_in[4];
    const float* Wo   = (const float*)d_in[5];
    const float* bo   = (const float*)d_in[6];
    float* out = (float*)d_out;

    const int GEMM_SMEM  = 2 * STAGE_B;                    // 81920 B
    const int FLASH_SMEM = (2 * 64 * 68 + 128 * 68) * 4;   // 69632 B
    cudaFuncSetAttribute(gemm_bf16<0>, cudaFuncAttributeMaxDynamicSharedMemorySize, GEMM_SMEM);
    cudaFuncSetAttribute(gemm_bf16<1>, cudaFuncAttributeMaxDynamicSharedMemorySize, GEMM_SMEM);
    cudaFuncSetAttribute(flash_tf32,   cudaFuncAttributeMaxDynamicSharedMemorySize, FLASH_SMEM);

    conv_split<<<MROWS + 4 * DIMF, 256>>>(x, Wq, Wk, Wv, Wo);

    gemm_bf16<0><<<dim3(8, 32, 3), 256, GEMM_SMEM>>>(nullptr, nullptr);

    rmsrope_kernel<<<dim3((BATCH * NH * NSEQ) / 8, 2), 256>>>();

    flash_tf32<<<dim3(NSEQ / 128, BATCH * NH), 256, FLASH_SMEM>>>(mask);

    gemm_bf16<1><<<dim3(8, 32), 256, GEMM_SMEM>>>(bo, out);
}

// round 6
// speedup vs baseline: 2.7176x; 1.2572x over previous
#include <cuda_runtime.h>
#include <cuda_bf16.h>
#include <math.h>
#include <stdint.h>

#define BATCH 2
#define NSEQ  2048
#define DIMF  1024
#define NH    16
#define HD    64
#define MROWS (BATCH * NSEQ)   // 4096

// fp32 scratch for attention path (Q/K/Vt hold tf32-rounded values)
__device__ float g_q [BATCH * NH * NSEQ * HD];
__device__ float g_k [BATCH * NH * NSEQ * HD];
__device__ float g_vt[BATCH * NH * HD * NSEQ];   // [b,h,d,seq]

// bf16 hi/lo split operands (row-major)
__device__ __nv_bfloat16 g_xh[(size_t)MROWS * DIMF];
__device__ __nv_bfloat16 g_xl[(size_t)MROWS * DIMF];
__device__ __nv_bfloat16 g_oh[(size_t)MROWS * DIMF];   // flash output, gathered layout
__device__ __nv_bfloat16 g_ol[(size_t)MROWS * DIMF];
__device__ __nv_bfloat16 g_wh[(size_t)4 * DIMF * DIMF];
__device__ __nv_bfloat16 g_wl[(size_t)4 * DIMF * DIMF];

// ---------------------------------------------------------------------------
// helpers
// ---------------------------------------------------------------------------
__device__ __forceinline__ uint32_t saddr(const void* p) {
    return (uint32_t)__cvta_generic_to_shared(p);
}
__device__ __forceinline__ float tf32r(float x) {
    uint32_t u;
    asm("cvt.rna.tf32.f32 %0, %1;" : "=r"(u) : "f"(x));
    return __uint_as_float(u);
}
__device__ __forceinline__ void ldsm_x4(uint32_t r[4], uint32_t a) {
    asm volatile("ldmatrix.sync.aligned.m8n8.x4.shared.b16 {%0,%1,%2,%3}, [%4];"
                 : "=r"(r[0]), "=r"(r[1]), "=r"(r[2]), "=r"(r[3]) : "r"(a));
}
// tf32 m16n8k8 (flash)
__device__ __forceinline__ void mma8(float c[4], const uint32_t a[4], const uint32_t b[2]) {
    asm volatile(
        "mma.sync.aligned.m16n8k8.row.col.f32.tf32.tf32.f32 "
        "{%0,%1,%2,%3}, {%4,%5,%6,%7}, {%8,%9}, {%0,%1,%2,%3};"
        : "+f"(c[0]), "+f"(c[1]), "+f"(c[2]), "+f"(c[3])
        : "r"(a[0]), "r"(a[1]), "r"(a[2]), "r"(a[3]), "r"(b[0]), "r"(b[1]));
}
// bf16 m16n8k16 (GEMMs)
__device__ __forceinline__ void mma16(float c[4], const uint32_t a[4], const uint32_t b[2]) {
    asm volatile(
        "mma.sync.aligned.m16n8k16.row.col.f32.bf16.bf16.f32 "
        "{%0,%1,%2,%3}, {%4,%5,%6,%7}, {%8,%9}, {%0,%1,%2,%3};"
        : "+f"(c[0]), "+f"(c[1]), "+f"(c[2]), "+f"(c[3])
        : "r"(a[0]), "r"(a[1]), "r"(a[2]), "r"(a[3]), "r"(b[0]), "r"(b[1]));
}
__device__ __forceinline__ void cpasync16(uint32_t s, const void* g) {
    asm volatile("cp.async.cg.shared.global [%0], [%1], 16;" :: "r"(s), "l"(g) : "memory");
}
#define CP_COMMIT()  asm volatile("cp.async.commit_group;" ::: "memory")
#define CP_WAIT(n)   asm volatile("cp.async.wait_group %0;" :: "n"(n) : "memory")

// ---------------------------------------------------------------------------
// Split fp32 -> bf16 hi/lo (row-major). 8192 rows of 1024: x then Wq/Wk/Wv/Wo.
// ---------------------------------------------------------------------------
__global__ void __launch_bounds__(256) conv_split(
    const float* __restrict__ x,
    const float* __restrict__ Wq, const float* __restrict__ Wk,
    const float* __restrict__ Wv, const float* __restrict__ Wo)
{
    const int row = blockIdx.x;
    const float* src;
    __nv_bfloat16 *dh, *dl;
    if (row < MROWS) {
        src = x + (size_t)row * DIMF;
        dh = g_xh + (size_t)row * DIMF;
        dl = g_xl + (size_t)row * DIMF;
    } else {
        int wi = (row - MROWS) >> 10, r = (row - MROWS) & 1023;
        const float* W = (wi == 0) ? Wq : (wi == 1) ? Wk : (wi == 2) ? Wv : Wo;
        src = W + (size_t)r * DIMF;
        dh = g_wh + ((size_t)wi * DIMF + r) * DIMF;
        dl = g_wl + ((size_t)wi * DIMF + r) * DIMF;
    }
    const int c = threadIdx.x * 4;
    float4 v = *(const float4*)(src + c);
    __nv_bfloat16 h0 = __float2bfloat16(v.x);
    __nv_bfloat16 h1 = __float2bfloat16(v.y);
    __nv_bfloat16 h2 = __float2bfloat16(v.z);
    __nv_bfloat16 h3 = __float2bfloat16(v.w);
    __nv_bfloat162 ph0; ph0.x = h0; ph0.y = h1;
    __nv_bfloat162 ph1; ph1.x = h2; ph1.y = h3;
    __nv_bfloat162 pl0; pl0.x = __float2bfloat16(v.x - __bfloat162float(h0));
    pl0.y = __float2bfloat16(v.y - __bfloat162float(h1));
    __nv_bfloat162 pl1; pl1.x = __float2bfloat16(v.z - __bfloat162float(h2));
    pl1.y = __float2bfloat16(v.w - __bfloat162float(h3));
    *(__nv_bfloat162*)(dh + c)     = ph0;
    *(__nv_bfloat162*)(dh + c + 2) = ph1;
    *(__nv_bfloat162*)(dl + c)     = pl0;
    *(__nv_bfloat162*)(dl + c + 2) = pl1;
}

// ---------------------------------------------------------------------------
// bf16 3-pass GEMM (NT): C[M,128-tile] = A[M,K] * W[N,K]^T
// CTA 128x128, BK=32, 256 threads (8 warps as 4x2, warp tile 32x64),
// 2-stage cp.async double buffer.
// OUT=0: A=x split, W=w[z] (z=blockIdx.z); scatter to g_q/g_k/g_vt.
//        z==2 (V) stores tf32-rounded values to g_vt.
// OUT=1: A=flash output split (already gathered), W=w[3]; out = C + bias.
// ---------------------------------------------------------------------------
#define TILE_B 10240              // 128 rows * 80 bytes
#define STAGE_B (4 * TILE_B)      // Ah, Al, Bh, Bl

template <int OUT>
__global__ void __launch_bounds__(256, 2) gemm_bf16(
    const float* __restrict__ bias, float* __restrict__ Cout)
{
    extern __shared__ char smem[];
    const uint32_t sbase = saddr(smem);
    const int tid = threadIdx.x, warp = tid >> 5, lane = tid & 31;
    const int m0 = blockIdx.y * 128, n0 = blockIdx.x * 128;
    const int z = OUT ? 3 : blockIdx.z;

    const __nv_bfloat16* Ah = OUT ? g_oh : g_xh;
    const __nv_bfloat16* Al = OUT ? g_ol : g_xl;
    const __nv_bfloat16* Bh = g_wh + (size_t)z * DIMF * DIMF;
    const __nv_bfloat16* Bl = g_wl + (size_t)z * DIMF * DIMF;

    const int lrow = tid >> 1;            // 0..127
    const int lq   = (tid & 1) * 2;       // quad 0 or 2

    auto load_stage = [&](int s) {
        const uint32_t d0 = sbase + (s & 1) * STAGE_B + lrow * 80 + lq * 16;
        const int kc = s * 32 + lq * 8;
        const __nv_bfloat16* pa = Ah + (size_t)(m0 + lrow) * DIMF + kc;
        const __nv_bfloat16* pl = Al + (size_t)(m0 + lrow) * DIMF + kc;
        const __nv_bfloat16* pb = Bh + (size_t)(n0 + lrow) * DIMF + kc;
        const __nv_bfloat16* pq = Bl + (size_t)(n0 + lrow) * DIMF + kc;
        cpasync16(d0,                pa);     cpasync16(d0 + 16,                pa + 8);
        cpasync16(d0 + TILE_B,       pl);     cpasync16(d0 + TILE_B + 16,       pl + 8);
        cpasync16(d0 + 2 * TILE_B,   pb);     cpasync16(d0 + 2 * TILE_B + 16,   pb + 8);
        cpasync16(d0 + 3 * TILE_B,   pq);     cpasync16(d0 + 3 * TILE_B + 16,   pq + 8);
        CP_COMMIT();
    };

    float acc[2][8][4];
#pragma unroll
    for (int i = 0; i < 2; i++)
#pragma unroll
        for (int j = 0; j < 8; j++)
#pragma unroll
            for (int l = 0; l < 4; l++) acc[i][j][l] = 0.0f;

    const int mw = (warp >> 1) * 32;
    const int nw = (warp & 1) * 64;

    load_stage(0);
    load_stage(1);

    for (int s = 0; s < 32; s++) {
        if (s == 31) CP_WAIT(0); else CP_WAIT(1);
        __syncthreads();

        const uint32_t base = sbase + (s & 1) * STAGE_B;
#pragma unroll
        for (int t = 0; t < 2; t++) {
            const int kk = t * 16;
            uint32_t ahi[2][4], alo[2][4];
#pragma unroll
            for (int mt = 0; mt < 2; mt++) {
                uint32_t addr = base + (mw + mt * 16 + (lane & 15)) * 80
                              + kk * 2 + ((lane >> 4) << 4);
                ldsm_x4(ahi[mt], addr);
                ldsm_x4(alo[mt], addr + TILE_B);
            }
#pragma unroll
            for (int p = 0; p < 4; p++) {
                uint32_t baddr = base + 2 * TILE_B
                               + (nw + p * 16 + (lane & 7) + ((lane >> 4) << 3)) * 80
                               + kk * 2 + (((lane >> 3) & 1) << 4);
                uint32_t bh4[4], bl4[4];
                ldsm_x4(bh4, baddr);
                ldsm_x4(bl4, baddr + TILE_B);
#pragma unroll
                for (int mt = 0; mt < 2; mt++) {
                    mma16(acc[mt][2 * p],     ahi[mt], bh4);
                    mma16(acc[mt][2 * p],     ahi[mt], bl4);
                    mma16(acc[mt][2 * p],     alo[mt], bh4);
                    mma16(acc[mt][2 * p + 1], ahi[mt], bh4 + 2);
                    mma16(acc[mt][2 * p + 1], ahi[mt], bl4 + 2);
                    mma16(acc[mt][2 * p + 1], alo[mt], bh4 + 2);
                }
            }
        }
        __syncthreads();
        if (s + 2 < 32) load_stage(s + 2);
    }

    // epilogue
#pragma unroll
    for (int mt = 0; mt < 2; mt++) {
#pragma unroll
        for (int nt = 0; nt < 8; nt++) {
#pragma unroll
            for (int half = 0; half < 2; half++) {
                int m = m0 + mw + mt * 16 + (lane >> 2) + half * 8;
                int c = n0 + nw + nt * 8 + ((lane & 3) << 1);
                float2 v = make_float2(acc[mt][nt][half * 2 + 0],
                                       acc[mt][nt][half * 2 + 1]);
                if (OUT) {
                    const float2 bb2 = *(const float2*)(bias + c);
                    v.x += bb2.x; v.y += bb2.y;
                    *(float2*)(Cout + (size_t)m * DIMF + c) = v;
                } else {
                    int bb = m >> 11, n = m & (NSEQ - 1);
                    int h = c >> 6, d = c & (HD - 1);
                    if (z == 2) {
                        // V^T stores tf32-rounded (what flash consumed before)
                        float* basep = g_vt + (((size_t)(bb * NH + h) * HD + d) * NSEQ) + n;
                        basep[0]    = tf32r(v.x);
                        basep[NSEQ] = tf32r(v.y);
                    } else {
                        float* dst = (z == 0 ? g_q : g_k)
                                   + (((size_t)(bb * NH + h) * NSEQ + n) << 6) + d;
                        *(float2*)dst = v;
                    }
                }
            }
        }
    }
}

// ---------------------------------------------------------------------------
// RMSNorm + interleaved RoPE in place on g_q / g_k.
// Stores tf32-rounded results (moves the rounding out of the flash kernel;
// numerics identical to rounding at flash load time).
// ---------------------------------------------------------------------------
__global__ void __launch_bounds__(256) rmsrope_kernel()
{
    const int warp = threadIdx.x >> 5;
    const int lane = threadIdx.x & 31;
    const size_t row = (size_t)blockIdx.x * 8 + warp;
    float* ptr = (blockIdx.y == 0 ? g_q : g_k) + row * HD;

    float2 x = *(float2*)(ptr + lane * 2);
    float ss = x.x * x.x + x.y * x.y;
#pragma unroll
    for (int off = 16; off; off >>= 1)
        ss += __shfl_xor_sync(0xffffffffu, ss, off);
    float rn = rsqrtf(ss * (1.0f / 64.0f) + 1e-5f);

    int pos = (int)(row & (NSEQ - 1));
    float ifr = exp2f((float)lane * (-2.0f / 64.0f) * 13.287712379549449f);
    float ang = (float)pos * ifr;
    float s, c;
    sincosf(ang, &s, &c);

    float x0 = x.x * rn, x1 = x.y * rn;
    float2 y;
    y.x = tf32r(x0 * c - x1 * s);
    y.y = tf32r(x1 * c + x0 * s);
    *(float2*)(ptr + lane * 2) = y;
}

// ---------------------------------------------------------------------------
// Flash attention (tf32 mma.sync). CTA: 128 q-rows, 8 warps (16 rows each),
// 2 CTAs/SM. Q/K/V arrive pre-rounded to tf32 -> staging is plain copies.
// Epilogue writes bf16 hi/lo to g_oh/g_ol in the gathered [b*n, h*64+d] layout.
// ---------------------------------------------------------------------------
__global__ void __launch_bounds__(256, 2) flash_tf32(const float* __restrict__ mask)
{
    extern __shared__ float sm[];
    float* Ks  = sm;                // 64*68
    float* Vts = sm + 64 * 68;      // 64*68
    float* Ps  = sm + 2 * 64 * 68;  // 128*68

    const int tid = threadIdx.x, warp = tid >> 5, lane = tid & 31;
    const int bh = blockIdx.y, b = bh >> 4, h = bh & 15;
    const int q0 = blockIdx.x * 128;

    const float* Qg  = g_q  + ((size_t)bh * NSEQ + q0) * HD;
    const float* Kg  = g_k  + (size_t)bh * NSEQ * HD;
    const float* Vtg = g_vt + (size_t)bh * HD * NSEQ;
    const float* Mg  = mask + (size_t)b * NSEQ * NSEQ + (size_t)q0 * NSEQ;

#pragma unroll
    for (int i = 0; i < 8; i++) {
        int r = (tid >> 4) + i * 16;
        int c = (tid & 15) * 4;
        *(float4*)(Ps + r * 68 + c) = *(const float4*)(Qg + (size_t)r * HD + c);
    }
    __syncthreads();
    uint32_t qf[8][4];
    {
        int row = warp * 16 + (lane & 15);
        int cb  = (lane >> 4) << 2;
#pragma unroll
        for (int t = 0; t < 8; t++)
            ldsm_x4(qf[t], saddr(Ps + row * 68 + t * 8 + cb));
    }
    __syncthreads();

    const int r  = lane >> 2;
    const int cq = lane & 3;
    float* Pw = Ps + warp * 16 * 68;

    float mrow[2] = {-INFINITY, -INFINITY};
    float lrow[2] = {0.0f, 0.0f};
    float o[8][4];
#pragma unroll
    for (int nt = 0; nt < 8; nt++)
#pragma unroll
        for (int j = 0; j < 4; j++) o[nt][j] = 0.0f;

    const float scale = 1.0f / 64.0f;

    for (int kt = 0; kt < NSEQ / 64; kt++) {
        const int k0 = kt * 64;
#pragma unroll
        for (int i = 0; i < 4; i++) {
            int rr = (tid >> 4) + i * 16;
            int cc = (tid & 15) * 4;
            *(float4*)(Ks  + rr * 68 + cc) = *(const float4*)(Kg  + (size_t)(k0 + rr) * HD + cc);
            *(float4*)(Vts + rr * 68 + cc) = *(const float4*)(Vtg + (size_t)rr * NSEQ + k0 + cc);
        }
        __syncthreads();

        float s[8][4];
#pragma unroll
        for (int nt = 0; nt < 8; nt++)
#pragma unroll
            for (int j = 0; j < 4; j++) s[nt][j] = 0.0f;

#pragma unroll
        for (int t = 0; t < 8; t++) {
            uint32_t bb[8][2];
#pragma unroll
            for (int p = 0; p < 4; p++) {
                int row = p * 16 + (lane & 7) + ((lane >> 4) << 3);
                int col = t * 8 + (((lane >> 3) & 1) << 2);
                uint32_t r4[4];
                ldsm_x4(r4, saddr(Ks + row * 68 + col));
                bb[2 * p][0] = r4[0]; bb[2 * p][1] = r4[1];
                bb[2 * p + 1][0] = r4[2]; bb[2 * p + 1][1] = r4[3];
            }
#pragma unroll
            for (int nt = 0; nt < 8; nt++) mma8(s[nt], qf[t], bb[nt]);
        }

#pragma unroll
        for (int half = 0; half < 2; half++) {
            const float* mp = Mg + (size_t)(warp * 16 + r + half * 8) * NSEQ + k0;
            float sim[16];
            float vmax = -INFINITY;
#pragma unroll
            for (int nt = 0; nt < 8; nt++) {
                float2 mk = *(const float2*)(mp + nt * 8 + 2 * cq);
                sim[2 * nt]     = s[nt][half * 2 + 0] * scale + mk.x;
                sim[2 * nt + 1] = s[nt][half * 2 + 1] * scale + mk.y;
                vmax = fmaxf(vmax, fmaxf(sim[2 * nt], sim[2 * nt + 1]));
            }
            vmax = fmaxf(vmax, __shfl_xor_sync(0xffffffffu, vmax, 1, 4));
            vmax = fmaxf(vmax, __shfl_xor_sync(0xffffffffu, vmax, 2, 4));
            float mnew = fmaxf(mrow[half], vmax);
            float corr = __expf(mrow[half] - mnew);
            float sum = 0.0f;
#pragma unroll
            for (int nt = 0; nt < 8; nt++) {
                float p0 = __expf(sim[2 * nt]     - mnew);
                float p1 = __expf(sim[2 * nt + 1] - mnew);
                sum += p0 + p1;
                *(float2*)(Pw + (size_t)(r + half * 8) * 68 + nt * 8 + 2 * cq) =
                    make_float2(tf32r(p0), tf32r(p1));
            }
            sum += __shfl_xor_sync(0xffffffffu, sum, 1, 4);
            sum += __shfl_xor_sync(0xffffffffu, sum, 2, 4);
            lrow[half] = lrow[half] * corr + sum;
            mrow[half] = mnew;
#pragma unroll
            for (int nt = 0; nt < 8; nt++) {
                o[nt][half * 2 + 0] *= corr;
                o[nt][half * 2 + 1] *= corr;
            }
        }
        __syncwarp();

#pragma unroll
        for (int t = 0; t < 8; t++) {
            uint32_t af[4];
            {
                int row = lane & 15;
                int col = t * 8 + ((lane >> 4) << 2);
                ldsm_x4(af, saddr(Pw + row * 68 + col));
            }
            uint32_t bb[8][2];
#pragma unroll
            for (int p = 0; p < 4; p++) {
                int row = p * 16 + (lane & 7) + ((lane >> 4) << 3);
                int col = t * 8 + (((lane >> 3) & 1) << 2);
                uint32_t r4[4];
                ldsm_x4(r4, saddr(Vts + row * 68 + col));
                bb[2 * p][0] = r4[0]; bb[2 * p][1] = r4[1];
                bb[2 * p + 1][0] = r4[2]; bb[2 * p + 1][1] = r4[3];
            }
#pragma unroll
            for (int nt = 0; nt < 8; nt++) mma8(o[nt], af, bb[nt]);
        }
        __syncthreads();
    }

    // epilogue: write bf16 hi/lo into gathered layout [b*2048+seq][h*64+d]
    float inv0 = 1.0f / lrow[0], inv1 = 1.0f / lrow[1];
#pragma unroll
    for (int nt = 0; nt < 8; nt++) {
        int col = h * HD + nt * 8 + 2 * cq;
#pragma unroll
        for (int half = 0; half < 2; half++) {
            int m = b * NSEQ + q0 + warp * 16 + r + half * 8;
            float inv = half ? inv1 : inv0;
            float v0 = o[nt][half * 2 + 0] * inv;
            float v1 = o[nt][half * 2 + 1] * inv;
            __nv_bfloat16 h0 = __float2bfloat16(v0);
            __nv_bfloat16 h1 = __float2bfloat16(v1);
            __nv_bfloat162 ph; ph.x = h0; ph.y = h1;
            __nv_bfloat162 pl;
            pl.x = __float2bfloat16(v0 - __bfloat162float(h0));
            pl.y = __float2bfloat16(v1 - __bfloat162float(h1));
            *(__nv_bfloat162*)(g_oh + (size_t)m * DIMF + col) = ph;
            *(__nv_bfloat162*)(g_ol + (size_t)m * DIMF + col) = pl;
        }
    }
}

// ---------------------------------------------------------------------------
// Launch
// ---------------------------------------------------------------------------
extern "C" void kernel_launch(void* const* d_in, const int* in_sizes, int n_in,
                              void* d_out, int out_size)
{
    const float* x    = (const float*)d_in[0];
    const float* mask = (const float*)d_in[1];
    const float* Wq   = (const float*)d_in[2];
    const float* Wk   = (const float*)d_in[3];
    const float* Wv   = (const float*)d_in[4];
    const float* Wo   = (const float*)d_in[5];
    const float* bo   = (const float*)d_in[6];
    float* out = (float*)d_out;

    const int GEMM_SMEM  = 2 * STAGE_B;                    // 81920 B
    const int FLASH_SMEM = (2 * 64 * 68 + 128 * 68) * 4;   // 69632 B
    cudaFuncSetAttribute(gemm_bf16<0>, cudaFuncAttributeMaxDynamicSharedMemorySize, GEMM_SMEM);
    cudaFuncSetAttribute(gemm_bf16<1>, cudaFuncAttributeMaxDynamicSharedMemorySize, GEMM_SMEM);
    cudaFuncSetAttribute(flash_tf32,   cudaFuncAttributeMaxDynamicSharedMemorySize, FLASH_SMEM);

    conv_split<<<MROWS + 4 * DIMF, 256>>>(x, Wq, Wk, Wv, Wo);

    gemm_bf16<0><<<dim3(8, 32, 3), 256, GEMM_SMEM>>>(nullptr, nullptr);

    rmsrope_kernel<<<dim3((BATCH * NH * NSEQ) / 8, 2), 256>>>();

    flash_tf32<<<dim3(NSEQ / 128, BATCH * NH), 256, FLASH_SMEM>>>(mask);

    gemm_bf16<1><<<dim3(8, 32), 256, GEMM_SMEM>>>(bo, out);
}

// round 7
// speedup vs baseline: 2.7999x; 1.0303x over previous
#include <cuda_runtime.h>
#include <cuda_bf16.h>
#include <math.h>
#include <stdint.h>

#define BATCH 2
#define NSEQ  2048
#define DIMF  1024
#define NH    16
#define HD    64
#define MROWS (BATCH * NSEQ)   // 4096

// fp32 scratch for attention path (Q/K/Vt hold tf32-rounded values; Q pre-scaled by 1/64)
__device__ float g_q [BATCH * NH * NSEQ * HD];
__device__ float g_k [BATCH * NH * NSEQ * HD];
__device__ float g_vt[BATCH * NH * HD * NSEQ];   // [b,h,d,seq]

// bf16 hi/lo split operands (row-major)
__device__ __nv_bfloat16 g_xh[(size_t)MROWS * DIMF];
__device__ __nv_bfloat16 g_xl[(size_t)MROWS * DIMF];
__device__ __nv_bfloat16 g_oh[(size_t)MROWS * DIMF];   // flash output, gathered layout
__device__ __nv_bfloat16 g_ol[(size_t)MROWS * DIMF];
__device__ __nv_bfloat16 g_wh[(size_t)4 * DIMF * DIMF];
__device__ __nv_bfloat16 g_wl[(size_t)4 * DIMF * DIMF];

// ---------------------------------------------------------------------------
// helpers
// ---------------------------------------------------------------------------
__device__ __forceinline__ uint32_t saddr(const void* p) {
    return (uint32_t)__cvta_generic_to_shared(p);
}
__device__ __forceinline__ float tf32r(float x) {
    uint32_t u;
    asm("cvt.rna.tf32.f32 %0, %1;" : "=r"(u) : "f"(x));
    return __uint_as_float(u);
}
__device__ __forceinline__ void ldsm_x4(uint32_t r[4], uint32_t a) {
    asm volatile("ldmatrix.sync.aligned.m8n8.x4.shared.b16 {%0,%1,%2,%3}, [%4];"
                 : "=r"(r[0]), "=r"(r[1]), "=r"(r[2]), "=r"(r[3]) : "r"(a));
}
// tf32 m16n8k8 (flash)
__device__ __forceinline__ void mma8(float c[4], const uint32_t a[4], const uint32_t b[2]) {
    asm volatile(
        "mma.sync.aligned.m16n8k8.row.col.f32.tf32.tf32.f32 "
        "{%0,%1,%2,%3}, {%4,%5,%6,%7}, {%8,%9}, {%0,%1,%2,%3};"
        : "+f"(c[0]), "+f"(c[1]), "+f"(c[2]), "+f"(c[3])
        : "r"(a[0]), "r"(a[1]), "r"(a[2]), "r"(a[3]), "r"(b[0]), "r"(b[1]));
}
// bf16 m16n8k16 (GEMMs)
__device__ __forceinline__ void mma16(float c[4], const uint32_t a[4], const uint32_t b[2]) {
    asm volatile(
        "mma.sync.aligned.m16n8k16.row.col.f32.bf16.bf16.f32 "
        "{%0,%1,%2,%3}, {%4,%5,%6,%7}, {%8,%9}, {%0,%1,%2,%3};"
        : "+f"(c[0]), "+f"(c[1]), "+f"(c[2]), "+f"(c[3])
        : "r"(a[0]), "r"(a[1]), "r"(a[2]), "r"(a[3]), "r"(b[0]), "r"(b[1]));
}
__device__ __forceinline__ void cpasync16(uint32_t s, const void* g) {
    asm volatile("cp.async.cg.shared.global [%0], [%1], 16;" :: "r"(s), "l"(g) : "memory");
}
#define CP_COMMIT()  asm volatile("cp.async.commit_group;" ::: "memory")
#define CP_WAIT(n)   asm volatile("cp.async.wait_group %0;" :: "n"(n) : "memory")

// ---------------------------------------------------------------------------
// Split fp32 -> bf16 hi/lo (row-major). 8192 rows of 1024: x then Wq/Wk/Wv/Wo.
// ---------------------------------------------------------------------------
__global__ void __launch_bounds__(256) conv_split(
    const float* __restrict__ x,
    const float* __restrict__ Wq, const float* __restrict__ Wk,
    const float* __restrict__ Wv, const float* __restrict__ Wo)
{
    const int row = blockIdx.x;
    const float* src;
    __nv_bfloat16 *dh, *dl;
    if (row < MROWS) {
        src = x + (size_t)row * DIMF;
        dh = g_xh + (size_t)row * DIMF;
        dl = g_xl + (size_t)row * DIMF;
    } else {
        int wi = (row - MROWS) >> 10, r = (row - MROWS) & 1023;
        const float* W = (wi == 0) ? Wq : (wi == 1) ? Wk : (wi == 2) ? Wv : Wo;
        src = W + (size_t)r * DIMF;
        dh = g_wh + ((size_t)wi * DIMF + r) * DIMF;
        dl = g_wl + ((size_t)wi * DIMF + r) * DIMF;
    }
    const int c = threadIdx.x * 4;
    float4 v = *(const float4*)(src + c);
    __nv_bfloat16 h0 = __float2bfloat16(v.x);
    __nv_bfloat16 h1 = __float2bfloat16(v.y);
    __nv_bfloat16 h2 = __float2bfloat16(v.z);
    __nv_bfloat16 h3 = __float2bfloat16(v.w);
    __nv_bfloat162 ph0; ph0.x = h0; ph0.y = h1;
    __nv_bfloat162 ph1; ph1.x = h2; ph1.y = h3;
    __nv_bfloat162 pl0; pl0.x = __float2bfloat16(v.x - __bfloat162float(h0));
    pl0.y = __float2bfloat16(v.y - __bfloat162float(h1));
    __nv_bfloat162 pl1; pl1.x = __float2bfloat16(v.z - __bfloat162float(h2));
    pl1.y = __float2bfloat16(v.w - __bfloat162float(h3));
    *(__nv_bfloat162*)(dh + c)     = ph0;
    *(__nv_bfloat162*)(dh + c + 2) = ph1;
    *(__nv_bfloat162*)(dl + c)     = pl0;
    *(__nv_bfloat162*)(dl + c + 2) = pl1;
}

// ---------------------------------------------------------------------------
// bf16 3-pass GEMM (NT): C[M,128-tile] = A[M,K] * W[N,K]^T
// CTA 128x128, BK=32, 256 threads, 2-stage cp.async double buffer.
// ---------------------------------------------------------------------------
#define TILE_B 10240              // 128 rows * 80 bytes
#define STAGE_B (4 * TILE_B)      // Ah, Al, Bh, Bl

template <int OUT>
__global__ void __launch_bounds__(256, 2) gemm_bf16(
    const float* __restrict__ bias, float* __restrict__ Cout)
{
    extern __shared__ char smem[];
    const uint32_t sbase = saddr(smem);
    const int tid = threadIdx.x, warp = tid >> 5, lane = tid & 31;
    const int m0 = blockIdx.y * 128, n0 = blockIdx.x * 128;
    const int z = OUT ? 3 : blockIdx.z;

    const __nv_bfloat16* Ah = OUT ? g_oh : g_xh;
    const __nv_bfloat16* Al = OUT ? g_ol : g_xl;
    const __nv_bfloat16* Bh = g_wh + (size_t)z * DIMF * DIMF;
    const __nv_bfloat16* Bl = g_wl + (size_t)z * DIMF * DIMF;

    const int lrow = tid >> 1;            // 0..127
    const int lq   = (tid & 1) * 2;       // quad 0 or 2

    auto load_stage = [&](int s) {
        const uint32_t d0 = sbase + (s & 1) * STAGE_B + lrow * 80 + lq * 16;
        const int kc = s * 32 + lq * 8;
        const __nv_bfloat16* pa = Ah + (size_t)(m0 + lrow) * DIMF + kc;
        const __nv_bfloat16* pl = Al + (size_t)(m0 + lrow) * DIMF + kc;
        const __nv_bfloat16* pb = Bh + (size_t)(n0 + lrow) * DIMF + kc;
        const __nv_bfloat16* pq = Bl + (size_t)(n0 + lrow) * DIMF + kc;
        cpasync16(d0,                pa);     cpasync16(d0 + 16,                pa + 8);
        cpasync16(d0 + TILE_B,       pl);     cpasync16(d0 + TILE_B + 16,       pl + 8);
        cpasync16(d0 + 2 * TILE_B,   pb);     cpasync16(d0 + 2 * TILE_B + 16,   pb + 8);
        cpasync16(d0 + 3 * TILE_B,   pq);     cpasync16(d0 + 3 * TILE_B + 16,   pq + 8);
        CP_COMMIT();
    };

    float acc[2][8][4];
#pragma unroll
    for (int i = 0; i < 2; i++)
#pragma unroll
        for (int j = 0; j < 8; j++)
#pragma unroll
            for (int l = 0; l < 4; l++) acc[i][j][l] = 0.0f;

    const int mw = (warp >> 1) * 32;
    const int nw = (warp & 1) * 64;

    load_stage(0);
    load_stage(1);

    for (int s = 0; s < 32; s++) {
        if (s == 31) CP_WAIT(0); else CP_WAIT(1);
        __syncthreads();

        const uint32_t base = sbase + (s & 1) * STAGE_B;
#pragma unroll
        for (int t = 0; t < 2; t++) {
            const int kk = t * 16;
            uint32_t ahi[2][4], alo[2][4];
#pragma unroll
            for (int mt = 0; mt < 2; mt++) {
                uint32_t addr = base + (mw + mt * 16 + (lane & 15)) * 80
                              + kk * 2 + ((lane >> 4) << 4);
                ldsm_x4(ahi[mt], addr);
                ldsm_x4(alo[mt], addr + TILE_B);
            }
#pragma unroll
            for (int p = 0; p < 4; p++) {
                uint32_t baddr = base + 2 * TILE_B
                               + (nw + p * 16 + (lane & 7) + ((lane >> 4) << 3)) * 80
                               + kk * 2 + (((lane >> 3) & 1) << 4);
                uint32_t bh4[4], bl4[4];
                ldsm_x4(bh4, baddr);
                ldsm_x4(bl4, baddr + TILE_B);
#pragma unroll
                for (int mt = 0; mt < 2; mt++) {
                    mma16(acc[mt][2 * p],     ahi[mt], bh4);
                    mma16(acc[mt][2 * p],     ahi[mt], bl4);
                    mma16(acc[mt][2 * p],     alo[mt], bh4);
                    mma16(acc[mt][2 * p + 1], ahi[mt], bh4 + 2);
                    mma16(acc[mt][2 * p + 1], ahi[mt], bl4 + 2);
                    mma16(acc[mt][2 * p + 1], alo[mt], bh4 + 2);
                }
            }
        }
        __syncthreads();
        if (s + 2 < 32) load_stage(s + 2);
    }

    // epilogue
#pragma unroll
    for (int mt = 0; mt < 2; mt++) {
#pragma unroll
        for (int nt = 0; nt < 8; nt++) {
#pragma unroll
            for (int half = 0; half < 2; half++) {
                int m = m0 + mw + mt * 16 + (lane >> 2) + half * 8;
                int c = n0 + nw + nt * 8 + ((lane & 3) << 1);
                float2 v = make_float2(acc[mt][nt][half * 2 + 0],
                                       acc[mt][nt][half * 2 + 1]);
                if (OUT) {
                    const float2 bb2 = *(const float2*)(bias + c);
                    v.x += bb2.x; v.y += bb2.y;
                    *(float2*)(Cout + (size_t)m * DIMF + c) = v;
                } else {
                    int bb = m >> 11, n = m & (NSEQ - 1);
                    int h = c >> 6, d = c & (HD - 1);
                    if (z == 2) {
                        // V^T stores tf32-rounded
                        float* basep = g_vt + (((size_t)(bb * NH + h) * HD + d) * NSEQ) + n;
                        basep[0]    = tf32r(v.x);
                        basep[NSEQ] = tf32r(v.y);
                    } else {
                        float* dst = (z == 0 ? g_q : g_k)
                                   + (((size_t)(bb * NH + h) * NSEQ + n) << 6) + d;
                        *(float2*)dst = v;
                    }
                }
            }
        }
    }
}

// ---------------------------------------------------------------------------
// RMSNorm + interleaved RoPE in place on g_q / g_k, tf32-rounded stores.
// Q additionally pre-scaled by 1/64 (exact power-of-2: commutes with rounding).
// ---------------------------------------------------------------------------
__global__ void __launch_bounds__(256) rmsrope_kernel()
{
    const int warp = threadIdx.x >> 5;
    const int lane = threadIdx.x & 31;
    const size_t row = (size_t)blockIdx.x * 8 + warp;
    const int isQ = (blockIdx.y == 0);
    float* ptr = (isQ ? g_q : g_k) + row * HD;

    float2 x = *(float2*)(ptr + lane * 2);
    float ss = x.x * x.x + x.y * x.y;
#pragma unroll
    for (int off = 16; off; off >>= 1)
        ss += __shfl_xor_sync(0xffffffffu, ss, off);
    float rn = rsqrtf(ss * (1.0f / 64.0f) + 1e-5f);

    int pos = (int)(row & (NSEQ - 1));
    float ifr = exp2f((float)lane * (-2.0f / 64.0f) * 13.287712379549449f);
    float ang = (float)pos * ifr;
    float s, c;
    sincosf(ang, &s, &c);

    float x0 = x.x * rn, x1 = x.y * rn;
    float post = isQ ? 0.015625f : 1.0f;   // fold attention scale (1/64, exact) into Q
    float2 y;
    y.x = tf32r((x0 * c - x1 * s) * post);
    y.y = tf32r((x1 * c + x0 * s) * post);
    *(float2*)(ptr + lane * 2) = y;
}

// ---------------------------------------------------------------------------
// Flash attention (tf32 mma.sync). CTA: 128 q-rows, 8 warps, 2 CTAs/SM.
// K/Vt tiles double-buffered via cp.async (load kt+1 during compute of kt).
// Smem: KV[2] blocks of (64*68 K + 64*68 Vt) floats, then Ps 128*68 floats.
// Q pre-scaled by 1/64 upstream -> softmax adds mask directly to S.
// ---------------------------------------------------------------------------
#define KVBUF_F (2 * 64 * 68)              // floats per KV buffer (K then Vt)
#define FLASH_SMEM_B ((2 * KVBUF_F + 128 * 68) * 4)   // 104448 bytes

__global__ void __launch_bounds__(256, 2) flash_tf32(const float* __restrict__ mask)
{
    extern __shared__ float sm[];
    float* Ps = sm + 2 * KVBUF_F;   // 128*68

    const int tid = threadIdx.x, warp = tid >> 5, lane = tid & 31;
    const int bh = blockIdx.y, b = bh >> 4, h = bh & 15;
    const int q0 = blockIdx.x * 128;

    const float* Qg  = g_q  + ((size_t)bh * NSEQ + q0) * HD;
    const float* Kg  = g_k  + (size_t)bh * NSEQ * HD;
    const float* Vtg = g_vt + (size_t)bh * HD * NSEQ;
    const float* Mg  = mask + (size_t)b * NSEQ * NSEQ + (size_t)q0 * NSEQ;

    const uint32_t sbase = saddr(sm);

    // async loader for K/Vt tile kt into buffer kt&1
    auto load_kv = [&](int kt) {
        const int k0 = kt * 64;
        const uint32_t kb = sbase + (kt & 1) * (KVBUF_F * 4);
#pragma unroll
        for (int i = 0; i < 4; i++) {
            int rr = (tid >> 4) + i * 16;
            int cc = (tid & 15) * 4;
            cpasync16(kb + (rr * 68 + cc) * 4,              Kg  + (size_t)(k0 + rr) * HD + cc);
            cpasync16(kb + (64 * 68 + rr * 68 + cc) * 4,    Vtg + (size_t)rr * NSEQ + k0 + cc);
        }
        CP_COMMIT();
    };

    load_kv(0);

    // stage Q via Ps, pick up fragments
#pragma unroll
    for (int i = 0; i < 8; i++) {
        int r = (tid >> 4) + i * 16;
        int c = (tid & 15) * 4;
        *(float4*)(Ps + r * 68 + c) = *(const float4*)(Qg + (size_t)r * HD + c);
    }
    __syncthreads();
    uint32_t qf[8][4];
    {
        int row = warp * 16 + (lane & 15);
        int cb  = (lane >> 4) << 2;
#pragma unroll
        for (int t = 0; t < 8; t++)
            ldsm_x4(qf[t], saddr(Ps + row * 68 + t * 8 + cb));
    }
    __syncthreads();   // Ps now free for P staging

    const int r  = lane >> 2;
    const int cq = lane & 3;
    float* Pw = Ps + warp * 16 * 68;

    float mrow[2] = {-INFINITY, -INFINITY};
    float lrow[2] = {0.0f, 0.0f};
    float o[8][4];
#pragma unroll
    for (int nt = 0; nt < 8; nt++)
#pragma unroll
        for (int j = 0; j < 4; j++) o[nt][j] = 0.0f;

    for (int kt = 0; kt < NSEQ / 64; kt++) {
        const int k0 = kt * 64;
        if (kt + 1 < NSEQ / 64) { load_kv(kt + 1); CP_WAIT(1); }
        else                    { CP_WAIT(0); }
        __syncthreads();

        float* Ks  = sm + (kt & 1) * KVBUF_F;
        float* Vts = Ks + 64 * 68;

        // S = Q K^T (Q pre-scaled by 1/64)
        float s[8][4];
#pragma unroll
        for (int nt = 0; nt < 8; nt++)
#pragma unroll
            for (int j = 0; j < 4; j++) s[nt][j] = 0.0f;

#pragma unroll
        for (int t = 0; t < 8; t++) {
            uint32_t bb[8][2];
#pragma unroll
            for (int p = 0; p < 4; p++) {
                int row = p * 16 + (lane & 7) + ((lane >> 4) << 3);
                int col = t * 8 + (((lane >> 3) & 1) << 2);
                uint32_t r4[4];
                ldsm_x4(r4, saddr(Ks + row * 68 + col));
                bb[2 * p][0] = r4[0]; bb[2 * p][1] = r4[1];
                bb[2 * p + 1][0] = r4[2]; bb[2 * p + 1][1] = r4[3];
            }
#pragma unroll
            for (int nt = 0; nt < 8; nt++) mma8(s[nt], qf[t], bb[nt]);
        }

        // online softmax (mask added directly; scale already folded into Q)
#pragma unroll
        for (int half = 0; half < 2; half++) {
            const float* mp = Mg + (size_t)(warp * 16 + r + half * 8) * NSEQ + k0;
            float sim[16];
            float vmax = -INFINITY;
#pragma unroll
            for (int nt = 0; nt < 8; nt++) {
                float2 mk = *(const float2*)(mp + nt * 8 + 2 * cq);
                sim[2 * nt]     = s[nt][half * 2 + 0] + mk.x;
                sim[2 * nt + 1] = s[nt][half * 2 + 1] + mk.y;
                vmax = fmaxf(vmax, fmaxf(sim[2 * nt], sim[2 * nt + 1]));
            }
            vmax = fmaxf(vmax, __shfl_xor_sync(0xffffffffu, vmax, 1, 4));
            vmax = fmaxf(vmax, __shfl_xor_sync(0xffffffffu, vmax, 2, 4));
            float mnew = fmaxf(mrow[half], vmax);
            float corr = __expf(mrow[half] - mnew);
            float sum = 0.0f;
#pragma unroll
            for (int nt = 0; nt < 8; nt++) {
                float p0 = __expf(sim[2 * nt]     - mnew);
                float p1 = __expf(sim[2 * nt + 1] - mnew);
                sum += p0 + p1;
                *(float2*)(Pw + (size_t)(r + half * 8) * 68 + nt * 8 + 2 * cq) =
                    make_float2(tf32r(p0), tf32r(p1));
            }
            sum += __shfl_xor_sync(0xffffffffu, sum, 1, 4);
            sum += __shfl_xor_sync(0xffffffffu, sum, 2, 4);
            lrow[half] = lrow[half] * corr + sum;
            mrow[half] = mnew;
#pragma unroll
            for (int nt = 0; nt < 8; nt++) {
                o[nt][half * 2 + 0] *= corr;
                o[nt][half * 2 + 1] *= corr;
            }
        }
        __syncwarp();

        // O += P V
#pragma unroll
        for (int t = 0; t < 8; t++) {
            uint32_t af[4];
            {
                int row = lane & 15;
                int col = t * 8 + ((lane >> 4) << 2);
                ldsm_x4(af, saddr(Pw + row * 68 + col));
            }
            uint32_t bb[8][2];
#pragma unroll
            for (int p = 0; p < 4; p++) {
                int row = p * 16 + (lane & 7) + ((lane >> 4) << 3);
                int col = t * 8 + (((lane >> 3) & 1) << 2);
                uint32_t r4[4];
                ldsm_x4(r4, saddr(Vts + row * 68 + col));
                bb[2 * p][0] = r4[0]; bb[2 * p][1] = r4[1];
                bb[2 * p + 1][0] = r4[2]; bb[2 * p + 1][1] = r4[3];
            }
#pragma unroll
            for (int nt = 0; nt < 8; nt++) mma8(o[nt], af, bb[nt]);
        }
        __syncthreads();   // all warps done with buffer (kt&1) before reuse
    }

    // epilogue: write bf16 hi/lo into gathered layout [b*2048+seq][h*64+d]
    float inv0 = 1.0f / lrow[0], inv1 = 1.0f / lrow[1];
#pragma unroll
    for (int nt = 0; nt < 8; nt++) {
        int col = h * HD + nt * 8 + 2 * cq;
#pragma unroll
        for (int half = 0; half < 2; half++) {
            int m = b * NSEQ + q0 + warp * 16 + r + half * 8;
            float inv = half ? inv1 : inv0;
            float v0 = o[nt][half * 2 + 0] * inv;
            float v1 = o[nt][half * 2 + 1] * inv;
            __nv_bfloat16 h0 = __float2bfloat16(v0);
            __nv_bfloat16 h1 = __float2bfloat16(v1);
            __nv_bfloat162 ph; ph.x = h0; ph.y = h1;
            __nv_bfloat162 pl;
            pl.x = __float2bfloat16(v0 - __bfloat162float(h0));
            pl.y = __float2bfloat16(v1 - __bfloat162float(h1));
            *(__nv_bfloat162*)(g_oh + (size_t)m * DIMF + col) = ph;
            *(__nv_bfloat162*)(g_ol + (size_t)m * DIMF + col) = pl;
        }
    }
}

// ---------------------------------------------------------------------------
// Launch
// ---------------------------------------------------------------------------
extern "C" void kernel_launch(void* const* d_in, const int* in_sizes, int n_in,
                              void* d_out, int out_size)
{
    const float* x    = (const float*)d_in[0];
    const float* mask = (const float*)d_in[1];
    const float* Wq   = (const float*)d_in[2];
    const float* Wk   = (const float*)d_in[3];
    const float* Wv   = (const float*)d_in[4];
    const float* Wo   = (const float*)d_in[5];
    const float* bo   = (const float*)d_in[6];
    float* out = (float*)d_out;

    const int GEMM_SMEM = 2 * STAGE_B;   // 81920 B
    cudaFuncSetAttribute(gemm_bf16<0>, cudaFuncAttributeMaxDynamicSharedMemorySize, GEMM_SMEM);
    cudaFuncSetAttribute(gemm_bf16<1>, cudaFuncAttributeMaxDynamicSharedMemorySize, GEMM_SMEM);
    cudaFuncSetAttribute(flash_tf32,   cudaFuncAttributeMaxDynamicSharedMemorySize, FLASH_SMEM_B);

    conv_split<<<MROWS + 4 * DIMF, 256>>>(x, Wq, Wk, Wv, Wo);

    gemm_bf16<0><<<dim3(8, 32, 3), 256, GEMM_SMEM>>>(nullptr, nullptr);

    rmsrope_kernel<<<dim3((BATCH * NH * NSEQ) / 8, 2), 256>>>();

    flash_tf32<<<dim3(NSEQ / 128, BATCH * NH), 256, FLASH_SMEM_B>>>(mask);

    gemm_bf16<1><<<dim3(8, 32), 256, GEMM_SMEM>>>(bo, out);
}

// round 8
// speedup vs baseline: 3.1039x; 1.1086x over previous
#include <cuda_runtime.h>
#include <cuda_bf16.h>
#include <math.h>
#include <stdint.h>

#define BATCH 2
#define NSEQ  2048
#define DIMF  1024
#define NH    16
#define HD    64
#define MROWS (BATCH * NSEQ)   // 4096

// fp32 scratch for attention path (Q/K/Vt tf32-rounded; Q pre-scaled by 1/64)
__device__ float g_q [BATCH * NH * NSEQ * HD];
__device__ float g_k [BATCH * NH * NSEQ * HD];
__device__ float g_vt[BATCH * NH * HD * NSEQ];   // [b,h,d,seq]

// bf16 hi/lo split operands (row-major)
__device__ __nv_bfloat16 g_xh[(size_t)MROWS * DIMF];
__device__ __nv_bfloat16 g_xl[(size_t)MROWS * DIMF];
__device__ __nv_bfloat16 g_oh[(size_t)MROWS * DIMF];
__device__ __nv_bfloat16 g_ol[(size_t)MROWS * DIMF];
__device__ __nv_bfloat16 g_wh[(size_t)4 * DIMF * DIMF];
__device__ __nv_bfloat16 g_wl[(size_t)4 * DIMF * DIMF];

__device__ int g_mask_nz;   // runtime flag: mask has any nonzero element

// ---------------------------------------------------------------------------
// helpers
// ---------------------------------------------------------------------------
__device__ __forceinline__ uint32_t saddr(const void* p) {
    return (uint32_t)__cvta_generic_to_shared(p);
}
__device__ __forceinline__ float tf32r(float x) {
    uint32_t u;
    asm("cvt.rna.tf32.f32 %0, %1;" : "=r"(u) : "f"(x));
    return __uint_as_float(u);
}
__device__ __forceinline__ void ldsm_x4(uint32_t r[4], uint32_t a) {
    asm volatile("ldmatrix.sync.aligned.m8n8.x4.shared.b16 {%0,%1,%2,%3}, [%4];"
                 : "=r"(r[0]), "=r"(r[1]), "=r"(r[2]), "=r"(r[3]) : "r"(a));
}
__device__ __forceinline__ void mma8(float c[4], const uint32_t a[4], const uint32_t b[2]) {
    asm volatile(
        "mma.sync.aligned.m16n8k8.row.col.f32.tf32.tf32.f32 "
        "{%0,%1,%2,%3}, {%4,%5,%6,%7}, {%8,%9}, {%0,%1,%2,%3};"
        : "+f"(c[0]), "+f"(c[1]), "+f"(c[2]), "+f"(c[3])
        : "r"(a[0]), "r"(a[1]), "r"(a[2]), "r"(a[3]), "r"(b[0]), "r"(b[1]));
}
__device__ __forceinline__ void mma16(float c[4], const uint32_t a[4], const uint32_t b[2]) {
    asm volatile(
        "mma.sync.aligned.m16n8k16.row.col.f32.bf16.bf16.f32 "
        "{%0,%1,%2,%3}, {%4,%5,%6,%7}, {%8,%9}, {%0,%1,%2,%3};"
        : "+f"(c[0]), "+f"(c[1]), "+f"(c[2]), "+f"(c[3])
        : "r"(a[0]), "r"(a[1]), "r"(a[2]), "r"(a[3]), "r"(b[0]), "r"(b[1]));
}
__device__ __forceinline__ void cpasync16(uint32_t s, const void* g) {
    asm volatile("cp.async.cg.shared.global [%0], [%1], 16;" :: "r"(s), "l"(g) : "memory");
}
#define CP_COMMIT()  asm volatile("cp.async.commit_group;" ::: "memory")
#define CP_WAIT(n)   asm volatile("cp.async.wait_group %0;" :: "n"(n) : "memory")

// ---------------------------------------------------------------------------
// mask scan: reset flag, then OR-reduce nonzero-ness of the mask
// ---------------------------------------------------------------------------
__global__ void mask_reset() { g_mask_nz = 0; }

__global__ void __launch_bounds__(256) mask_scan(const float* __restrict__ mask, int n4)
{
    const float4* m4 = (const float4*)mask;
    uint32_t acc = 0;
    for (int i = blockIdx.x * 256 + threadIdx.x; i < n4; i += gridDim.x * 256) {
        float4 v = m4[i];
        acc |= __float_as_uint(v.x) | __float_as_uint(v.y)
             | __float_as_uint(v.z) | __float_as_uint(v.w);
    }
    // any set bit (including -0.0 sign) counts as "not all +0.0"
    if (acc) atomicOr(&g_mask_nz, 1);
}

// ---------------------------------------------------------------------------
// Split fp32 -> bf16 hi/lo (row-major). 8192 rows of 1024: x then Wq/Wk/Wv/Wo.
// ---------------------------------------------------------------------------
__global__ void __launch_bounds__(256) conv_split(
    const float* __restrict__ x,
    const float* __restrict__ Wq, const float* __restrict__ Wk,
    const float* __restrict__ Wv, const float* __restrict__ Wo)
{
    const int row = blockIdx.x;
    const float* src;
    __nv_bfloat16 *dh, *dl;
    if (row < MROWS) {
        src = x + (size_t)row * DIMF;
        dh = g_xh + (size_t)row * DIMF;
        dl = g_xl + (size_t)row * DIMF;
    } else {
        int wi = (row - MROWS) >> 10, r = (row - MROWS) & 1023;
        const float* W = (wi == 0) ? Wq : (wi == 1) ? Wk : (wi == 2) ? Wv : Wo;
        src = W + (size_t)r * DIMF;
        dh = g_wh + ((size_t)wi * DIMF + r) * DIMF;
        dl = g_wl + ((size_t)wi * DIMF + r) * DIMF;
    }
    const int c = threadIdx.x * 4;
    float4 v = *(const float4*)(src + c);
    __nv_bfloat16 h0 = __float2bfloat16(v.x);
    __nv_bfloat16 h1 = __float2bfloat16(v.y);
    __nv_bfloat16 h2 = __float2bfloat16(v.z);
    __nv_bfloat16 h3 = __float2bfloat16(v.w);
    __nv_bfloat162 ph0; ph0.x = h0; ph0.y = h1;
    __nv_bfloat162 ph1; ph1.x = h2; ph1.y = h3;
    __nv_bfloat162 pl0; pl0.x = __float2bfloat16(v.x - __bfloat162float(h0));
    pl0.y = __float2bfloat16(v.y - __bfloat162float(h1));
    __nv_bfloat162 pl1; pl1.x = __float2bfloat16(v.z - __bfloat162float(h2));
    pl1.y = __float2bfloat16(v.w - __bfloat162float(h3));
    *(__nv_bfloat162*)(dh + c)     = ph0;
    *(__nv_bfloat162*)(dh + c + 2) = ph1;
    *(__nv_bfloat162*)(dl + c)     = pl0;
    *(__nv_bfloat162*)(dl + c + 2) = pl1;
}

// ---------------------------------------------------------------------------
// bf16 3-pass GEMM (NT), unchanged from R7
// ---------------------------------------------------------------------------
#define TILE_B 10240
#define STAGE_B (4 * TILE_B)

template <int OUT>
__global__ void __launch_bounds__(256, 2) gemm_bf16(
    const float* __restrict__ bias, float* __restrict__ Cout)
{
    extern __shared__ char smem[];
    const uint32_t sbase = saddr(smem);
    const int tid = threadIdx.x, warp = tid >> 5, lane = tid & 31;
    const int m0 = blockIdx.y * 128, n0 = blockIdx.x * 128;
    const int z = OUT ? 3 : blockIdx.z;

    const __nv_bfloat16* Ah = OUT ? g_oh : g_xh;
    const __nv_bfloat16* Al = OUT ? g_ol : g_xl;
    const __nv_bfloat16* Bh = g_wh + (size_t)z * DIMF * DIMF;
    const __nv_bfloat16* Bl = g_wl + (size_t)z * DIMF * DIMF;

    const int lrow = tid >> 1;
    const int lq   = (tid & 1) * 2;

    auto load_stage = [&](int s) {
        const uint32_t d0 = sbase + (s & 1) * STAGE_B + lrow * 80 + lq * 16;
        const int kc = s * 32 + lq * 8;
        const __nv_bfloat16* pa = Ah + (size_t)(m0 + lrow) * DIMF + kc;
        const __nv_bfloat16* pl = Al + (size_t)(m0 + lrow) * DIMF + kc;
        const __nv_bfloat16* pb = Bh + (size_t)(n0 + lrow) * DIMF + kc;
        const __nv_bfloat16* pq = Bl + (size_t)(n0 + lrow) * DIMF + kc;
        cpasync16(d0,                pa);     cpasync16(d0 + 16,                pa + 8);
        cpasync16(d0 + TILE_B,       pl);     cpasync16(d0 + TILE_B + 16,       pl + 8);
        cpasync16(d0 + 2 * TILE_B,   pb);     cpasync16(d0 + 2 * TILE_B + 16,   pb + 8);
        cpasync16(d0 + 3 * TILE_B,   pq);     cpasync16(d0 + 3 * TILE_B + 16,   pq + 8);
        CP_COMMIT();
    };

    float acc[2][8][4];
#pragma unroll
    for (int i = 0; i < 2; i++)
#pragma unroll
        for (int j = 0; j < 8; j++)
#pragma unroll
            for (int l = 0; l < 4; l++) acc[i][j][l] = 0.0f;

    const int mw = (warp >> 1) * 32;
    const int nw = (warp & 1) * 64;

    load_stage(0);
    load_stage(1);

    for (int s = 0; s < 32; s++) {
        if (s == 31) CP_WAIT(0); else CP_WAIT(1);
        __syncthreads();

        const uint32_t base = sbase + (s & 1) * STAGE_B;
#pragma unroll
        for (int t = 0; t < 2; t++) {
            const int kk = t * 16;
            uint32_t ahi[2][4], alo[2][4];
#pragma unroll
            for (int mt = 0; mt < 2; mt++) {
                uint32_t addr = base + (mw + mt * 16 + (lane & 15)) * 80
                              + kk * 2 + ((lane >> 4) << 4);
                ldsm_x4(ahi[mt], addr);
                ldsm_x4(alo[mt], addr + TILE_B);
            }
#pragma unroll
            for (int p = 0; p < 4; p++) {
                uint32_t baddr = base + 2 * TILE_B
                               + (nw + p * 16 + (lane & 7) + ((lane >> 4) << 3)) * 80
                               + kk * 2 + (((lane >> 3) & 1) << 4);
                uint32_t bh4[4], bl4[4];
                ldsm_x4(bh4, baddr);
                ldsm_x4(bl4, baddr + TILE_B);
#pragma unroll
                for (int mt = 0; mt < 2; mt++) {
                    mma16(acc[mt][2 * p],     ahi[mt], bh4);
                    mma16(acc[mt][2 * p],     ahi[mt], bl4);
                    mma16(acc[mt][2 * p],     alo[mt], bh4);
                    mma16(acc[mt][2 * p + 1], ahi[mt], bh4 + 2);
                    mma16(acc[mt][2 * p + 1], ahi[mt], bl4 + 2);
                    mma16(acc[mt][2 * p + 1], alo[mt], bh4 + 2);
                }
            }
        }
        __syncthreads();
        if (s + 2 < 32) load_stage(s + 2);
    }

#pragma unroll
    for (int mt = 0; mt < 2; mt++) {
#pragma unroll
        for (int nt = 0; nt < 8; nt++) {
#pragma unroll
            for (int half = 0; half < 2; half++) {
                int m = m0 + mw + mt * 16 + (lane >> 2) + half * 8;
                int c = n0 + nw + nt * 8 + ((lane & 3) << 1);
                float2 v = make_float2(acc[mt][nt][half * 2 + 0],
                                       acc[mt][nt][half * 2 + 1]);
                if (OUT) {
                    const float2 bb2 = *(const float2*)(bias + c);
                    v.x += bb2.x; v.y += bb2.y;
                    *(float2*)(Cout + (size_t)m * DIMF + c) = v;
                } else {
                    int bb = m >> 11, n = m & (NSEQ - 1);
                    int h = c >> 6, d = c & (HD - 1);
                    if (z == 2) {
                        float* basep = g_vt + (((size_t)(bb * NH + h) * HD + d) * NSEQ) + n;
                        basep[0]    = tf32r(v.x);
                        basep[NSEQ] = tf32r(v.y);
                    } else {
                        float* dst = (z == 0 ? g_q : g_k)
                                   + (((size_t)(bb * NH + h) * NSEQ + n) << 6) + d;
                        *(float2*)dst = v;
                    }
                }
            }
        }
    }
}

// ---------------------------------------------------------------------------
// RMSNorm + RoPE (tf32-rounded; Q pre-scaled by 1/64)
// ---------------------------------------------------------------------------
__global__ void __launch_bounds__(256) rmsrope_kernel()
{
    const int warp = threadIdx.x >> 5;
    const int lane = threadIdx.x & 31;
    const size_t row = (size_t)blockIdx.x * 8 + warp;
    const int isQ = (blockIdx.y == 0);
    float* ptr = (isQ ? g_q : g_k) + row * HD;

    float2 x = *(float2*)(ptr + lane * 2);
    float ss = x.x * x.x + x.y * x.y;
#pragma unroll
    for (int off = 16; off; off >>= 1)
        ss += __shfl_xor_sync(0xffffffffu, ss, off);
    float rn = rsqrtf(ss * (1.0f / 64.0f) + 1e-5f);

    int pos = (int)(row & (NSEQ - 1));
    float ifr = exp2f((float)lane * (-2.0f / 64.0f) * 13.287712379549449f);
    float ang = (float)pos * ifr;
    float s, c;
    sincosf(ang, &s, &c);

    float x0 = x.x * rn, x1 = x.y * rn;
    float post = isQ ? 0.015625f : 1.0f;
    float2 y;
    y.x = tf32r((x0 * c - x1 * s) * post);
    y.y = tf32r((x1 * c + x0 * s) * post);
    *(float2*)(ptr + lane * 2) = y;
}

// ---------------------------------------------------------------------------
// Flash attention: 128 threads (4 warps), 32 q-rows/warp (2x m16 frags),
// K/V fragments shared across both row-tiles -> half the smem traffic/row.
// Double-buffered cp.async K/V. 2 CTAs/SM.
// ---------------------------------------------------------------------------
#define KVBUF_F (2 * 64 * 68)
#define FLASH_SMEM_B ((2 * KVBUF_F + 128 * 68) * 4)   // 104448 bytes

__global__ void __launch_bounds__(128) flash_tf32(const float* __restrict__ mask)
{
    extern __shared__ float sm[];
    float* Ps = sm + 2 * KVBUF_F;   // 128*68

    const int tid = threadIdx.x, warp = tid >> 5, lane = tid & 31;
    const int bh = blockIdx.y, b = bh >> 4, h = bh & 15;
    const int q0 = blockIdx.x * 128;
    const int mnz = g_mask_nz;

    const float* Qg  = g_q  + ((size_t)bh * NSEQ + q0) * HD;
    const float* Kg  = g_k  + (size_t)bh * NSEQ * HD;
    const float* Vtg = g_vt + (size_t)bh * HD * NSEQ;
    const float* Mg  = mask + (size_t)b * NSEQ * NSEQ + (size_t)q0 * NSEQ;

    const uint32_t sbase = saddr(sm);

    auto load_kv = [&](int kt) {
        const int k0 = kt * 64;
        const uint32_t kb = sbase + (kt & 1) * (KVBUF_F * 4);
        const int rbase = tid >> 4;
        const int cc = (tid & 15) * 4;
#pragma unroll
        for (int i = 0; i < 8; i++) {
            int rr = rbase + i * 8;
            cpasync16(kb + (rr * 68 + cc) * 4,           Kg  + (size_t)(k0 + rr) * HD + cc);
            cpasync16(kb + (64 * 68 + rr * 68 + cc) * 4, Vtg + (size_t)rr * NSEQ + k0 + cc);
        }
        CP_COMMIT();
    };

    load_kv(0);

    // stage Q (rows 0..127) via Ps, pick up fragments for this warp's 32 rows
    {
        const int rbase = tid >> 4;
        const int c = (tid & 15) * 4;
#pragma unroll
        for (int i = 0; i < 16; i++) {
            int r = rbase + i * 8;
            *(float4*)(Ps + r * 68 + c) = *(const float4*)(Qg + (size_t)r * HD + c);
        }
    }
    __syncthreads();
    uint32_t qf[2][8][4];
#pragma unroll
    for (int mt = 0; mt < 2; mt++) {
        int row = warp * 32 + mt * 16 + (lane & 15);
        int cb  = (lane >> 4) << 2;
#pragma unroll
        for (int t = 0; t < 8; t++)
            ldsm_x4(qf[mt][t], saddr(Ps + row * 68 + t * 8 + cb));
    }
    __syncthreads();   // Ps now free for P staging

    const int r  = lane >> 2;
    const int cq = lane & 3;
    float* Pw = Ps + warp * 32 * 68;

    float mrow[2][2] = {{-INFINITY, -INFINITY}, {-INFINITY, -INFINITY}};
    float lrow[2][2] = {{0.0f, 0.0f}, {0.0f, 0.0f}};
    float o[2][8][4];
#pragma unroll
    for (int mt = 0; mt < 2; mt++)
#pragma unroll
        for (int nt = 0; nt < 8; nt++)
#pragma unroll
            for (int j = 0; j < 4; j++) o[mt][nt][j] = 0.0f;

    for (int kt = 0; kt < NSEQ / 64; kt++) {
        const int k0 = kt * 64;
        if (kt + 1 < NSEQ / 64) { load_kv(kt + 1); CP_WAIT(1); }
        else                    { CP_WAIT(0); }
        __syncthreads();

        float* Ks  = sm + (kt & 1) * KVBUF_F;
        float* Vts = Ks + 64 * 68;

        // S = Q K^T for both 16-row tiles, sharing K fragments
        float s[2][8][4];
#pragma unroll
        for (int mt = 0; mt < 2; mt++)
#pragma unroll
            for (int nt = 0; nt < 8; nt++)
#pragma unroll
                for (int j = 0; j < 4; j++) s[mt][nt][j] = 0.0f;

#pragma unroll
        for (int t = 0; t < 8; t++) {
            uint32_t bb[8][2];
#pragma unroll
            for (int p = 0; p < 4; p++) {
                int row = p * 16 + (lane & 7) + ((lane >> 4) << 3);
                int col = t * 8 + (((lane >> 3) & 1) << 2);
                uint32_t r4[4];
                ldsm_x4(r4, saddr(Ks + row * 68 + col));
                bb[2 * p][0] = r4[0]; bb[2 * p][1] = r4[1];
                bb[2 * p + 1][0] = r4[2]; bb[2 * p + 1][1] = r4[3];
            }
#pragma unroll
            for (int nt = 0; nt < 8; nt++) {
                mma8(s[0][nt], qf[0][t], bb[nt]);
                mma8(s[1][nt], qf[1][t], bb[nt]);
            }
        }

        // online softmax per (mt, half)
#pragma unroll
        for (int mt = 0; mt < 2; mt++) {
#pragma unroll
            for (int half = 0; half < 2; half++) {
                float sim[16];
                float vmax = -INFINITY;
                if (mnz) {
                    const float* mp = Mg + (size_t)(warp * 32 + mt * 16 + r + half * 8) * NSEQ + k0;
#pragma unroll
                    for (int nt = 0; nt < 8; nt++) {
                        float2 mk = *(const float2*)(mp + nt * 8 + 2 * cq);
                        sim[2 * nt]     = s[mt][nt][half * 2 + 0] + mk.x;
                        sim[2 * nt + 1] = s[mt][nt][half * 2 + 1] + mk.y;
                        vmax = fmaxf(vmax, fmaxf(sim[2 * nt], sim[2 * nt + 1]));
                    }
                } else {
#pragma unroll
                    for (int nt = 0; nt < 8; nt++) {
                        sim[2 * nt]     = s[mt][nt][half * 2 + 0];
                        sim[2 * nt + 1] = s[mt][nt][half * 2 + 1];
                        vmax = fmaxf(vmax, fmaxf(sim[2 * nt], sim[2 * nt + 1]));
                    }
                }
                vmax = fmaxf(vmax, __shfl_xor_sync(0xffffffffu, vmax, 1, 4));
                vmax = fmaxf(vmax, __shfl_xor_sync(0xffffffffu, vmax, 2, 4));
                float mnew = fmaxf(mrow[mt][half], vmax);
                float corr = __expf(mrow[mt][half] - mnew);
                float sum = 0.0f;
#pragma unroll
                for (int nt = 0; nt < 8; nt++) {
                    float p0 = __expf(sim[2 * nt]     - mnew);
                    float p1 = __expf(sim[2 * nt + 1] - mnew);
                    sum += p0 + p1;
                    *(float2*)(Pw + (size_t)(mt * 16 + r + half * 8) * 68 + nt * 8 + 2 * cq) =
                        make_float2(tf32r(p0), tf32r(p1));
                }
                sum += __shfl_xor_sync(0xffffffffu, sum, 1, 4);
                sum += __shfl_xor_sync(0xffffffffu, sum, 2, 4);
                lrow[mt][half] = lrow[mt][half] * corr + sum;
                mrow[mt][half] = mnew;
#pragma unroll
                for (int nt = 0; nt < 8; nt++) {
                    o[mt][nt][half * 2 + 0] *= corr;
                    o[mt][nt][half * 2 + 1] *= corr;
                }
            }
        }
        __syncwarp();

        // O += P V, sharing V fragments across both row-tiles
#pragma unroll
        for (int t = 0; t < 8; t++) {
            uint32_t af[2][4];
#pragma unroll
            for (int mt = 0; mt < 2; mt++) {
                int row = mt * 16 + (lane & 15);
                int col = t * 8 + ((lane >> 4) << 2);
                ldsm_x4(af[mt], saddr(Pw + row * 68 + col));
            }
            uint32_t bb[8][2];
#pragma unroll
            for (int p = 0; p < 4; p++) {
                int row = p * 16 + (lane & 7) + ((lane >> 4) << 3);
                int col = t * 8 + (((lane >> 3) & 1) << 2);
                uint32_t r4[4];
                ldsm_x4(r4, saddr(Vts + row * 68 + col));
                bb[2 * p][0] = r4[0]; bb[2 * p][1] = r4[1];
                bb[2 * p + 1][0] = r4[2]; bb[2 * p + 1][1] = r4[3];
            }
#pragma unroll
            for (int nt = 0; nt < 8; nt++) {
                mma8(o[0][nt], af[0], bb[nt]);
                mma8(o[1][nt], af[1], bb[nt]);
            }
        }
        __syncthreads();
    }

    // epilogue: bf16 hi/lo into gathered layout [b*2048+seq][h*64+d]
#pragma unroll
    for (int mt = 0; mt < 2; mt++) {
        float inv0 = 1.0f / lrow[mt][0], inv1 = 1.0f / lrow[mt][1];
#pragma unroll
        for (int nt = 0; nt < 8; nt++) {
            int col = h * HD + nt * 8 + 2 * cq;
#pragma unroll
            for (int half = 0; half < 2; half++) {
                int m = b * NSEQ + q0 + warp * 32 + mt * 16 + r + half * 8;
                float inv = half ? inv1 : inv0;
                float v0 = o[mt][nt][half * 2 + 0] * inv;
                float v1 = o[mt][nt][half * 2 + 1] * inv;
                __nv_bfloat16 h0 = __float2bfloat16(v0);
                __nv_bfloat16 h1 = __float2bfloat16(v1);
                __nv_bfloat162 ph; ph.x = h0; ph.y = h1;
                __nv_bfloat162 pl;
                pl.x = __float2bfloat16(v0 - __bfloat162float(h0));
                pl.y = __float2bfloat16(v1 - __bfloat162float(h1));
                *(__nv_bfloat162*)(g_oh + (size_t)m * DIMF + col) = ph;
                *(__nv_bfloat162*)(g_ol + (size_t)m * DIMF + col) = pl;
            }
        }
    }
}

// ---------------------------------------------------------------------------
// Launch
// ---------------------------------------------------------------------------
extern "C" void kernel_launch(void* const* d_in, const int* in_sizes, int n_in,
                              void* d_out, int out_size)
{
    const float* x    = (const float*)d_in[0];
    const float* mask = (const float*)d_in[1];
    const float* Wq   = (const float*)d_in[2];
    const float* Wk   = (const float*)d_in[3];
    const float* Wv   = (const float*)d_in[4];
    const float* Wo   = (const float*)d_in[5];
    const float* bo   = (const float*)d_in[6];
    float* out = (float*)d_out;

    const int GEMM_SMEM = 2 * STAGE_B;   // 81920 B
    cudaFuncSetAttribute(gemm_bf16<0>, cudaFuncAttributeMaxDynamicSharedMemorySize, GEMM_SMEM);
    cudaFuncSetAttribute(gemm_bf16<1>, cudaFuncAttributeMaxDynamicSharedMemorySize, GEMM_SMEM);
    cudaFuncSetAttribute(flash_tf32,   cudaFuncAttributeMaxDynamicSharedMemorySize, FLASH_SMEM_B);

    mask_reset<<<1, 1>>>();
    mask_scan<<<256, 256>>>(mask, (BATCH * NSEQ * NSEQ) / 4);

    conv_split<<<MROWS + 4 * DIMF, 256>>>(x, Wq, Wk, Wv, Wo);

    gemm_bf16<0><<<dim3(8, 32, 3), 256, GEMM_SMEM>>>(nullptr, nullptr);

    rmsrope_kernel<<<dim3((BATCH * NH * NSEQ) / 8, 2), 256>>>();

    flash_tf32<<<dim3(NSEQ / 128, BATCH * NH), 128, FLASH_SMEM_B>>>(mask);

    gemm_bf16<1><<<dim3(8, 32), 256, GEMM_SMEM>>>(bo, out);
}

// round 9
// speedup vs baseline: 3.6568x; 1.1782x over previous
#include <cuda_runtime.h>
#include <cuda_fp16.h>
#include <cuda_bf16.h>
#include <math.h>
#include <stdint.h>

#define BATCH 2
#define NSEQ  2048
#define DIMF  1024
#define NH    16
#define HD    64
#define MROWS (BATCH * NSEQ)   // 4096

// fp32 scratch for attention path (Q/K/Vt tf32-rounded; Q pre-scaled by 1/64)
__device__ float g_q [BATCH * NH * NSEQ * HD];
__device__ float g_k [BATCH * NH * NSEQ * HD];
__device__ float g_vt[BATCH * NH * HD * NSEQ];   // [b,h,d,seq]

// fp16 GEMM operands: A single-rounded, weights hi/lo split
__device__ __half g_x16[(size_t)MROWS * DIMF];
__device__ __half g_o16[(size_t)MROWS * DIMF];   // flash output, gathered layout
__device__ __half g_wh [(size_t)4 * DIMF * DIMF];
__device__ __half g_wl [(size_t)4 * DIMF * DIMF];

__device__ int g_mask_nz;   // runtime flag: mask has any nonzero element

// ---------------------------------------------------------------------------
// helpers
// ---------------------------------------------------------------------------
__device__ __forceinline__ uint32_t saddr(const void* p) {
    return (uint32_t)__cvta_generic_to_shared(p);
}
__device__ __forceinline__ float tf32r(float x) {
    uint32_t u;
    asm("cvt.rna.tf32.f32 %0, %1;" : "=r"(u) : "f"(x));
    return __uint_as_float(u);
}
__device__ __forceinline__ void ldsm_x4(uint32_t r[4], uint32_t a) {
    asm volatile("ldmatrix.sync.aligned.m8n8.x4.shared.b16 {%0,%1,%2,%3}, [%4];"
                 : "=r"(r[0]), "=r"(r[1]), "=r"(r[2]), "=r"(r[3]) : "r"(a));
}
// tf32 m16n8k8 (flash)
__device__ __forceinline__ void mma8(float c[4], const uint32_t a[4], const uint32_t b[2]) {
    asm volatile(
        "mma.sync.aligned.m16n8k8.row.col.f32.tf32.tf32.f32 "
        "{%0,%1,%2,%3}, {%4,%5,%6,%7}, {%8,%9}, {%0,%1,%2,%3};"
        : "+f"(c[0]), "+f"(c[1]), "+f"(c[2]), "+f"(c[3])
        : "r"(a[0]), "r"(a[1]), "r"(a[2]), "r"(a[3]), "r"(b[0]), "r"(b[1]));
}
// fp16 m16n8k16 (GEMMs)
__device__ __forceinline__ void mma16h(float c[4], const uint32_t a[4], const uint32_t b[2]) {
    asm volatile(
        "mma.sync.aligned.m16n8k16.row.col.f32.f16.f16.f32 "
        "{%0,%1,%2,%3}, {%4,%5,%6,%7}, {%8,%9}, {%0,%1,%2,%3};"
        : "+f"(c[0]), "+f"(c[1]), "+f"(c[2]), "+f"(c[3])
        : "r"(a[0]), "r"(a[1]), "r"(a[2]), "r"(a[3]), "r"(b[0]), "r"(b[1]));
}
__device__ __forceinline__ void cpasync16(uint32_t s, const void* g) {
    asm volatile("cp.async.cg.shared.global [%0], [%1], 16;" :: "r"(s), "l"(g) : "memory");
}
#define CP_COMMIT()  asm volatile("cp.async.commit_group;" ::: "memory")
#define CP_WAIT(n)   asm volatile("cp.async.wait_group %0;" :: "n"(n) : "memory")

// ---------------------------------------------------------------------------
// mask scan
// ---------------------------------------------------------------------------
__global__ void mask_reset() { g_mask_nz = 0; }

__global__ void __launch_bounds__(256) mask_scan(const float* __restrict__ mask, int n4)
{
    const float4* m4 = (const float4*)mask;
    uint32_t acc = 0;
    for (int i = blockIdx.x * 256 + threadIdx.x; i < n4; i += gridDim.x * 256) {
        float4 v = m4[i];
        acc |= __float_as_uint(v.x) | __float_as_uint(v.y)
             | __float_as_uint(v.z) | __float_as_uint(v.w);
    }
    if (acc) atomicOr(&g_mask_nz, 1);
}

// ---------------------------------------------------------------------------
// Convert: x rows -> g_x16 (single fp16); weight rows -> g_wh + g_wl (split)
// ---------------------------------------------------------------------------
__global__ void __launch_bounds__(256) conv_split(
    const float* __restrict__ x,
    const float* __restrict__ Wq, const float* __restrict__ Wk,
    const float* __restrict__ Wv, const float* __restrict__ Wo)
{
    const int row = blockIdx.x;
    const int c = threadIdx.x * 4;
    if (row < MROWS) {
        float4 v = *(const float4*)(x + (size_t)row * DIMF + c);
        __half2 p0; p0.x = __float2half(v.x); p0.y = __float2half(v.y);
        __half2 p1; p1.x = __float2half(v.z); p1.y = __float2half(v.w);
        *(__half2*)(g_x16 + (size_t)row * DIMF + c)     = p0;
        *(__half2*)(g_x16 + (size_t)row * DIMF + c + 2) = p1;
    } else {
        int wi = (row - MROWS) >> 10, r = (row - MROWS) & 1023;
        const float* W = (wi == 0) ? Wq : (wi == 1) ? Wk : (wi == 2) ? Wv : Wo;
        float4 v = *(const float4*)(W + (size_t)r * DIMF + c);
        __half h0 = __float2half(v.x), h1 = __float2half(v.y);
        __half h2 = __float2half(v.z), h3 = __float2half(v.w);
        __half2 ph0; ph0.x = h0; ph0.y = h1;
        __half2 ph1; ph1.x = h2; ph1.y = h3;
        __half2 pl0; pl0.x = __float2half(v.x - __half2float(h0));
        pl0.y = __float2half(v.y - __half2float(h1));
        __half2 pl1; pl1.x = __float2half(v.z - __half2float(h2));
        pl1.y = __float2half(v.w - __half2float(h3));
        __half* dh = g_wh + ((size_t)wi * DIMF + r) * DIMF;
        __half* dl = g_wl + ((size_t)wi * DIMF + r) * DIMF;
        *(__half2*)(dh + c)     = ph0;
        *(__half2*)(dh + c + 2) = ph1;
        *(__half2*)(dl + c)     = pl0;
        *(__half2*)(dl + c + 2) = pl1;
    }
}

// ---------------------------------------------------------------------------
// fp16 2-pass GEMM (NT): C = A16[M,K] * (Wh+Wl)[N,K]^T
// CTA 128x128, BK=32, 256 threads (8 warps 4x2, warp tile 32x64),
// 2-stage cp.async. Stage = 3 tiles (A, Bh, Bl) of 10240B.
// ---------------------------------------------------------------------------
#define TILE_B 10240
#define STAGE_B (3 * TILE_B)

template <int OUT>
__global__ void __launch_bounds__(256, 2) gemm_fp16(
    const float* __restrict__ bias, float* __restrict__ Cout)
{
    extern __shared__ char smem[];
    const uint32_t sbase = saddr(smem);
    const int tid = threadIdx.x, warp = tid >> 5, lane = tid & 31;
    const int m0 = blockIdx.y * 128, n0 = blockIdx.x * 128;
    const int z = OUT ? 3 : blockIdx.z;

    const __half* A  = OUT ? g_o16 : g_x16;
    const __half* Bh = g_wh + (size_t)z * DIMF * DIMF;
    const __half* Bl = g_wl + (size_t)z * DIMF * DIMF;

    const int lrow = tid >> 1;
    const int lq   = (tid & 1) * 2;

    auto load_stage = [&](int s) {
        const uint32_t d0 = sbase + (s & 1) * STAGE_B + lrow * 80 + lq * 16;
        const int kc = s * 32 + lq * 8;
        const __half* pa = A  + (size_t)(m0 + lrow) * DIMF + kc;
        const __half* pb = Bh + (size_t)(n0 + lrow) * DIMF + kc;
        const __half* pq = Bl + (size_t)(n0 + lrow) * DIMF + kc;
        cpasync16(d0,              pa);   cpasync16(d0 + 16,              pa + 8);
        cpasync16(d0 + TILE_B,     pb);   cpasync16(d0 + TILE_B + 16,     pb + 8);
        cpasync16(d0 + 2 * TILE_B, pq);   cpasync16(d0 + 2 * TILE_B + 16, pq + 8);
        CP_COMMIT();
    };

    float acc[2][8][4];
#pragma unroll
    for (int i = 0; i < 2; i++)
#pragma unroll
        for (int j = 0; j < 8; j++)
#pragma unroll
            for (int l = 0; l < 4; l++) acc[i][j][l] = 0.0f;

    const int mw = (warp >> 1) * 32;
    const int nw = (warp & 1) * 64;

    load_stage(0);
    load_stage(1);

    for (int s = 0; s < 32; s++) {
        if (s == 31) CP_WAIT(0); else CP_WAIT(1);
        __syncthreads();

        const uint32_t base = sbase + (s & 1) * STAGE_B;
#pragma unroll
        for (int t = 0; t < 2; t++) {
            const int kk = t * 16;
            uint32_t a16[2][4];
#pragma unroll
            for (int mt = 0; mt < 2; mt++) {
                uint32_t addr = base + (mw + mt * 16 + (lane & 15)) * 80
                              + kk * 2 + ((lane >> 4) << 4);
                ldsm_x4(a16[mt], addr);
            }
#pragma unroll
            for (int p = 0; p < 4; p++) {
                uint32_t baddr = base + TILE_B
                               + (nw + p * 16 + (lane & 7) + ((lane >> 4) << 3)) * 80
                               + kk * 2 + (((lane >> 3) & 1) << 4);
                uint32_t bh4[4], bl4[4];
                ldsm_x4(bh4, baddr);
                ldsm_x4(bl4, baddr + TILE_B);
#pragma unroll
                for (int mt = 0; mt < 2; mt++) {
                    mma16h(acc[mt][2 * p],     a16[mt], bh4);
                    mma16h(acc[mt][2 * p],     a16[mt], bl4);
                    mma16h(acc[mt][2 * p + 1], a16[mt], bh4 + 2);
                    mma16h(acc[mt][2 * p + 1], a16[mt], bl4 + 2);
                }
            }
        }
        __syncthreads();
        if (s + 2 < 32) load_stage(s + 2);
    }

    // epilogue
#pragma unroll
    for (int mt = 0; mt < 2; mt++) {
#pragma unroll
        for (int nt = 0; nt < 8; nt++) {
#pragma unroll
            for (int half = 0; half < 2; half++) {
                int m = m0 + mw + mt * 16 + (lane >> 2) + half * 8;
                int c = n0 + nw + nt * 8 + ((lane & 3) << 1);
                float2 v = make_float2(acc[mt][nt][half * 2 + 0],
                                       acc[mt][nt][half * 2 + 1]);
                if (OUT) {
                    const float2 bb2 = *(const float2*)(bias + c);
                    v.x += bb2.x; v.y += bb2.y;
                    *(float2*)(Cout + (size_t)m * DIMF + c) = v;
                } else {
                    int bb = m >> 11, n = m & (NSEQ - 1);
                    int h = c >> 6, d = c & (HD - 1);
                    if (z == 2) {
                        float* basep = g_vt + (((size_t)(bb * NH + h) * HD + d) * NSEQ) + n;
                        basep[0]    = tf32r(v.x);
                        basep[NSEQ] = tf32r(v.y);
                    } else {
                        float* dst = (z == 0 ? g_q : g_k)
                                   + (((size_t)(bb * NH + h) * NSEQ + n) << 6) + d;
                        *(float2*)dst = v;
                    }
                }
            }
        }
    }
}

// ---------------------------------------------------------------------------
// RMSNorm + RoPE (tf32-rounded; Q pre-scaled by 1/64)
// ---------------------------------------------------------------------------
__global__ void __launch_bounds__(256) rmsrope_kernel()
{
    const int warp = threadIdx.x >> 5;
    const int lane = threadIdx.x & 31;
    const size_t row = (size_t)blockIdx.x * 8 + warp;
    const int isQ = (blockIdx.y == 0);
    float* ptr = (isQ ? g_q : g_k) + row * HD;

    float2 x = *(float2*)(ptr + lane * 2);
    float ss = x.x * x.x + x.y * x.y;
#pragma unroll
    for (int off = 16; off; off >>= 1)
        ss += __shfl_xor_sync(0xffffffffu, ss, off);
    float rn = rsqrtf(ss * (1.0f / 64.0f) + 1e-5f);

    int pos = (int)(row & (NSEQ - 1));
    float ifr = exp2f((float)lane * (-2.0f / 64.0f) * 13.287712379549449f);
    float ang = (float)pos * ifr;
    float s, c;
    sincosf(ang, &s, &c);

    float x0 = x.x * rn, x1 = x.y * rn;
    float post = isQ ? 0.015625f : 1.0f;
    float2 y;
    y.x = tf32r((x0 * c - x1 * s) * post);
    y.y = tf32r((x1 * c + x0 * s) * post);
    *(float2*)(ptr + lane * 2) = y;
}

// ---------------------------------------------------------------------------
// Flash attention: 128 threads (4 warps), 32 q-rows/warp, shared K/V frags,
// double-buffered cp.async K/V, 2 CTAs/SM. Epilogue -> g_o16 (single fp16).
// ---------------------------------------------------------------------------
#define KVBUF_F (2 * 64 * 68)
#define FLASH_SMEM_B ((2 * KVBUF_F + 128 * 68) * 4)   // 104448 bytes

__global__ void __launch_bounds__(128) flash_tf32(const float* __restrict__ mask)
{
    extern __shared__ float sm[];
    float* Ps = sm + 2 * KVBUF_F;   // 128*68

    const int tid = threadIdx.x, warp = tid >> 5, lane = tid & 31;
    const int bh = blockIdx.y, b = bh >> 4, h = bh & 15;
    const int q0 = blockIdx.x * 128;
    const int mnz = g_mask_nz;

    const float* Qg  = g_q  + ((size_t)bh * NSEQ + q0) * HD;
    const float* Kg  = g_k  + (size_t)bh * NSEQ * HD;
    const float* Vtg = g_vt + (size_t)bh * HD * NSEQ;
    const float* Mg  = mask + (size_t)b * NSEQ * NSEQ + (size_t)q0 * NSEQ;

    const uint32_t sbase = saddr(sm);

    auto load_kv = [&](int kt) {
        const int k0 = kt * 64;
        const uint32_t kb = sbase + (kt & 1) * (KVBUF_F * 4);
        const int rbase = tid >> 4;
        const int cc = (tid & 15) * 4;
#pragma unroll
        for (int i = 0; i < 8; i++) {
            int rr = rbase + i * 8;
            cpasync16(kb + (rr * 68 + cc) * 4,           Kg  + (size_t)(k0 + rr) * HD + cc);
            cpasync16(kb + (64 * 68 + rr * 68 + cc) * 4, Vtg + (size_t)rr * NSEQ + k0 + cc);
        }
        CP_COMMIT();
    };

    load_kv(0);

    {
        const int rbase = tid >> 4;
        const int c = (tid & 15) * 4;
#pragma unroll
        for (int i = 0; i < 16; i++) {
            int r = rbase + i * 8;
            *(float4*)(Ps + r * 68 + c) = *(const float4*)(Qg + (size_t)r * HD + c);
        }
    }
    __syncthreads();
    uint32_t qf[2][8][4];
#pragma unroll
    for (int mt = 0; mt < 2; mt++) {
        int row = warp * 32 + mt * 16 + (lane & 15);
        int cb  = (lane >> 4) << 2;
#pragma unroll
        for (int t = 0; t < 8; t++)
            ldsm_x4(qf[mt][t], saddr(Ps + row * 68 + t * 8 + cb));
    }
    __syncthreads();

    const int r  = lane >> 2;
    const int cq = lane & 3;
    float* Pw = Ps + warp * 32 * 68;

    float mrow[2][2] = {{-INFINITY, -INFINITY}, {-INFINITY, -INFINITY}};
    float lrow[2][2] = {{0.0f, 0.0f}, {0.0f, 0.0f}};
    float o[2][8][4];
#pragma unroll
    for (int mt = 0; mt < 2; mt++)
#pragma unroll
        for (int nt = 0; nt < 8; nt++)
#pragma unroll
            for (int j = 0; j < 4; j++) o[mt][nt][j] = 0.0f;

    for (int kt = 0; kt < NSEQ / 64; kt++) {
        const int k0 = kt * 64;
        if (kt + 1 < NSEQ / 64) { load_kv(kt + 1); CP_WAIT(1); }
        else                    { CP_WAIT(0); }
        __syncthreads();

        float* Ks  = sm + (kt & 1) * KVBUF_F;
        float* Vts = Ks + 64 * 68;

        float s[2][8][4];
#pragma unroll
        for (int mt = 0; mt < 2; mt++)
#pragma unroll
            for (int nt = 0; nt < 8; nt++)
#pragma unroll
                for (int j = 0; j < 4; j++) s[mt][nt][j] = 0.0f;

#pragma unroll
        for (int t = 0; t < 8; t++) {
            uint32_t bb[8][2];
#pragma unroll
            for (int p = 0; p < 4; p++) {
                int row = p * 16 + (lane & 7) + ((lane >> 4) << 3);
                int col = t * 8 + (((lane >> 3) & 1) << 2);
                uint32_t r4[4];
                ldsm_x4(r4, saddr(Ks + row * 68 + col));
                bb[2 * p][0] = r4[0]; bb[2 * p][1] = r4[1];
                bb[2 * p + 1][0] = r4[2]; bb[2 * p + 1][1] = r4[3];
            }
#pragma unroll
            for (int nt = 0; nt < 8; nt++) {
                mma8(s[0][nt], qf[0][t], bb[nt]);
                mma8(s[1][nt], qf[1][t], bb[nt]);
            }
        }

#pragma unroll
        for (int mt = 0; mt < 2; mt++) {
#pragma unroll
            for (int half = 0; half < 2; half++) {
                float sim[16];
                float vmax = -INFINITY;
                if (mnz) {
                    const float* mp = Mg + (size_t)(warp * 32 + mt * 16 + r + half * 8) * NSEQ + k0;
#pragma unroll
                    for (int nt = 0; nt < 8; nt++) {
                        float2 mk = *(const float2*)(mp + nt * 8 + 2 * cq);
                        sim[2 * nt]     = s[mt][nt][half * 2 + 0] + mk.x;
                        sim[2 * nt + 1] = s[mt][nt][half * 2 + 1] + mk.y;
                        vmax = fmaxf(vmax, fmaxf(sim[2 * nt], sim[2 * nt + 1]));
                    }
                } else {
#pragma unroll
                    for (int nt = 0; nt < 8; nt++) {
                        sim[2 * nt]     = s[mt][nt][half * 2 + 0];
                        sim[2 * nt + 1] = s[mt][nt][half * 2 + 1];
                        vmax = fmaxf(vmax, fmaxf(sim[2 * nt], sim[2 * nt + 1]));
                    }
                }
                vmax = fmaxf(vmax, __shfl_xor_sync(0xffffffffu, vmax, 1, 4));
                vmax = fmaxf(vmax, __shfl_xor_sync(0xffffffffu, vmax, 2, 4));
                float mnew = fmaxf(mrow[mt][half], vmax);
                float corr = __expf(mrow[mt][half] - mnew);
                float sum = 0.0f;
#pragma unroll
                for (int nt = 0; nt < 8; nt++) {
                    float p0 = __expf(sim[2 * nt]     - mnew);
                    float p1 = __expf(sim[2 * nt + 1] - mnew);
                    sum += p0 + p1;
                    *(float2*)(Pw + (size_t)(mt * 16 + r + half * 8) * 68 + nt * 8 + 2 * cq) =
                        make_float2(tf32r(p0), tf32r(p1));
                }
                sum += __shfl_xor_sync(0xffffffffu, sum, 1, 4);
                sum += __shfl_xor_sync(0xffffffffu, sum, 2, 4);
                lrow[mt][half] = lrow[mt][half] * corr + sum;
                mrow[mt][half] = mnew;
#pragma unroll
                for (int nt = 0; nt < 8; nt++) {
                    o[mt][nt][half * 2 + 0] *= corr;
                    o[mt][nt][half * 2 + 1] *= corr;
                }
            }
        }
        __syncwarp();

#pragma unroll
        for (int t = 0; t < 8; t++) {
            uint32_t af[2][4];
#pragma unroll
            for (int mt = 0; mt < 2; mt++) {
                int row = mt * 16 + (lane & 15);
                int col = t * 8 + ((lane >> 4) << 2);
                ldsm_x4(af[mt], saddr(Pw + row * 68 + col));
            }
            uint32_t bb[8][2];
#pragma unroll
            for (int p = 0; p < 4; p++) {
                int row = p * 16 + (lane & 7) + ((lane >> 4) << 3);
                int col = t * 8 + (((lane >> 3) & 1) << 2);
                uint32_t r4[4];
                ldsm_x4(r4, saddr(Vts + row * 68 + col));
                bb[2 * p][0] = r4[0]; bb[2 * p][1] = r4[1];
                bb[2 * p + 1][0] = r4[2]; bb[2 * p + 1][1] = r4[3];
            }
#pragma unroll
            for (int nt = 0; nt < 8; nt++) {
                mma8(o[0][nt], af[0], bb[nt]);
                mma8(o[1][nt], af[1], bb[nt]);
            }
        }
        __syncthreads();
    }

    // epilogue: single fp16 into gathered layout [b*2048+seq][h*64+d]
#pragma unroll
    for (int mt = 0; mt < 2; mt++) {
        float inv0 = 1.0f / lrow[mt][0], inv1 = 1.0f / lrow[mt][1];
#pragma unroll
        for (int nt = 0; nt < 8; nt++) {
            int col = h * HD + nt * 8 + 2 * cq;
#pragma unroll
            for (int half = 0; half < 2; half++) {
                int m = b * NSEQ + q0 + warp * 32 + mt * 16 + r + half * 8;
                float inv = half ? inv1 : inv0;
                __half2 ph;
                ph.x = __float2half(o[mt][nt][half * 2 + 0] * inv);
                ph.y = __float2half(o[mt][nt][half * 2 + 1] * inv);
                *(__half2*)(g_o16 + (size_t)m * DIMF + col) = ph;
            }
        }
    }
}

// ---------------------------------------------------------------------------
// Launch
// ---------------------------------------------------------------------------
extern "C" void kernel_launch(void* const* d_in, const int* in_sizes, int n_in,
                              void* d_out, int out_size)
{
    const float* x    = (const float*)d_in[0];
    const float* mask = (const float*)d_in[1];
    const float* Wq   = (const float*)d_in[2];
    const float* Wk   = (const float*)d_in[3];
    const float* Wv   = (const float*)d_in[4];
    const float* Wo   = (const float*)d_in[5];
    const float* bo   = (const float*)d_in[6];
    float* out = (float*)d_out;

    const int GEMM_SMEM = 2 * STAGE_B;   // 61440 B
    cudaFuncSetAttribute(gemm_fp16<0>, cudaFuncAttributeMaxDynamicSharedMemorySize, GEMM_SMEM);
    cudaFuncSetAttribute(gemm_fp16<1>, cudaFuncAttributeMaxDynamicSharedMemorySize, GEMM_SMEM);
    cudaFuncSetAttribute(flash_tf32,   cudaFuncAttributeMaxDynamicSharedMemorySize, FLASH_SMEM_B);

    mask_reset<<<1, 1>>>();
    mask_scan<<<256, 256>>>(mask, (BATCH * NSEQ * NSEQ) / 4);

    conv_split<<<MROWS + 4 * DIMF, 256>>>(x, Wq, Wk, Wv, Wo);

    gemm_fp16<0><<<dim3(8, 32, 3), 256, GEMM_SMEM>>>(nullptr, nullptr);

    rmsrope_kernel<<<dim3((BATCH * NH * NSEQ) / 8, 2), 256>>>();

    flash_tf32<<<dim3(NSEQ / 128, BATCH * NH), 128, FLASH_SMEM_B>>>(mask);

    gemm_fp16<1><<<dim3(8, 32), 256, GEMM_SMEM>>>(bo, out);
}

// round 12
// speedup vs baseline: 4.5135x; 1.2342x over previous
#include <cuda_runtime.h>
#include <cuda_fp16.h>
#include <math.h>
#include <stdint.h>

#define BATCH 2
#define NSEQ  2048
#define DIMF  1024
#define NH    16
#define HD    64
#define MROWS (BATCH * NSEQ)   // 4096

// fp32 scratch: projection results for Q/K (input to rmsnorm)
__device__ float g_q [BATCH * NH * NSEQ * HD];
__device__ float g_k [BATCH * NH * NSEQ * HD];

// fp16 attention operands
__device__ __half g_q16 [BATCH * NH * NSEQ * HD];   // rmsnorm+rope output, /64
__device__ __half g_k16 [BATCH * NH * NSEQ * HD];
__device__ __half g_vt16[BATCH * NH * HD * NSEQ];   // [b,h,d,seq]

// fp16 GEMM operands
__device__ __half g_x16[(size_t)MROWS * DIMF];
__device__ __half g_o16[(size_t)MROWS * DIMF];      // flash output, gathered
__device__ __half g_wh [(size_t)4 * DIMF * DIMF];
__device__ __half g_wl [(size_t)4 * DIMF * DIMF];

__device__ int g_mask_nz;

// ---------------------------------------------------------------------------
// helpers
// ---------------------------------------------------------------------------
__device__ __forceinline__ uint32_t saddr(const void* p) {
    return (uint32_t)__cvta_generic_to_shared(p);
}
__device__ __forceinline__ void ldsm_x4(uint32_t r[4], uint32_t a) {
    asm volatile("ldmatrix.sync.aligned.m8n8.x4.shared.b16 {%0,%1,%2,%3}, [%4];"
                 : "=r"(r[0]), "=r"(r[1]), "=r"(r[2]), "=r"(r[3]) : "r"(a));
}
__device__ __forceinline__ void mma16h(float c[4], const uint32_t a[4], const uint32_t b[2]) {
    asm volatile(
        "mma.sync.aligned.m16n8k16.row.col.f32.f16.f16.f32 "
        "{%0,%1,%2,%3}, {%4,%5,%6,%7}, {%8,%9}, {%0,%1,%2,%3};"
        : "+f"(c[0]), "+f"(c[1]), "+f"(c[2]), "+f"(c[3])
        : "r"(a[0]), "r"(a[1]), "r"(a[2]), "r"(a[3]), "r"(b[0]), "r"(b[1]));
}
__device__ __forceinline__ void cpasync16(uint32_t s, const void* g) {
    asm volatile("cp.async.cg.shared.global [%0], [%1], 16;" :: "r"(s), "l"(g) : "memory");
}
#define CP_COMMIT()  asm volatile("cp.async.commit_group;" ::: "memory")
#define CP_WAIT(n)   asm volatile("cp.async.wait_group %0;" :: "n"(n) : "memory")

// ---------------------------------------------------------------------------
// mask scan
// ---------------------------------------------------------------------------
__global__ void mask_reset() { g_mask_nz = 0; }

__global__ void __launch_bounds__(256) mask_scan(const float* __restrict__ mask, int n4)
{
    const float4* m4 = (const float4*)mask;
    uint32_t acc = 0;
    for (int i = blockIdx.x * 256 + threadIdx.x; i < n4; i += gridDim.x * 256) {
        float4 v = m4[i];
        acc |= __float_as_uint(v.x) | __float_as_uint(v.y)
             | __float_as_uint(v.z) | __float_as_uint(v.w);
    }
    if (acc) atomicOr(&g_mask_nz, 1);
}

// ---------------------------------------------------------------------------
// Convert: x -> fp16; weights -> fp16 hi/lo split
// ---------------------------------------------------------------------------
__global__ void __launch_bounds__(256) conv_split(
    const float* __restrict__ x,
    const float* __restrict__ Wq, const float* __restrict__ Wk,
    const float* __restrict__ Wv, const float* __restrict__ Wo)
{
    const int row = blockIdx.x;
    const int c = threadIdx.x * 4;
    if (row < MROWS) {
        float4 v = *(const float4*)(x + (size_t)row * DIMF + c);
        __half2 p0; p0.x = __float2half(v.x); p0.y = __float2half(v.y);
        __half2 p1; p1.x = __float2half(v.z); p1.y = __float2half(v.w);
        *(__half2*)(g_x16 + (size_t)row * DIMF + c)     = p0;
        *(__half2*)(g_x16 + (size_t)row * DIMF + c + 2) = p1;
    } else {
        int wi = (row - MROWS) >> 10, r = (row - MROWS) & 1023;
        const float* W = (wi == 0) ? Wq : (wi == 1) ? Wk : (wi == 2) ? Wv : Wo;
        float4 v = *(const float4*)(W + (size_t)r * DIMF + c);
        __half h0 = __float2half(v.x), h1 = __float2half(v.y);
        __half h2 = __float2half(v.z), h3 = __float2half(v.w);
        __half2 ph0; ph0.x = h0; ph0.y = h1;
        __half2 ph1; ph1.x = h2; ph1.y = h3;
        __half2 pl0; pl0.x = __float2half(v.x - __half2float(h0));
        pl0.y = __float2half(v.y - __half2float(h1));
        __half2 pl1; pl1.x = __float2half(v.z - __half2float(h2));
        pl1.y = __float2half(v.w - __half2float(h3));
        __half* dh = g_wh + ((size_t)wi * DIMF + r) * DIMF;
        __half* dl = g_wl + ((size_t)wi * DIMF + r) * DIMF;
        *(__half2*)(dh + c)     = ph0;
        *(__half2*)(dh + c + 2) = ph1;
        *(__half2*)(dl + c)     = pl0;
        *(__half2*)(dl + c + 2) = pl1;
    }
}

// ---------------------------------------------------------------------------
// fp16 2-pass GEMM (NT): C = A16[M,K] * (Wh+Wl)[N,K]^T
// ---------------------------------------------------------------------------
#define TILE_B 10240
#define STAGE_B (3 * TILE_B)

template <int OUT>
__global__ void __launch_bounds__(256, 2) gemm_fp16(
    const float* __restrict__ bias, float* __restrict__ Cout)
{
    extern __shared__ char smem[];
    const uint32_t sbase = saddr(smem);
    const int tid = threadIdx.x, warp = tid >> 5, lane = tid & 31;
    const int m0 = blockIdx.y * 128, n0 = blockIdx.x * 128;
    const int z = OUT ? 3 : blockIdx.z;

    const __half* A  = OUT ? g_o16 : g_x16;
    const __half* Bh = g_wh + (size_t)z * DIMF * DIMF;
    const __half* Bl = g_wl + (size_t)z * DIMF * DIMF;

    const int lrow = tid >> 1;
    const int lq   = (tid & 1) * 2;

    auto load_stage = [&](int s) {
        const uint32_t d0 = sbase + (s & 1) * STAGE_B + lrow * 80 + lq * 16;
        const int kc = s * 32 + lq * 8;
        const __half* pa = A  + (size_t)(m0 + lrow) * DIMF + kc;
        const __half* pb = Bh + (size_t)(n0 + lrow) * DIMF + kc;
        const __half* pq = Bl + (size_t)(n0 + lrow) * DIMF + kc;
        cpasync16(d0,              pa);   cpasync16(d0 + 16,              pa + 8);
        cpasync16(d0 + TILE_B,     pb);   cpasync16(d0 + TILE_B + 16,     pb + 8);
        cpasync16(d0 + 2 * TILE_B, pq);   cpasync16(d0 + 2 * TILE_B + 16, pq + 8);
        CP_COMMIT();
    };

    float acc[2][8][4];
#pragma unroll
    for (int i = 0; i < 2; i++)
#pragma unroll
        for (int j = 0; j < 8; j++)
#pragma unroll
            for (int l = 0; l < 4; l++) acc[i][j][l] = 0.0f;

    const int mw = (warp >> 1) * 32;
    const int nw = (warp & 1) * 64;

    load_stage(0);
    load_stage(1);

    for (int s = 0; s < 32; s++) {
        if (s == 31) CP_WAIT(0); else CP_WAIT(1);
        __syncthreads();

        const uint32_t base = sbase + (s & 1) * STAGE_B;
#pragma unroll
        for (int t = 0; t < 2; t++) {
            const int kk = t * 16;
            uint32_t a16[2][4];
#pragma unroll
            for (int mt = 0; mt < 2; mt++) {
                uint32_t addr = base + (mw + mt * 16 + (lane & 15)) * 80
                              + kk * 2 + ((lane >> 4) << 4);
                ldsm_x4(a16[mt], addr);
            }
#pragma unroll
            for (int p = 0; p < 4; p++) {
                uint32_t baddr = base + TILE_B
                               + (nw + p * 16 + (lane & 7) + ((lane >> 4) << 3)) * 80
                               + kk * 2 + (((lane >> 3) & 1) << 4);
                uint32_t bh4[4], bl4[4];
                ldsm_x4(bh4, baddr);
                ldsm_x4(bl4, baddr + TILE_B);
#pragma unroll
                for (int mt = 0; mt < 2; mt++) {
                    mma16h(acc[mt][2 * p],     a16[mt], bh4);
                    mma16h(acc[mt][2 * p],     a16[mt], bl4);
                    mma16h(acc[mt][2 * p + 1], a16[mt], bh4 + 2);
                    mma16h(acc[mt][2 * p + 1], a16[mt], bl4 + 2);
                }
            }
        }
        __syncthreads();
        if (s + 2 < 32) load_stage(s + 2);
    }

#pragma unroll
    for (int mt = 0; mt < 2; mt++) {
#pragma unroll
        for (int nt = 0; nt < 8; nt++) {
#pragma unroll
            for (int half = 0; half < 2; half++) {
                int m = m0 + mw + mt * 16 + (lane >> 2) + half * 8;
                int c = n0 + nw + nt * 8 + ((lane & 3) << 1);
                float2 v = make_float2(acc[mt][nt][half * 2 + 0],
                                       acc[mt][nt][half * 2 + 1]);
                if (OUT) {
                    const float2 bb2 = *(const float2*)(bias + c);
                    v.x += bb2.x; v.y += bb2.y;
                    *(float2*)(Cout + (size_t)m * DIMF + c) = v;
                } else {
                    int bb = m >> 11, n = m & (NSEQ - 1);
                    int h = c >> 6, d = c & (HD - 1);
                    if (z == 2) {
                        __half* basep = g_vt16 + (((size_t)(bb * NH + h) * HD + d) * NSEQ) + n;
                        basep[0]    = __float2half(v.x);
                        basep[NSEQ] = __float2half(v.y);
                    } else {
                        float* dst = (z == 0 ? g_q : g_k)
                                   + (((size_t)(bb * NH + h) * NSEQ + n) << 6) + d;
                        *(float2*)dst = v;
                    }
                }
            }
        }
    }
}

// ---------------------------------------------------------------------------
// RMSNorm + RoPE: reads fp32 g_q/g_k, writes fp16 g_q16/g_k16.
// Q pre-scaled by 1/64 (exact).
// ---------------------------------------------------------------------------
__global__ void __launch_bounds__(256) rmsrope_kernel()
{
    const int warp = threadIdx.x >> 5;
    const int lane = threadIdx.x & 31;
    const size_t row = (size_t)blockIdx.x * 8 + warp;
    const int isQ = (blockIdx.y == 0);
    const float* src = (isQ ? g_q : g_k) + row * HD;
    __half* dst = (isQ ? g_q16 : g_k16) + row * HD;

    float2 x = *(const float2*)(src + lane * 2);
    float ss = x.x * x.x + x.y * x.y;
#pragma unroll
    for (int off = 16; off; off >>= 1)
        ss += __shfl_xor_sync(0xffffffffu, ss, off);
    float rn = rsqrtf(ss * (1.0f / 64.0f) + 1e-5f);

    int pos = (int)(row & (NSEQ - 1));
    float ifr = exp2f((float)lane * (-2.0f / 64.0f) * 13.287712379549449f);
    float ang = (float)pos * ifr;
    float s, c;
    sincosf(ang, &s, &c);

    float x0 = x.x * rn, x1 = x.y * rn;
    float post = isQ ? 0.015625f : 1.0f;
    __half2 y;
    y.x = __float2half((x0 * c - x1 * s) * post);
    y.y = __float2half((x1 * c + x0 * s) * post);
    *(__half2*)(dst + lane * 2) = y;
}

// ---------------------------------------------------------------------------
// Flash attention, fp16 m16n8k16 everywhere. 128 threads (4 warps),
// 32 q-rows/warp, shared K/V fragments, double-buffered cp.async K/V.
// Smem (bytes): KV buf[2] @ 18432 each (K 64x144 | Vt 64x144), Ps 128x144.
// ---------------------------------------------------------------------------
#define KROW_B   144                      // 64 fp16 (128B) + 16B pad
#define KVBUF_B  (2 * 64 * KROW_B)        // 18432
#define PS_OFF   (2 * KVBUF_B)            // 36864
#define FLASH_SMEM_B (PS_OFF + 128 * KROW_B)   // 55296

__global__ void __launch_bounds__(128) flash_fp16(const float* __restrict__ mask)
{
    extern __shared__ char smf[];
    const uint32_t sbase = saddr(smf);

    const int tid = threadIdx.x, warp = tid >> 5, lane = tid & 31;
    const int bh = blockIdx.y, b = bh >> 4, h = bh & 15;
    const int q0 = blockIdx.x * 128;
    const int mnz = g_mask_nz;

    const __half* Qg  = g_q16  + ((size_t)bh * NSEQ + q0) * HD;
    const __half* Kg  = g_k16  + (size_t)bh * NSEQ * HD;
    const __half* Vtg = g_vt16 + (size_t)bh * HD * NSEQ;
    const float*  Mg  = mask + (size_t)b * NSEQ * NSEQ + (size_t)q0 * NSEQ;

    // async K/Vt tile loader (64 rows x 128B each)
    auto load_kv = [&](int kt) {
        const int k0 = kt * 64;
        const uint32_t kb = sbase + (kt & 1) * KVBUF_B;
        const int row = tid >> 3;          // 0..15
        const int ch  = (tid & 7) * 16;    // byte chunk
#pragma unroll
        for (int i = 0; i < 4; i++) {
            int rr = row + i * 16;
            cpasync16(kb + rr * KROW_B + ch,
                      (const char*)(Kg + (size_t)(k0 + rr) * HD) + ch);
            cpasync16(kb + 64 * KROW_B + rr * KROW_B + ch,
                      (const char*)(Vtg + (size_t)rr * NSEQ + k0) + ch);
        }
        CP_COMMIT();
    };

    load_kv(0);

    // stage Q (128 rows x 128B) into Ps, pick up fragments
    {
        const int row = tid >> 3;
        const int ch  = (tid & 7) * 16;
#pragma unroll
        for (int i = 0; i < 8; i++) {
            int rr = row + i * 16;
            *(uint4*)(smf + PS_OFF + rr * KROW_B + ch) =
                *(const uint4*)((const char*)(Qg + (size_t)rr * HD) + ch);
        }
    }
    __syncthreads();
    uint32_t qf[2][4][4];
#pragma unroll
    for (int mt = 0; mt < 2; mt++) {
        int row = warp * 32 + mt * 16 + (lane & 15);
#pragma unroll
        for (int t = 0; t < 4; t++)
            ldsm_x4(qf[mt][t], sbase + PS_OFF + row * KROW_B + t * 32 + ((lane >> 4) << 4));
    }
    __syncthreads();   // Ps free for P staging

    const int r  = lane >> 2;
    const int cq = lane & 3;
    const uint32_t pw = sbase + PS_OFF + warp * 32 * KROW_B;

    float mrow[2][2] = {{-INFINITY, -INFINITY}, {-INFINITY, -INFINITY}};
    float lrow[2][2] = {{0.0f, 0.0f}, {0.0f, 0.0f}};
    float o[2][8][4];
#pragma unroll
    for (int mt = 0; mt < 2; mt++)
#pragma unroll
        for (int nt = 0; nt < 8; nt++)
#pragma unroll
            for (int j = 0; j < 4; j++) o[mt][nt][j] = 0.0f;

    for (int kt = 0; kt < NSEQ / 64; kt++) {
        const int k0 = kt * 64;
        if (kt + 1 < NSEQ / 64) { load_kv(kt + 1); CP_WAIT(1); }
        else                    { CP_WAIT(0); }
        __syncthreads();

        const uint32_t kbuf = sbase + (kt & 1) * KVBUF_B;
        const uint32_t vbuf = kbuf + 64 * KROW_B;

        // S = Q K^T  (4 k16 steps over HD=64)
        float s[2][8][4];
#pragma unroll
        for (int mt = 0; mt < 2; mt++)
#pragma unroll
            for (int nt = 0; nt < 8; nt++)
#pragma unroll
                for (int j = 0; j < 4; j++) s[mt][nt][j] = 0.0f;

#pragma unroll
        for (int t = 0; t < 4; t++) {
            uint32_t bb[8][2];
#pragma unroll
            for (int p = 0; p < 4; p++) {
                uint32_t addr = kbuf + (p * 16 + (lane & 7) + ((lane >> 4) << 3)) * KROW_B
                              + t * 32 + (((lane >> 3) & 1) << 4);
                uint32_t r4[4];
                ldsm_x4(r4, addr);
                bb[2 * p][0] = r4[0]; bb[2 * p][1] = r4[1];
                bb[2 * p + 1][0] = r4[2]; bb[2 * p + 1][1] = r4[3];
            }
#pragma unroll
            for (int nt = 0; nt < 8; nt++) {
                mma16h(s[0][nt], qf[0][t], bb[nt]);
                mma16h(s[1][nt], qf[1][t], bb[nt]);
            }
        }

        // online softmax
#pragma unroll
        for (int mt = 0; mt < 2; mt++) {
#pragma unroll
            for (int half = 0; half < 2; half++) {
                float sim[16];
                float vmax = -INFINITY;
                if (mnz) {
                    const float* mp = Mg + (size_t)(warp * 32 + mt * 16 + r + half * 8) * NSEQ + k0;
#pragma unroll
                    for (int nt = 0; nt < 8; nt++) {
                        float2 mk = *(const float2*)(mp + nt * 8 + 2 * cq);
                        sim[2 * nt]     = s[mt][nt][half * 2 + 0] + mk.x;
                        sim[2 * nt + 1] = s[mt][nt][half * 2 + 1] + mk.y;
                        vmax = fmaxf(vmax, fmaxf(sim[2 * nt], sim[2 * nt + 1]));
                    }
                } else {
#pragma unroll
                    for (int nt = 0; nt < 8; nt++) {
                        sim[2 * nt]     = s[mt][nt][half * 2 + 0];
                        sim[2 * nt + 1] = s[mt][nt][half * 2 + 1];
                        vmax = fmaxf(vmax, fmaxf(sim[2 * nt], sim[2 * nt + 1]));
                    }
                }
                vmax = fmaxf(vmax, __shfl_xor_sync(0xffffffffu, vmax, 1, 4));
                vmax = fmaxf(vmax, __shfl_xor_sync(0xffffffffu, vmax, 2, 4));
                float mnew = fmaxf(mrow[mt][half], vmax);
                float corr = __expf(mrow[mt][half] - mnew);
                float sum = 0.0f;
                const uint32_t prow = pw + (mt * 16 + r + half * 8) * KROW_B;
#pragma unroll
                for (int nt = 0; nt < 8; nt++) {
                    float p0 = __expf(sim[2 * nt]     - mnew);
                    float p1 = __expf(sim[2 * nt + 1] - mnew);
                    sum += p0 + p1;
                    __half2 ph;
                    ph.x = __float2half(p0);
                    ph.y = __float2half(p1);
                    *(__half2*)(smf + (prow - sbase) + (nt * 8 + 2 * cq) * 2) = ph;
                }
                sum += __shfl_xor_sync(0xffffffffu, sum, 1, 4);
                sum += __shfl_xor_sync(0xffffffffu, sum, 2, 4);
                lrow[mt][half] = lrow[mt][half] * corr + sum;
                mrow[mt][half] = mnew;
#pragma unroll
                for (int nt = 0; nt < 8; nt++) {
                    o[mt][nt][half * 2 + 0] *= corr;
                    o[mt][nt][half * 2 + 1] *= corr;
                }
            }
        }
        __syncwarp();

        // O += P V  (4 k16 steps over 64 keys)
#pragma unroll
        for (int t = 0; t < 4; t++) {
            uint32_t af[2][4];
#pragma unroll
            for (int mt = 0; mt < 2; mt++) {
                uint32_t addr = pw + (mt * 16 + (lane & 15)) * KROW_B
                              + t * 32 + ((lane >> 4) << 4);
                ldsm_x4(af[mt], addr);
            }
            uint32_t bb[8][2];
#pragma unroll
            for (int p = 0; p < 4; p++) {
                uint32_t addr = vbuf + (p * 16 + (lane & 7) + ((lane >> 4) << 3)) * KROW_B
                              + t * 32 + (((lane >> 3) & 1) << 4);
                uint32_t r4[4];
                ldsm_x4(r4, addr);
                bb[2 * p][0] = r4[0]; bb[2 * p][1] = r4[1];
                bb[2 * p + 1][0] = r4[2]; bb[2 * p + 1][1] = r4[3];
            }
#pragma unroll
            for (int nt = 0; nt < 8; nt++) {
                mma16h(o[0][nt], af[0], bb[nt]);
                mma16h(o[1][nt], af[1], bb[nt]);
            }
        }
        __syncthreads();
    }

    // epilogue: single fp16 into gathered layout [b*2048+seq][h*64+d]
#pragma unroll
    for (int mt = 0; mt < 2; mt++) {
        float inv0 = 1.0f / lrow[mt][0], inv1 = 1.0f / lrow[mt][1];
#pragma unroll
        for (int nt = 0; nt < 8; nt++) {
            int col = h * HD + nt * 8 + 2 * cq;
#pragma unroll
            for (int half = 0; half < 2; half++) {
                int m = b * NSEQ + q0 + warp * 32 + mt * 16 + r + half * 8;
                float inv = half ? inv1 : inv0;
                __half2 ph;
                ph.x = __float2half(o[mt][nt][half * 2 + 0] * inv);
                ph.y = __float2half(o[mt][nt][half * 2 + 1] * inv);
                *(__half2*)(g_o16 + (size_t)m * DIMF + col) = ph;
            }
        }
    }
}

// ---------------------------------------------------------------------------
// Launch
// ---------------------------------------------------------------------------
extern "C" void kernel_launch(void* const* d_in, const int* in_sizes, int n_in,
                              void* d_out, int out_size)
{
    const float* x    = (const float*)d_in[0];
    const float* mask = (const float*)d_in[1];
    const float* Wq   = (const float*)d_in[2];
    const float* Wk   = (const float*)d_in[3];
    const float* Wv   = (const float*)d_in[4];
    const float* Wo   = (const float*)d_in[5];
    const float* bo   = (const float*)d_in[6];
    float* out = (float*)d_out;

    const int GEMM_SMEM = 2 * STAGE_B;   // 61440 B
    cudaFuncSetAttribute(gemm_fp16<0>, cudaFuncAttributeMaxDynamicSharedMemorySize, GEMM_SMEM);
    cudaFuncSetAttribute(gemm_fp16<1>, cudaFuncAttributeMaxDynamicSharedMemorySize, GEMM_SMEM);
    cudaFuncSetAttribute(flash_fp16,   cudaFuncAttributeMaxDynamicSharedMemorySize, FLASH_SMEM_B);

    mask_reset<<<1, 1>>>();
    mask_scan<<<256, 256>>>(mask, (BATCH * NSEQ * NSEQ) / 4);

    conv_split<<<MROWS + 4 * DIMF, 256>>>(x, Wq, Wk, Wv, Wo);

    gemm_fp16<0><<<dim3(8, 32, 3), 256, GEMM_SMEM>>>(nullptr, nullptr);

    rmsrope_kernel<<<dim3((BATCH * NH * NSEQ) / 8, 2), 256>>>();

    flash_fp16<<<dim3(NSEQ / 128, BATCH * NH), 128, FLASH_SMEM_B>>>(mask);

    gemm_fp16<1><<<dim3(8, 32), 256, GEMM_SMEM>>>(bo, out);
}

// round 13
// speedup vs baseline: 5.7105x; 1.2652x over previous
#include <cuda_runtime.h>
#include <cuda_fp16.h>
#include <math.h>
#include <stdint.h>

#define BATCH 2
#define NSEQ  2048
#define DIMF  1024
#define NH    16
#define HD    64
#define MROWS (BATCH * NSEQ)   // 4096

// fp32 scratch: projection results for Q/K (input to rmsnorm)
__device__ float g_q [BATCH * NH * NSEQ * HD];
__device__ float g_k [BATCH * NH * NSEQ * HD];

// fp16 attention operands
__device__ __half g_q16 [BATCH * NH * NSEQ * HD];   // rmsnorm+rope output, /64
__device__ __half g_k16 [BATCH * NH * NSEQ * HD];
__device__ __half g_vt16[BATCH * NH * HD * NSEQ];   // [b,h,d,seq]

// fp16 GEMM operands
__device__ __half g_x16[(size_t)MROWS * DIMF];
__device__ __half g_o16[(size_t)MROWS * DIMF];      // flash output, gathered
__device__ __half g_wh [(size_t)4 * DIMF * DIMF];
__device__ __half g_wl [(size_t)DIMF * DIMF];       // lo split only for Wo

__device__ int g_mask_nz;

// ---------------------------------------------------------------------------
// helpers
// ---------------------------------------------------------------------------
__device__ __forceinline__ uint32_t saddr(const void* p) {
    return (uint32_t)__cvta_generic_to_shared(p);
}
__device__ __forceinline__ void ldsm_x4(uint32_t r[4], uint32_t a) {
    asm volatile("ldmatrix.sync.aligned.m8n8.x4.shared.b16 {%0,%1,%2,%3}, [%4];"
                 : "=r"(r[0]), "=r"(r[1]), "=r"(r[2]), "=r"(r[3]) : "r"(a));
}
__device__ __forceinline__ void mma16h(float c[4], const uint32_t a[4], const uint32_t b[2]) {
    asm volatile(
        "mma.sync.aligned.m16n8k16.row.col.f32.f16.f16.f32 "
        "{%0,%1,%2,%3}, {%4,%5,%6,%7}, {%8,%9}, {%0,%1,%2,%3};"
        : "+f"(c[0]), "+f"(c[1]), "+f"(c[2]), "+f"(c[3])
        : "r"(a[0]), "r"(a[1]), "r"(a[2]), "r"(a[3]), "r"(b[0]), "r"(b[1]));
}
__device__ __forceinline__ void cpasync16(uint32_t s, const void* g) {
    asm volatile("cp.async.cg.shared.global [%0], [%1], 16;" :: "r"(s), "l"(g) : "memory");
}
#define CP_COMMIT()  asm volatile("cp.async.commit_group;" ::: "memory")
#define CP_WAIT(n)   asm volatile("cp.async.wait_group %0;" :: "n"(n) : "memory")

// ---------------------------------------------------------------------------
// mask scan
// ---------------------------------------------------------------------------
__global__ void mask_reset() { g_mask_nz = 0; }

__global__ void __launch_bounds__(256) mask_scan(const float* __restrict__ mask, int n4)
{
    const float4* m4 = (const float4*)mask;
    uint32_t acc = 0;
    for (int i = blockIdx.x * 256 + threadIdx.x; i < n4; i += gridDim.x * 256) {
        float4 v = m4[i];
        acc |= __float_as_uint(v.x) | __float_as_uint(v.y)
             | __float_as_uint(v.z) | __float_as_uint(v.w);
    }
    if (acc) atomicOr(&g_mask_nz, 1);
}

// ---------------------------------------------------------------------------
// Convert: x -> fp16; Wq/Wk/Wv -> fp16; Wo -> fp16 hi + lo
// ---------------------------------------------------------------------------
__global__ void __launch_bounds__(256) conv_split(
    const float* __restrict__ x,
    const float* __restrict__ Wq, const float* __restrict__ Wk,
    const float* __restrict__ Wv, const float* __restrict__ Wo)
{
    const int row = blockIdx.x;
    const int c = threadIdx.x * 4;
    if (row < MROWS) {
        float4 v = *(const float4*)(x + (size_t)row * DIMF + c);
        __half2 p0; p0.x = __float2half(v.x); p0.y = __float2half(v.y);
        __half2 p1; p1.x = __float2half(v.z); p1.y = __float2half(v.w);
        *(__half2*)(g_x16 + (size_t)row * DIMF + c)     = p0;
        *(__half2*)(g_x16 + (size_t)row * DIMF + c + 2) = p1;
    } else {
        int wi = (row - MROWS) >> 10, r = (row - MROWS) & 1023;
        const float* W = (wi == 0) ? Wq : (wi == 1) ? Wk : (wi == 2) ? Wv : Wo;
        float4 v = *(const float4*)(W + (size_t)r * DIMF + c);
        __half h0 = __float2half(v.x), h1 = __float2half(v.y);
        __half h2 = __float2half(v.z), h3 = __float2half(v.w);
        __half2 ph0; ph0.x = h0; ph0.y = h1;
        __half2 ph1; ph1.x = h2; ph1.y = h3;
        __half* dh = g_wh + ((size_t)wi * DIMF + r) * DIMF;
        *(__half2*)(dh + c)     = ph0;
        *(__half2*)(dh + c + 2) = ph1;
        if (wi == 3) {
            __half2 pl0; pl0.x = __float2half(v.x - __half2float(h0));
            pl0.y = __float2half(v.y - __half2float(h1));
            __half2 pl1; pl1.x = __float2half(v.z - __half2float(h2));
            pl1.y = __float2half(v.w - __half2float(h3));
            __half* dl = g_wl + (size_t)r * DIMF;
            *(__half2*)(dl + c)     = pl0;
            *(__half2*)(dl + c + 2) = pl1;
        }
    }
}

// ---------------------------------------------------------------------------
// fp16 GEMM (NT), 3-stage cp.async ring, ONE __syncthreads per stage.
// OUT=0: single-pass  C = A16 * Wh[z]^T          (stage = 2 tiles)
// OUT=1: two-pass     C = A16 * (Wh[3]+Wl)^T + b (stage = 3 tiles)
// CTA 128x128, BK=32, 256 threads (8 warps 4x2, warp tile 32x64).
// ---------------------------------------------------------------------------
#define TILE_B   10240                 // 128 rows * 80 bytes
#define NKSTAGES 32

template <int OUT>
__global__ void __launch_bounds__(256, 2) gemm_fp16(
    const float* __restrict__ bias, float* __restrict__ Cout)
{
    constexpr int NT = OUT ? 3 : 2;            // tiles per stage
    constexpr int STAGE = NT * TILE_B;
    extern __shared__ char smem[];
    const uint32_t sbase = saddr(smem);
    const int tid = threadIdx.x, warp = tid >> 5, lane = tid & 31;
    const int m0 = blockIdx.y * 128, n0 = blockIdx.x * 128;
    const int z = OUT ? 3 : blockIdx.z;

    const __half* A  = OUT ? g_o16 : g_x16;
    const __half* Bh = g_wh + (size_t)z * DIMF * DIMF;

    const int lrow = tid >> 1;
    const int lq   = (tid & 1) * 2;

    auto load_stage = [&](int s) {
        const uint32_t d0 = sbase + (s % 3) * STAGE + lrow * 80 + lq * 16;
        const int kc = s * 32 + lq * 8;
        const __half* pa = A  + (size_t)(m0 + lrow) * DIMF + kc;
        const __half* pb = Bh + (size_t)(n0 + lrow) * DIMF + kc;
        cpasync16(d0,          pa);   cpasync16(d0 + 16,          pa + 8);
        cpasync16(d0 + TILE_B, pb);   cpasync16(d0 + TILE_B + 16, pb + 8);
        if (OUT) {
            const __half* pq = g_wl + (size_t)(n0 + lrow) * DIMF + kc;
            cpasync16(d0 + 2 * TILE_B, pq);
            cpasync16(d0 + 2 * TILE_B + 16, pq + 8);
        }
        CP_COMMIT();
    };

    float acc[2][8][4];
#pragma unroll
    for (int i = 0; i < 2; i++)
#pragma unroll
        for (int j = 0; j < 8; j++)
#pragma unroll
            for (int l = 0; l < 4; l++) acc[i][j][l] = 0.0f;

    const int mw = (warp >> 1) * 32;
    const int nw = (warp & 1) * 64;

    load_stage(0);
    load_stage(1);

    for (int s = 0; s < NKSTAGES; s++) {
        if (s == NKSTAGES - 1) CP_WAIT(0); else CP_WAIT(1);
        __syncthreads();     // single barrier: stage s resident, buf (s+2)%3 free

        const uint32_t base = sbase + (s % 3) * STAGE;
#pragma unroll
        for (int t = 0; t < 2; t++) {
            const int kk = t * 16;
            uint32_t a16[2][4];
#pragma unroll
            for (int mt = 0; mt < 2; mt++) {
                uint32_t addr = base + (mw + mt * 16 + (lane & 15)) * 80
                              + kk * 2 + ((lane >> 4) << 4);
                ldsm_x4(a16[mt], addr);
            }
#pragma unroll
            for (int p = 0; p < 4; p++) {
                uint32_t baddr = base + TILE_B
                               + (nw + p * 16 + (lane & 7) + ((lane >> 4) << 3)) * 80
                               + kk * 2 + (((lane >> 3) & 1) << 4);
                uint32_t bh4[4];
                ldsm_x4(bh4, baddr);
#pragma unroll
                for (int mt = 0; mt < 2; mt++) {
                    mma16h(acc[mt][2 * p],     a16[mt], bh4);
                    mma16h(acc[mt][2 * p + 1], a16[mt], bh4 + 2);
                }
                if (OUT) {
                    uint32_t bl4[4];
                    ldsm_x4(bl4, baddr + TILE_B);
#pragma unroll
                    for (int mt = 0; mt < 2; mt++) {
                        mma16h(acc[mt][2 * p],     a16[mt], bl4);
                        mma16h(acc[mt][2 * p + 1], a16[mt], bl4 + 2);
                    }
                }
            }
        }
        if (s + 2 < NKSTAGES) load_stage(s + 2);
    }

    // epilogue
#pragma unroll
    for (int mt = 0; mt < 2; mt++) {
#pragma unroll
        for (int nt = 0; nt < 8; nt++) {
#pragma unroll
            for (int half = 0; half < 2; half++) {
                int m = m0 + mw + mt * 16 + (lane >> 2) + half * 8;
                int c = n0 + nw + nt * 8 + ((lane & 3) << 1);
                float2 v = make_float2(acc[mt][nt][half * 2 + 0],
                                       acc[mt][nt][half * 2 + 1]);
                if (OUT) {
                    const float2 bb2 = *(const float2*)(bias + c);
                    v.x += bb2.x; v.y += bb2.y;
                    *(float2*)(Cout + (size_t)m * DIMF + c) = v;
                } else {
                    int bb = m >> 11, n = m & (NSEQ - 1);
                    int h = c >> 6, d = c & (HD - 1);
                    if (z == 2) {
                        __half* basep = g_vt16 + (((size_t)(bb * NH + h) * HD + d) * NSEQ) + n;
                        basep[0]    = __float2half(v.x);
                        basep[NSEQ] = __float2half(v.y);
                    } else {
                        float* dst = (z == 0 ? g_q : g_k)
                                   + (((size_t)(bb * NH + h) * NSEQ + n) << 6) + d;
                        *(float2*)dst = v;
                    }
                }
            }
        }
    }
}

// ---------------------------------------------------------------------------
// RMSNorm + RoPE: reads fp32 g_q/g_k, writes fp16 g_q16/g_k16 (Q /64).
// ---------------------------------------------------------------------------
__global__ void __launch_bounds__(256) rmsrope_kernel()
{
    const int warp = threadIdx.x >> 5;
    const int lane = threadIdx.x & 31;
    const size_t row = (size_t)blockIdx.x * 8 + warp;
    const int isQ = (blockIdx.y == 0);
    const float* src = (isQ ? g_q : g_k) + row * HD;
    __half* dst = (isQ ? g_q16 : g_k16) + row * HD;

    float2 x = *(const float2*)(src + lane * 2);
    float ss = x.x * x.x + x.y * x.y;
#pragma unroll
    for (int off = 16; off; off >>= 1)
        ss += __shfl_xor_sync(0xffffffffu, ss, off);
    float rn = rsqrtf(ss * (1.0f / 64.0f) + 1e-5f);

    int pos = (int)(row & (NSEQ - 1));
    float ifr = exp2f((float)lane * (-2.0f / 64.0f) * 13.287712379549449f);
    float ang = (float)pos * ifr;
    float s, c;
    sincosf(ang, &s, &c);

    float x0 = x.x * rn, x1 = x.y * rn;
    float post = isQ ? 0.015625f : 1.0f;
    __half2 y;
    y.x = __float2half((x0 * c - x1 * s) * post);
    y.y = __float2half((x1 * c + x0 * s) * post);
    *(__half2*)(dst + lane * 2) = y;
}

// ---------------------------------------------------------------------------
// Flash attention (unchanged from R12): fp16 m16n8k16, 128 threads (4 warps),
// 32 q-rows/warp, shared K/V fragments, double-buffered cp.async K/V.
// ---------------------------------------------------------------------------
#define KROW_B   144
#define KVBUF_B  (2 * 64 * KROW_B)
#define PS_OFF   (2 * KVBUF_B)
#define FLASH_SMEM_B (PS_OFF + 128 * KROW_B)   // 55296

__global__ void __launch_bounds__(128) flash_fp16(const float* __restrict__ mask)
{
    extern __shared__ char smf[];
    const uint32_t sbase = saddr(smf);

    const int tid = threadIdx.x, warp = tid >> 5, lane = tid & 31;
    const int bh = blockIdx.y, b = bh >> 4, h = bh & 15;
    const int q0 = blockIdx.x * 128;
    const int mnz = g_mask_nz;

    const __half* Qg  = g_q16  + ((size_t)bh * NSEQ + q0) * HD;
    const __half* Kg  = g_k16  + (size_t)bh * NSEQ * HD;
    const __half* Vtg = g_vt16 + (size_t)bh * HD * NSEQ;
    const float*  Mg  = mask + (size_t)b * NSEQ * NSEQ + (size_t)q0 * NSEQ;

    auto load_kv = [&](int kt) {
        const int k0 = kt * 64;
        const uint32_t kb = sbase + (kt & 1) * KVBUF_B;
        const int row = tid >> 3;
        const int ch  = (tid & 7) * 16;
#pragma unroll
        for (int i = 0; i < 4; i++) {
            int rr = row + i * 16;
            cpasync16(kb + rr * KROW_B + ch,
                      (const char*)(Kg + (size_t)(k0 + rr) * HD) + ch);
            cpasync16(kb + 64 * KROW_B + rr * KROW_B + ch,
                      (const char*)(Vtg + (size_t)rr * NSEQ + k0) + ch);
        }
        CP_COMMIT();
    };

    load_kv(0);

    {
        const int row = tid >> 3;
        const int ch  = (tid & 7) * 16;
#pragma unroll
        for (int i = 0; i < 8; i++) {
            int rr = row + i * 16;
            *(uint4*)(smf + PS_OFF + rr * KROW_B + ch) =
                *(const uint4*)((const char*)(Qg + (size_t)rr * HD) + ch);
        }
    }
    __syncthreads();
    uint32_t qf[2][4][4];
#pragma unroll
    for (int mt = 0; mt < 2; mt++) {
        int row = warp * 32 + mt * 16 + (lane & 15);
#pragma unroll
        for (int t = 0; t < 4; t++)
            ldsm_x4(qf[mt][t], sbase + PS_OFF + row * KROW_B + t * 32 + ((lane >> 4) << 4));
    }
    __syncthreads();

    const int r  = lane >> 2;
    const int cq = lane & 3;
    const uint32_t pw = sbase + PS_OFF + warp * 32 * KROW_B;

    float mrow[2][2] = {{-INFINITY, -INFINITY}, {-INFINITY, -INFINITY}};
    float lrow[2][2] = {{0.0f, 0.0f}, {0.0f, 0.0f}};
    float o[2][8][4];
#pragma unroll
    for (int mt = 0; mt < 2; mt++)
#pragma unroll
        for (int nt = 0; nt < 8; nt++)
#pragma unroll
            for (int j = 0; j < 4; j++) o[mt][nt][j] = 0.0f;

    for (int kt = 0; kt < NSEQ / 64; kt++) {
        const int k0 = kt * 64;
        if (kt + 1 < NSEQ / 64) { load_kv(kt + 1); CP_WAIT(1); }
        else                    { CP_WAIT(0); }
        __syncthreads();

        const uint32_t kbuf = sbase + (kt & 1) * KVBUF_B;
        const uint32_t vbuf = kbuf + 64 * KROW_B;

        float s[2][8][4];
#pragma unroll
        for (int mt = 0; mt < 2; mt++)
#pragma unroll
            for (int nt = 0; nt < 8; nt++)
#pragma unroll
                for (int j = 0; j < 4; j++) s[mt][nt][j] = 0.0f;

#pragma unroll
        for (int t = 0; t < 4; t++) {
            uint32_t bb[8][2];
#pragma unroll
            for (int p = 0; p < 4; p++) {
                uint32_t addr = kbuf + (p * 16 + (lane & 7) + ((lane >> 4) << 3)) * KROW_B
                              + t * 32 + (((lane >> 3) & 1) << 4);
                uint32_t r4[4];
                ldsm_x4(r4, addr);
                bb[2 * p][0] = r4[0]; bb[2 * p][1] = r4[1];
                bb[2 * p + 1][0] = r4[2]; bb[2 * p + 1][1] = r4[3];
            }
#pragma unroll
            for (int nt = 0; nt < 8; nt++) {
                mma16h(s[0][nt], qf[0][t], bb[nt]);
                mma16h(s[1][nt], qf[1][t], bb[nt]);
            }
        }

#pragma unroll
        for (int mt = 0; mt < 2; mt++) {
#pragma unroll
            for (int half = 0; half < 2; half++) {
                float sim[16];
                float vmax = -INFINITY;
                if (mnz) {
                    const float* mp = Mg + (size_t)(warp * 32 + mt * 16 + r + half * 8) * NSEQ + k0;
#pragma unroll
                    for (int nt = 0; nt < 8; nt++) {
                        float2 mk = *(const float2*)(mp + nt * 8 + 2 * cq);
                        sim[2 * nt]     = s[mt][nt][half * 2 + 0] + mk.x;
                        sim[2 * nt + 1] = s[mt][nt][half * 2 + 1] + mk.y;
                        vmax = fmaxf(vmax, fmaxf(sim[2 * nt], sim[2 * nt + 1]));
                    }
                } else {
#pragma unroll
                    for (int nt = 0; nt < 8; nt++) {
                        sim[2 * nt]     = s[mt][nt][half * 2 + 0];
                        sim[2 * nt + 1] = s[mt][nt][half * 2 + 1];
                        vmax = fmaxf(vmax, fmaxf(sim[2 * nt], sim[2 * nt + 1]));
                    }
                }
                vmax = fmaxf(vmax, __shfl_xor_sync(0xffffffffu, vmax, 1, 4));
                vmax = fmaxf(vmax, __shfl_xor_sync(0xffffffffu, vmax, 2, 4));
                float mnew = fmaxf(mrow[mt][half], vmax);
                float corr = __expf(mrow[mt][half] - mnew);
                float sum = 0.0f;
                const uint32_t prow = pw + (mt * 16 + r + half * 8) * KROW_B;
#pragma unroll
                for (int nt = 0; nt < 8; nt++) {
                    float p0 = __expf(sim[2 * nt]     - mnew);
                    float p1 = __expf(sim[2 * nt + 1] - mnew);
                    sum += p0 + p1;
                    __half2 ph;
                    ph.x = __float2half(p0);
                    ph.y = __float2half(p1);
                    *(__half2*)(smf + (prow - sbase) + (nt * 8 + 2 * cq) * 2) = ph;
                }
                sum += __shfl_xor_sync(0xffffffffu, sum, 1, 4);
                sum += __shfl_xor_sync(0xffffffffu, sum, 2, 4);
                lrow[mt][half] = lrow[mt][half] * corr + sum;
                mrow[mt][half] = mnew;
#pragma unroll
                for (int nt = 0; nt < 8; nt++) {
                    o[mt][nt][half * 2 + 0] *= corr;
                    o[mt][nt][half * 2 + 1] *= corr;
                }
            }
        }
        __syncwarp();

#pragma unroll
        for (int t = 0; t < 4; t++) {
            uint32_t af[2][4];
#pragma unroll
            for (int mt = 0; mt < 2; mt++) {
                uint32_t addr = pw + (mt * 16 + (lane & 15)) * KROW_B
                              + t * 32 + ((lane >> 4) << 4);
                ldsm_x4(af[mt], addr);
            }
            uint32_t bb[8][2];
#pragma unroll
            for (int p = 0; p < 4; p++) {
                uint32_t addr = vbuf + (p * 16 + (lane & 7) + ((lane >> 4) << 3)) * KROW_B
                              + t * 32 + (((lane >> 3) & 1) << 4);
                uint32_t r4[4];
                ldsm_x4(r4, addr);
                bb[2 * p][0] = r4[0]; bb[2 * p][1] = r4[1];
                bb[2 * p + 1][0] = r4[2]; bb[2 * p + 1][1] = r4[3];
            }
#pragma unroll
            for (int nt = 0; nt < 8; nt++) {
                mma16h(o[0][nt], af[0], bb[nt]);
                mma16h(o[1][nt], af[1], bb[nt]);
            }
        }
        __syncthreads();
    }

#pragma unroll
    for (int mt = 0; mt < 2; mt++) {
        float inv0 = 1.0f / lrow[mt][0], inv1 = 1.0f / lrow[mt][1];
#pragma unroll
        for (int nt = 0; nt < 8; nt++) {
            int col = h * HD + nt * 8 + 2 * cq;
#pragma unroll
            for (int half = 0; half < 2; half++) {
                int m = b * NSEQ + q0 + warp * 32 + mt * 16 + r + half * 8;
                float inv = half ? inv1 : inv0;
                __half2 ph;
                ph.x = __float2half(o[mt][nt][half * 2 + 0] * inv);
                ph.y = __float2half(o[mt][nt][half * 2 + 1] * inv);
                *(__half2*)(g_o16 + (size_t)m * DIMF + col) = ph;
            }
        }
    }
}

// ---------------------------------------------------------------------------
// Launch
// ---------------------------------------------------------------------------
extern "C" void kernel_launch(void* const* d_in, const int* in_sizes, int n_in,
                              void* d_out, int out_size)
{
    const float* x    = (const float*)d_in[0];
    const float* mask = (const float*)d_in[1];
    const float* Wq   = (const float*)d_in[2];
    const float* Wk   = (const float*)d_in[3];
    const float* Wv   = (const float*)d_in[4];
    const float* Wo   = (const float*)d_in[5];
    const float* bo   = (const float*)d_in[6];
    float* out = (float*)d_out;

    const int GEMM0_SMEM = 3 * 2 * TILE_B;   // 61440 B
    const int GEMM1_SMEM = 3 * 3 * TILE_B;   // 92160 B
    cudaFuncSetAttribute(gemm_fp16<0>, cudaFuncAttributeMaxDynamicSharedMemorySize, GEMM0_SMEM);
    cudaFuncSetAttribute(gemm_fp16<1>, cudaFuncAttributeMaxDynamicSharedMemorySize, GEMM1_SMEM);
    cudaFuncSetAttribute(flash_fp16,   cudaFuncAttributeMaxDynamicSharedMemorySize, FLASH_SMEM_B);

    mask_reset<<<1, 1>>>();
    mask_scan<<<256, 256>>>(mask, (BATCH * NSEQ * NSEQ) / 4);

    conv_split<<<MROWS + 4 * DIMF, 256>>>(x, Wq, Wk, Wv, Wo);

    gemm_fp16<0><<<dim3(8, 32, 3), 256, GEMM0_SMEM>>>(nullptr, nullptr);

    rmsrope_kernel<<<dim3((BATCH * NH * NSEQ) / 8, 2), 256>>>();

    flash_fp16<<<dim3(NSEQ / 128, BATCH * NH), 128, FLASH_SMEM_B>>>(mask);

    gemm_fp16<1><<<dim3(8, 32), 256, GEMM1_SMEM>>>(bo, out);
}

// round 14
// speedup vs baseline: 6.4328x; 1.1265x over previous
#include <cuda_runtime.h>
#include <cuda_fp16.h>
#include <math.h>
#include <stdint.h>

#define BATCH 2
#define NSEQ  2048
#define DIMF  1024
#define NH    16
#define HD    64
#define MROWS (BATCH * NSEQ)   // 4096

// fp32 scratch: projection results for Q/K (input to rmsnorm)
__device__ float g_q [BATCH * NH * NSEQ * HD];
__device__ float g_k [BATCH * NH * NSEQ * HD];

// fp16 attention operands (Q carries log2e/64 factor)
__device__ __half g_q16 [BATCH * NH * NSEQ * HD];
__device__ __half g_k16 [BATCH * NH * NSEQ * HD];
__device__ __half g_vt16[BATCH * NH * HD * NSEQ];   // [b,h,d,seq]

// fp16 GEMM operands (single-rounded everywhere)
__device__ __half g_x16[(size_t)MROWS * DIMF];
__device__ __half g_o16[(size_t)MROWS * DIMF];      // flash output, gathered
__device__ __half g_wh [(size_t)4 * DIMF * DIMF];

__device__ int g_mask_nz;

#define LOG2E 1.4426950408889634f

// ---------------------------------------------------------------------------
// helpers
// ---------------------------------------------------------------------------
__device__ __forceinline__ uint32_t saddr(const void* p) {
    return (uint32_t)__cvta_generic_to_shared(p);
}
__device__ __forceinline__ float ex2f(float x) {
    float y;
    asm("ex2.approx.ftz.f32 %0, %1;" : "=f"(y) : "f"(x));
    return y;
}
__device__ __forceinline__ void ldsm_x4(uint32_t r[4], uint32_t a) {
    asm volatile("ldmatrix.sync.aligned.m8n8.x4.shared.b16 {%0,%1,%2,%3}, [%4];"
                 : "=r"(r[0]), "=r"(r[1]), "=r"(r[2]), "=r"(r[3]) : "r"(a));
}
__device__ __forceinline__ void mma16h(float c[4], const uint32_t a[4], const uint32_t b[2]) {
    asm volatile(
        "mma.sync.aligned.m16n8k16.row.col.f32.f16.f16.f32 "
        "{%0,%1,%2,%3}, {%4,%5,%6,%7}, {%8,%9}, {%0,%1,%2,%3};"
        : "+f"(c[0]), "+f"(c[1]), "+f"(c[2]), "+f"(c[3])
        : "r"(a[0]), "r"(a[1]), "r"(a[2]), "r"(a[3]), "r"(b[0]), "r"(b[1]));
}
__device__ __forceinline__ void cpasync16(uint32_t s, const void* g) {
    asm volatile("cp.async.cg.shared.global [%0], [%1], 16;" :: "r"(s), "l"(g) : "memory");
}
#define CP_COMMIT()  asm volatile("cp.async.commit_group;" ::: "memory")
#define CP_WAIT(n)   asm volatile("cp.async.wait_group %0;" :: "n"(n) : "memory")

// ---------------------------------------------------------------------------
// mask scan
// ---------------------------------------------------------------------------
__global__ void mask_reset() { g_mask_nz = 0; }

__global__ void __launch_bounds__(256) mask_scan(const float* __restrict__ mask, int n4)
{
    const float4* m4 = (const float4*)mask;
    uint32_t acc = 0;
    for (int i = blockIdx.x * 256 + threadIdx.x; i < n4; i += gridDim.x * 256) {
        float4 v = m4[i];
        acc |= __float_as_uint(v.x) | __float_as_uint(v.y)
             | __float_as_uint(v.z) | __float_as_uint(v.w);
    }
    if (acc) atomicOr(&g_mask_nz, 1);
}

// ---------------------------------------------------------------------------
// Convert: x -> fp16; Wq/Wk/Wv/Wo -> fp16
// ---------------------------------------------------------------------------
__global__ void __launch_bounds__(256) conv_split(
    const float* __restrict__ x,
    const float* __restrict__ Wq, const float* __restrict__ Wk,
    const float* __restrict__ Wv, const float* __restrict__ Wo)
{
    const int row = blockIdx.x;
    const int c = threadIdx.x * 4;
    const float* src;
    __half* dst;
    if (row < MROWS) {
        src = x + (size_t)row * DIMF;
        dst = g_x16 + (size_t)row * DIMF;
    } else {
        int wi = (row - MROWS) >> 10, r = (row - MROWS) & 1023;
        const float* W = (wi == 0) ? Wq : (wi == 1) ? Wk : (wi == 2) ? Wv : Wo;
        src = W + (size_t)r * DIMF;
        dst = g_wh + ((size_t)wi * DIMF + r) * DIMF;
    }
    float4 v = *(const float4*)(src + c);
    __half2 p0; p0.x = __float2half(v.x); p0.y = __float2half(v.y);
    __half2 p1; p1.x = __float2half(v.z); p1.y = __float2half(v.w);
    *(__half2*)(dst + c)     = p0;
    *(__half2*)(dst + c + 2) = p1;
}

// ---------------------------------------------------------------------------
// fp16 GEMM (NT), 3-stage cp.async ring, one __syncthreads per stage.
// Single-pass C = A16 * Wh[z]^T for all z. OUT selects A source + epilogue.
// CTA 128x128, BK=32, 256 threads (8 warps 4x2, warp tile 32x64).
// ---------------------------------------------------------------------------
#define TILE_B   10240
#define NKSTAGES 32
#define GEMM_SMEM (3 * 2 * TILE_B)   // 61440 B

template <int OUT>
__global__ void __launch_bounds__(256, 2) gemm_fp16(
    const float* __restrict__ bias, float* __restrict__ Cout)
{
    constexpr int STAGE = 2 * TILE_B;
    extern __shared__ char smem[];
    const uint32_t sbase = saddr(smem);
    const int tid = threadIdx.x, warp = tid >> 5, lane = tid & 31;
    const int m0 = blockIdx.y * 128, n0 = blockIdx.x * 128;
    const int z = OUT ? 3 : blockIdx.z;

    const __half* A  = OUT ? g_o16 : g_x16;
    const __half* Bh = g_wh + (size_t)z * DIMF * DIMF;

    const int lrow = tid >> 1;
    const int lq   = (tid & 1) * 2;

    auto load_stage = [&](int s) {
        const uint32_t d0 = sbase + (s % 3) * STAGE + lrow * 80 + lq * 16;
        const int kc = s * 32 + lq * 8;
        const __half* pa = A  + (size_t)(m0 + lrow) * DIMF + kc;
        const __half* pb = Bh + (size_t)(n0 + lrow) * DIMF + kc;
        cpasync16(d0,          pa);   cpasync16(d0 + 16,          pa + 8);
        cpasync16(d0 + TILE_B, pb);   cpasync16(d0 + TILE_B + 16, pb + 8);
        CP_COMMIT();
    };

    float acc[2][8][4];
#pragma unroll
    for (int i = 0; i < 2; i++)
#pragma unroll
        for (int j = 0; j < 8; j++)
#pragma unroll
            for (int l = 0; l < 4; l++) acc[i][j][l] = 0.0f;

    const int mw = (warp >> 1) * 32;
    const int nw = (warp & 1) * 64;

    load_stage(0);
    load_stage(1);

    for (int s = 0; s < NKSTAGES; s++) {
        if (s == NKSTAGES - 1) CP_WAIT(0); else CP_WAIT(1);
        __syncthreads();

        const uint32_t base = sbase + (s % 3) * STAGE;
#pragma unroll
        for (int t = 0; t < 2; t++) {
            const int kk = t * 16;
            uint32_t a16[2][4];
#pragma unroll
            for (int mt = 0; mt < 2; mt++) {
                uint32_t addr = base + (mw + mt * 16 + (lane & 15)) * 80
                              + kk * 2 + ((lane >> 4) << 4);
                ldsm_x4(a16[mt], addr);
            }
#pragma unroll
            for (int p = 0; p < 4; p++) {
                uint32_t baddr = base + TILE_B
                               + (nw + p * 16 + (lane & 7) + ((lane >> 4) << 3)) * 80
                               + kk * 2 + (((lane >> 3) & 1) << 4);
                uint32_t bh4[4];
                ldsm_x4(bh4, baddr);
#pragma unroll
                for (int mt = 0; mt < 2; mt++) {
                    mma16h(acc[mt][2 * p],     a16[mt], bh4);
                    mma16h(acc[mt][2 * p + 1], a16[mt], bh4 + 2);
                }
            }
        }
        if (s + 2 < NKSTAGES) load_stage(s + 2);
    }

    // epilogue
#pragma unroll
    for (int mt = 0; mt < 2; mt++) {
#pragma unroll
        for (int nt = 0; nt < 8; nt++) {
#pragma unroll
            for (int half = 0; half < 2; half++) {
                int m = m0 + mw + mt * 16 + (lane >> 2) + half * 8;
                int c = n0 + nw + nt * 8 + ((lane & 3) << 1);
                float2 v = make_float2(acc[mt][nt][half * 2 + 0],
                                       acc[mt][nt][half * 2 + 1]);
                if (OUT) {
                    const float2 bb2 = *(const float2*)(bias + c);
                    v.x += bb2.x; v.y += bb2.y;
                    *(float2*)(Cout + (size_t)m * DIMF + c) = v;
                } else {
                    int bb = m >> 11, n = m & (NSEQ - 1);
                    int h = c >> 6, d = c & (HD - 1);
                    if (z == 2) {
                        __half* basep = g_vt16 + (((size_t)(bb * NH + h) * HD + d) * NSEQ) + n;
                        basep[0]    = __float2half(v.x);
                        basep[NSEQ] = __float2half(v.y);
                    } else {
                        float* dst = (z == 0 ? g_q : g_k)
                                   + (((size_t)(bb * NH + h) * NSEQ + n) << 6) + d;
                        *(float2*)dst = v;
                    }
                }
            }
        }
    }
}

// ---------------------------------------------------------------------------
// RMSNorm + RoPE: reads fp32 g_q/g_k, writes fp16 g_q16/g_k16.
// Q pre-scaled by log2e/64 so flash computes p = 2^S directly.
// ---------------------------------------------------------------------------
__global__ void __launch_bounds__(256) rmsrope_kernel()
{
    const int warp = threadIdx.x >> 5;
    const int lane = threadIdx.x & 31;
    const size_t row = (size_t)blockIdx.x * 8 + warp;
    const int isQ = (blockIdx.y == 0);
    const float* src = (isQ ? g_q : g_k) + row * HD;
    __half* dst = (isQ ? g_q16 : g_k16) + row * HD;

    float2 x = *(const float2*)(src + lane * 2);
    float ss = x.x * x.x + x.y * x.y;
#pragma unroll
    for (int off = 16; off; off >>= 1)
        ss += __shfl_xor_sync(0xffffffffu, ss, off);
    float rn = rsqrtf(ss * (1.0f / 64.0f) + 1e-5f);

    int pos = (int)(row & (NSEQ - 1));
    float ifr = exp2f((float)lane * (-2.0f / 64.0f) * 13.287712379549449f);
    float ang = (float)pos * ifr;
    float s, c;
    sincosf(ang, &s, &c);

    float x0 = x.x * rn, x1 = x.y * rn;
    float post = isQ ? (LOG2E / 64.0f) : 1.0f;
    __half2 y;
    y.x = __float2half((x0 * c - x1 * s) * post);
    y.y = __float2half((x1 * c + x0 * s) * post);
    *(__half2*)(dst + lane * 2) = y;
}

// ---------------------------------------------------------------------------
// Flash attention, fp16 m16n8k16. 128 threads (4 warps), 32 q-rows/warp,
// shared K/V fragments, double-buffered cp.async K/V.
// S is in log2 domain (Q carries log2e/64). Fast path (mask==0): p = 2^S,
// no max tracking, no rescale (|S| <= log2e by Cauchy-Schwarz on RMS rows).
// Slow path (mask!=0): online softmax in log2 domain.
// ---------------------------------------------------------------------------
#define KROW_B   144
#define KVBUF_B  (2 * 64 * KROW_B)
#define PS_OFF   (2 * KVBUF_B)
#define FLASH_SMEM_B (PS_OFF + 128 * KROW_B)   // 55296

__global__ void __launch_bounds__(128) flash_fp16(const float* __restrict__ mask)
{
    extern __shared__ char smf[];
    const uint32_t sbase = saddr(smf);

    const int tid = threadIdx.x, warp = tid >> 5, lane = tid & 31;
    const int bh = blockIdx.y, b = bh >> 4, h = bh & 15;
    const int q0 = blockIdx.x * 128;
    const int mnz = g_mask_nz;

    const __half* Qg  = g_q16  + ((size_t)bh * NSEQ + q0) * HD;
    const __half* Kg  = g_k16  + (size_t)bh * NSEQ * HD;
    const __half* Vtg = g_vt16 + (size_t)bh * HD * NSEQ;
    const float*  Mg  = mask + (size_t)b * NSEQ * NSEQ + (size_t)q0 * NSEQ;

    auto load_kv = [&](int kt) {
        const int k0 = kt * 64;
        const uint32_t kb = sbase + (kt & 1) * KVBUF_B;
        const int row = tid >> 3;
        const int ch  = (tid & 7) * 16;
#pragma unroll
        for (int i = 0; i < 4; i++) {
            int rr = row + i * 16;
            cpasync16(kb + rr * KROW_B + ch,
                      (const char*)(Kg + (size_t)(k0 + rr) * HD) + ch);
            cpasync16(kb + 64 * KROW_B + rr * KROW_B + ch,
                      (const char*)(Vtg + (size_t)rr * NSEQ + k0) + ch);
        }
        CP_COMMIT();
    };

    load_kv(0);

    {
        const int row = tid >> 3;
        const int ch  = (tid & 7) * 16;
#pragma unroll
        for (int i = 0; i < 8; i++) {
            int rr = row + i * 16;
            *(uint4*)(smf + PS_OFF + rr * KROW_B + ch) =
                *(const uint4*)((const char*)(Qg + (size_t)rr * HD) + ch);
        }
    }
    __syncthreads();
    uint32_t qf[2][4][4];
#pragma unroll
    for (int mt = 0; mt < 2; mt++) {
        int row = warp * 32 + mt * 16 + (lane & 15);
#pragma unroll
        for (int t = 0; t < 4; t++)
            ldsm_x4(qf[mt][t], sbase + PS_OFF + row * KROW_B + t * 32 + ((lane >> 4) << 4));
    }
    __syncthreads();

    const int r  = lane >> 2;
    const int cq = lane & 3;
    const uint32_t pw = sbase + PS_OFF + warp * 32 * KROW_B;

    float mrow[2][2] = {{-INFINITY, -INFINITY}, {-INFINITY, -INFINITY}};
    float lrow[2][2] = {{0.0f, 0.0f}, {0.0f, 0.0f}};
    float o[2][8][4];
#pragma unroll
    for (int mt = 0; mt < 2; mt++)
#pragma unroll
        for (int nt = 0; nt < 8; nt++)
#pragma unroll
            for (int j = 0; j < 4; j++) o[mt][nt][j] = 0.0f;

    for (int kt = 0; kt < NSEQ / 64; kt++) {
        const int k0 = kt * 64;
        if (kt + 1 < NSEQ / 64) { load_kv(kt + 1); CP_WAIT(1); }
        else                    { CP_WAIT(0); }
        __syncthreads();

        const uint32_t kbuf = sbase + (kt & 1) * KVBUF_B;
        const uint32_t vbuf = kbuf + 64 * KROW_B;

        // S = Q K^T (log2 domain)
        float s[2][8][4];
#pragma unroll
        for (int mt = 0; mt < 2; mt++)
#pragma unroll
            for (int nt = 0; nt < 8; nt++)
#pragma unroll
                for (int j = 0; j < 4; j++) s[mt][nt][j] = 0.0f;

#pragma unroll
        for (int t = 0; t < 4; t++) {
            uint32_t bb[8][2];
#pragma unroll
            for (int p = 0; p < 4; p++) {
                uint32_t addr = kbuf + (p * 16 + (lane & 7) + ((lane >> 4) << 3)) * KROW_B
                              + t * 32 + (((lane >> 3) & 1) << 4);
                uint32_t r4[4];
                ldsm_x4(r4, addr);
                bb[2 * p][0] = r4[0]; bb[2 * p][1] = r4[1];
                bb[2 * p + 1][0] = r4[2]; bb[2 * p + 1][1] = r4[3];
            }
#pragma unroll
            for (int nt = 0; nt < 8; nt++) {
                mma16h(s[0][nt], qf[0][t], bb[nt]);
                mma16h(s[1][nt], qf[1][t], bb[nt]);
            }
        }

        if (!mnz) {
            // FAST PATH: |S| <= log2e, no overflow possible -> plain exp2
#pragma unroll
            for (int mt = 0; mt < 2; mt++) {
#pragma unroll
                for (int half = 0; half < 2; half++) {
                    float sum = 0.0f;
                    const uint32_t prow = pw + (mt * 16 + r + half * 8) * KROW_B;
#pragma unroll
                    for (int nt = 0; nt < 8; nt++) {
                        float p0 = ex2f(s[mt][nt][half * 2 + 0]);
                        float p1 = ex2f(s[mt][nt][half * 2 + 1]);
                        sum += p0 + p1;
                        __half2 ph;
                        ph.x = __float2half(p0);
                        ph.y = __float2half(p1);
                        *(__half2*)(smf + (prow - sbase) + (nt * 8 + 2 * cq) * 2) = ph;
                    }
                    sum += __shfl_xor_sync(0xffffffffu, sum, 1, 4);
                    sum += __shfl_xor_sync(0xffffffffu, sum, 2, 4);
                    lrow[mt][half] += sum;
                }
            }
        } else {
            // SLOW PATH: online softmax in log2 domain
#pragma unroll
            for (int mt = 0; mt < 2; mt++) {
#pragma unroll
                for (int half = 0; half < 2; half++) {
                    float sim[16];
                    float vmax = -INFINITY;
                    const float* mp = Mg + (size_t)(warp * 32 + mt * 16 + r + half * 8) * NSEQ + k0;
#pragma unroll
                    for (int nt = 0; nt < 8; nt++) {
                        float2 mk = *(const float2*)(mp + nt * 8 + 2 * cq);
                        sim[2 * nt]     = fmaf(mk.x, LOG2E, s[mt][nt][half * 2 + 0]);
                        sim[2 * nt + 1] = fmaf(mk.y, LOG2E, s[mt][nt][half * 2 + 1]);
                        vmax = fmaxf(vmax, fmaxf(sim[2 * nt], sim[2 * nt + 1]));
                    }
                    vmax = fmaxf(vmax, __shfl_xor_sync(0xffffffffu, vmax, 1, 4));
                    vmax = fmaxf(vmax, __shfl_xor_sync(0xffffffffu, vmax, 2, 4));
                    float mnew = fmaxf(mrow[mt][half], vmax);
                    float corr = ex2f(mrow[mt][half] - mnew);
                    float sum = 0.0f;
                    const uint32_t prow = pw + (mt * 16 + r + half * 8) * KROW_B;
#pragma unroll
                    for (int nt = 0; nt < 8; nt++) {
                        float p0 = ex2f(sim[2 * nt]     - mnew);
                        float p1 = ex2f(sim[2 * nt + 1] - mnew);
                        sum += p0 + p1;
                        __half2 ph;
                        ph.x = __float2half(p0);
                        ph.y = __float2half(p1);
                        *(__half2*)(smf + (prow - sbase) + (nt * 8 + 2 * cq) * 2) = ph;
                    }
                    sum += __shfl_xor_sync(0xffffffffu, sum, 1, 4);
                    sum += __shfl_xor_sync(0xffffffffu, sum, 2, 4);
                    lrow[mt][half] = lrow[mt][half] * corr + sum;
                    mrow[mt][half] = mnew;
#pragma unroll
                    for (int nt = 0; nt < 8; nt++) {
                        o[mt][nt][half * 2 + 0] *= corr;
                        o[mt][nt][half * 2 + 1] *= corr;
                    }
                }
            }
        }
        __syncwarp();

        // O += P V
#pragma unroll
        for (int t = 0; t < 4; t++) {
            uint32_t af[2][4];
#pragma unroll
            for (int mt = 0; mt < 2; mt++) {
                uint32_t addr = pw + (mt * 16 + (lane & 15)) * KROW_B
                              + t * 32 + ((lane >> 4) << 4);
                ldsm_x4(af[mt], addr);
            }
            uint32_t bb[8][2];
#pragma unroll
            for (int p = 0; p < 4; p++) {
                uint32_t addr = vbuf + (p * 16 + (lane & 7) + ((lane >> 4) << 3)) * KROW_B
                              + t * 32 + (((lane >> 3) & 1) << 4);
                uint32_t r4[4];
                ldsm_x4(r4, addr);
                bb[2 * p][0] = r4[0]; bb[2 * p][1] = r4[1];
                bb[2 * p + 1][0] = r4[2]; bb[2 * p + 1][1] = r4[3];
            }
#pragma unroll
            for (int nt = 0; nt < 8; nt++) {
                mma16h(o[0][nt], af[0], bb[nt]);
                mma16h(o[1][nt], af[1], bb[nt]);
            }
        }
        __syncthreads();
    }

    // epilogue: single fp16 into gathered layout [b*2048+seq][h*64+d]
#pragma unroll
    for (int mt = 0; mt < 2; mt++) {
        float inv0 = 1.0f / lrow[mt][0], inv1 = 1.0f / lrow[mt][1];
#pragma unroll
        for (int nt = 0; nt < 8; nt++) {
            int col = h * HD + nt * 8 + 2 * cq;
#pragma unroll
            for (int half = 0; half < 2; half++) {
                int m = b * NSEQ + q0 + warp * 32 + mt * 16 + r + half * 8;
                float inv = half ? inv1 : inv0;
                __half2 ph;
                ph.x = __float2half(o[mt][nt][half * 2 + 0] * inv);
                ph.y = __float2half(o[mt][nt][half * 2 + 1] * inv);
                *(__half2*)(g_o16 + (size_t)m * DIMF + col) = ph;
            }
        }
    }
}

// ---------------------------------------------------------------------------
// Launch
// ---------------------------------------------------------------------------
extern "C" void kernel_launch(void* const* d_in, const int* in_sizes, int n_in,
                              void* d_out, int out_size)
{
    const float* x    = (const float*)d_in[0];
    const float* mask = (const float*)d_in[1];
    const float* Wq   = (const float*)d_in[2];
    const float* Wk   = (const float*)d_in[3];
    const float* Wv   = (const float*)d_in[4];
    const float* Wo   = (const float*)d_in[5];
    const float* bo   = (const float*)d_in[6];
    float* out = (float*)d_out;

    cudaFuncSetAttribute(gemm_fp16<0>, cudaFuncAttributeMaxDynamicSharedMemorySize, GEMM_SMEM);
    cudaFuncSetAttribute(gemm_fp16<1>, cudaFuncAttributeMaxDynamicSharedMemorySize, GEMM_SMEM);
    cudaFuncSetAttribute(flash_fp16,   cudaFuncAttributeMaxDynamicSharedMemorySize, FLASH_SMEM_B);

    mask_reset<<<1, 1>>>();
    mask_scan<<<256, 256>>>(mask, (BATCH * NSEQ * NSEQ) / 4);

    conv_split<<<MROWS + 4 * DIMF, 256>>>(x, Wq, Wk, Wv, Wo);

    gemm_fp16<0><<<dim3(8, 32, 3), 256, GEMM_SMEM>>>(nullptr, nullptr);

    rmsrope_kernel<<<dim3((BATCH * NH * NSEQ) / 8, 2), 256>>>();

    flash_fp16<<<dim3(NSEQ / 128, BATCH * NH), 128, FLASH_SMEM_B>>>(mask);

    gemm_fp16<1><<<dim3(8, 32), 256, GEMM_SMEM>>>(bo, out);
}

// round 15
// speedup vs baseline: 6.6791x; 1.0383x over previous
#include <cuda_runtime.h>
#include <cuda_fp16.h>
#include <math.h>
#include <stdint.h>

#define BATCH 2
#define NSEQ  2048
#define DIMF  1024
#define NH    16
#define HD    64
#define MROWS (BATCH * NSEQ)   // 4096

// fp16 attention operands (Q carries log2e/64 factor)
__device__ __half g_q16 [BATCH * NH * NSEQ * HD];
__device__ __half g_k16 [BATCH * NH * NSEQ * HD];
__device__ __half g_vt16[BATCH * NH * HD * NSEQ];   // [b,h,d,seq]

// fp16 GEMM operands
__device__ __half g_x16[(size_t)MROWS * DIMF];
__device__ __half g_o16[(size_t)MROWS * DIMF];      // flash output, gathered
__device__ __half g_wh [(size_t)4 * DIMF * DIMF];

__device__ int g_mask_nz = 0;   // static init; atomicOr is idempotent per fixed mask

#define LOG2E 1.4426950408889634f

// ---------------------------------------------------------------------------
// helpers
// ---------------------------------------------------------------------------
__device__ __forceinline__ uint32_t saddr(const void* p) {
    return (uint32_t)__cvta_generic_to_shared(p);
}
__device__ __forceinline__ float ex2f(float x) {
    float y;
    asm("ex2.approx.ftz.f32 %0, %1;" : "=f"(y) : "f"(x));
    return y;
}
__device__ __forceinline__ void ldsm_x4(uint32_t r[4], uint32_t a) {
    asm volatile("ldmatrix.sync.aligned.m8n8.x4.shared.b16 {%0,%1,%2,%3}, [%4];"
                 : "=r"(r[0]), "=r"(r[1]), "=r"(r[2]), "=r"(r[3]) : "r"(a));
}
__device__ __forceinline__ void mma16h(float c[4], const uint32_t a[4], const uint32_t b[2]) {
    asm volatile(
        "mma.sync.aligned.m16n8k16.row.col.f32.f16.f16.f32 "
        "{%0,%1,%2,%3}, {%4,%5,%6,%7}, {%8,%9}, {%0,%1,%2,%3};"
        : "+f"(c[0]), "+f"(c[1]), "+f"(c[2]), "+f"(c[3])
        : "r"(a[0]), "r"(a[1]), "r"(a[2]), "r"(a[3]), "r"(b[0]), "r"(b[1]));
}
__device__ __forceinline__ void cpasync16(uint32_t s, const void* g) {
    asm volatile("cp.async.cg.shared.global [%0], [%1], 16;" :: "r"(s), "l"(g) : "memory");
}
#define CP_COMMIT()  asm volatile("cp.async.commit_group;" ::: "memory")
#define CP_WAIT(n)   asm volatile("cp.async.wait_group %0;" :: "n"(n) : "memory")

// ---------------------------------------------------------------------------
// mask scan (no reset kernel: static-zero + idempotent OR)
// ---------------------------------------------------------------------------
__global__ void __launch_bounds__(256) mask_scan(const float* __restrict__ mask, int n4)
{
    const float4* m4 = (const float4*)mask;
    uint32_t acc = 0;
    for (int i = blockIdx.x * 256 + threadIdx.x; i < n4; i += gridDim.x * 256) {
        float4 v = m4[i];
        acc |= __float_as_uint(v.x) | __float_as_uint(v.y)
             | __float_as_uint(v.z) | __float_as_uint(v.w);
    }
    if (acc) atomicOr(&g_mask_nz, 1);
}

// ---------------------------------------------------------------------------
// Convert: x -> fp16; Wq/Wk/Wv/Wo -> fp16
// ---------------------------------------------------------------------------
__global__ void __launch_bounds__(256) conv_split(
    const float* __restrict__ x,
    const float* __restrict__ Wq, const float* __restrict__ Wk,
    const float* __restrict__ Wv, const float* __restrict__ Wo)
{
    const int row = blockIdx.x;
    const int c = threadIdx.x * 4;
    const float* src;
    __half* dst;
    if (row < MROWS) {
        src = x + (size_t)row * DIMF;
        dst = g_x16 + (size_t)row * DIMF;
    } else {
        int wi = (row - MROWS) >> 10, r = (row - MROWS) & 1023;
        const float* W = (wi == 0) ? Wq : (wi == 1) ? Wk : (wi == 2) ? Wv : Wo;
        src = W + (size_t)r * DIMF;
        dst = g_wh + ((size_t)wi * DIMF + r) * DIMF;
    }
    float4 v = *(const float4*)(src + c);
    __half2 p0; p0.x = __float2half(v.x); p0.y = __float2half(v.y);
    __half2 p1; p1.x = __float2half(v.z); p1.y = __float2half(v.w);
    *(__half2*)(dst + c)     = p0;
    *(__half2*)(dst + c + 2) = p1;
}

// ---------------------------------------------------------------------------
// fp16 GEMM (NT), 3-stage cp.async ring, one __syncthreads per stage.
// OUT=0: z=0/1 epilogue fuses RMSNorm+RoPE -> g_q16/g_k16 (fp16);
//        z=2 stores transposed fp16 V.
// OUT=1: bias add, fp32 out.
// ---------------------------------------------------------------------------
#define TILE_B   10240
#define NKSTAGES 32
#define GEMM_SMEM (3 * 2 * TILE_B)   // 61440 B

template <int OUT>
__global__ void __launch_bounds__(256, 2) gemm_fp16(
    const float* __restrict__ bias, float* __restrict__ Cout)
{
    constexpr int STAGE = 2 * TILE_B;
    extern __shared__ char smem[];
    const uint32_t sbase = saddr(smem);
    const int tid = threadIdx.x, warp = tid >> 5, lane = tid & 31;
    const int m0 = blockIdx.y * 128, n0 = blockIdx.x * 128;
    const int z = OUT ? 3 : blockIdx.z;

    const __half* A  = OUT ? g_o16 : g_x16;
    const __half* Bh = g_wh + (size_t)z * DIMF * DIMF;

    const int lrow = tid >> 1;
    const int lq   = (tid & 1) * 2;

    auto load_stage = [&](int s) {
        const uint32_t d0 = sbase + (s % 3) * STAGE + lrow * 80 + lq * 16;
        const int kc = s * 32 + lq * 8;
        const __half* pa = A  + (size_t)(m0 + lrow) * DIMF + kc;
        const __half* pb = Bh + (size_t)(n0 + lrow) * DIMF + kc;
        cpasync16(d0,          pa);   cpasync16(d0 + 16,          pa + 8);
        cpasync16(d0 + TILE_B, pb);   cpasync16(d0 + TILE_B + 16, pb + 8);
        CP_COMMIT();
    };

    float acc[2][8][4];
#pragma unroll
    for (int i = 0; i < 2; i++)
#pragma unroll
        for (int j = 0; j < 8; j++)
#pragma unroll
            for (int l = 0; l < 4; l++) acc[i][j][l] = 0.0f;

    const int mw = (warp >> 1) * 32;
    const int nw = (warp & 1) * 64;

    load_stage(0);
    load_stage(1);

    for (int s = 0; s < NKSTAGES; s++) {
        if (s == NKSTAGES - 1) CP_WAIT(0); else CP_WAIT(1);
        __syncthreads();

        const uint32_t base = sbase + (s % 3) * STAGE;
#pragma unroll
        for (int t = 0; t < 2; t++) {
            const int kk = t * 16;
            uint32_t a16[2][4];
#pragma unroll
            for (int mt = 0; mt < 2; mt++) {
                uint32_t addr = base + (mw + mt * 16 + (lane & 15)) * 80
                              + kk * 2 + ((lane >> 4) << 4);
                ldsm_x4(a16[mt], addr);
            }
#pragma unroll
            for (int p = 0; p < 4; p++) {
                uint32_t baddr = base + TILE_B
                               + (nw + p * 16 + (lane & 7) + ((lane >> 4) << 3)) * 80
                               + kk * 2 + (((lane >> 3) & 1) << 4);
                uint32_t bh4[4];
                ldsm_x4(bh4, baddr);
#pragma unroll
                for (int mt = 0; mt < 2; mt++) {
                    mma16h(acc[mt][2 * p],     a16[mt], bh4);
                    mma16h(acc[mt][2 * p + 1], a16[mt], bh4 + 2);
                }
            }
        }
        if (s + 2 < NKSTAGES) load_stage(s + 2);
    }

    // ---------------- epilogue ----------------
    const int cq = lane & 3;
    if (OUT) {
#pragma unroll
        for (int mt = 0; mt < 2; mt++)
#pragma unroll
            for (int nt = 0; nt < 8; nt++)
#pragma unroll
                for (int half = 0; half < 2; half++) {
                    int m = m0 + mw + mt * 16 + (lane >> 2) + half * 8;
                    int c = n0 + nw + nt * 8 + (cq << 1);
                    const float2 bb2 = *(const float2*)(bias + c);
                    float2 v = make_float2(acc[mt][nt][half * 2 + 0] + bb2.x,
                                           acc[mt][nt][half * 2 + 1] + bb2.y);
                    *(float2*)(Cout + (size_t)m * DIMF + c) = v;
                }
    } else if (z == 2) {
#pragma unroll
        for (int mt = 0; mt < 2; mt++)
#pragma unroll
            for (int nt = 0; nt < 8; nt++)
#pragma unroll
                for (int half = 0; half < 2; half++) {
                    int m = m0 + mw + mt * 16 + (lane >> 2) + half * 8;
                    int bb = m >> 11, n = m & (NSEQ - 1);
                    int c = n0 + nw + nt * 8 + (cq << 1);
                    int h = c >> 6, d = c & (HD - 1);
                    __half* basep = g_vt16 + (((size_t)(bb * NH + h) * HD + d) * NSEQ) + n;
                    basep[0]    = __float2half(acc[mt][nt][half * 2 + 0]);
                    basep[NSEQ] = __float2half(acc[mt][nt][half * 2 + 1]);
                }
    } else {
        // fused RMSNorm + RoPE (z=0 -> Q with log2e/64, z=1 -> K)
        __half* dstbase = (z == 0) ? g_q16 : g_k16;
        const float post = (z == 0) ? (LOG2E / 64.0f) : 1.0f;
        const int head = (n0 + nw) >> 6;   // warp's 64-col slice = one head
#pragma unroll
        for (int mt = 0; mt < 2; mt++) {
#pragma unroll
            for (int half = 0; half < 2; half++) {
                int m = m0 + mw + mt * 16 + (lane >> 2) + half * 8;
                int bb = m >> 11, n = m & (NSEQ - 1);
                // sum of squares over the row's 64 head cols (16 local + quad shfl)
                float ss = 0.0f;
#pragma unroll
                for (int nt = 0; nt < 8; nt++) {
                    float v0 = acc[mt][nt][half * 2 + 0];
                    float v1 = acc[mt][nt][half * 2 + 1];
                    ss += v0 * v0 + v1 * v1;
                }
                ss += __shfl_xor_sync(0xffffffffu, ss, 1, 4);
                ss += __shfl_xor_sync(0xffffffffu, ss, 2, 4);
                float rn = rsqrtf(ss * (1.0f / 64.0f) + 1e-5f);
                __half* dst = dstbase + (((size_t)(bb * NH + head) * NSEQ + n) << 6);
#pragma unroll
                for (int nt = 0; nt < 8; nt++) {
                    int i = nt * 4 + cq;   // rope pair index (d = 2i)
                    float ifr = exp2f((float)i * (-2.0f / 64.0f) * 13.287712379549449f);
                    float ang = (float)n * ifr;
                    float sn, cs;
                    sincosf(ang, &sn, &cs);
                    float x0 = acc[mt][nt][half * 2 + 0] * rn;
                    float x1 = acc[mt][nt][half * 2 + 1] * rn;
                    __half2 y;
                    y.x = __float2half((x0 * cs - x1 * sn) * post);
                    y.y = __float2half((x1 * cs + x0 * sn) * post);
                    *(__half2*)(dst + nt * 8 + (cq << 1)) = y;
                }
            }
        }
    }
}

// ---------------------------------------------------------------------------
// Flash attention, fp16 m16n8k16. 128 threads (4 warps), 32 q-rows/warp.
// 4-buffer KV ring, 2-stage-ahead cp.async prefetch, ONE barrier per kt.
// Fast path (mask==0): p = 2^S (|S| <= log2e by Cauchy-Schwarz on RMS rows).
// ---------------------------------------------------------------------------
#define KROW_B   144
#define KVBUF_B  (2 * 64 * KROW_B)            // 18432
#define PS_OFF   (4 * KVBUF_B)                // 73728
#define FLASH_SMEM_B (PS_OFF + 128 * KROW_B)  // 92160

__global__ void __launch_bounds__(128) flash_fp16(const float* __restrict__ mask)
{
    extern __shared__ char smf[];
    const uint32_t sbase = saddr(smf);

    const int tid = threadIdx.x, warp = tid >> 5, lane = tid & 31;
    const int bh = blockIdx.y, b = bh >> 4, h = bh & 15;
    const int q0 = blockIdx.x * 128;
    const int mnz = g_mask_nz;

    const __half* Qg  = g_q16  + ((size_t)bh * NSEQ + q0) * HD;
    const __half* Kg  = g_k16  + (size_t)bh * NSEQ * HD;
    const __half* Vtg = g_vt16 + (size_t)bh * HD * NSEQ;
    const float*  Mg  = mask + (size_t)b * NSEQ * NSEQ + (size_t)q0 * NSEQ;

    auto load_kv = [&](int kt) {
        const int k0 = kt * 64;
        const uint32_t kb = sbase + (kt & 3) * KVBUF_B;
        const int row = tid >> 3;
        const int ch  = (tid & 7) * 16;
#pragma unroll
        for (int i = 0; i < 4; i++) {
            int rr = row + i * 16;
            cpasync16(kb + rr * KROW_B + ch,
                      (const char*)(Kg + (size_t)(k0 + rr) * HD) + ch);
            cpasync16(kb + 64 * KROW_B + rr * KROW_B + ch,
                      (const char*)(Vtg + (size_t)rr * NSEQ + k0) + ch);
        }
        CP_COMMIT();
    };

    load_kv(0);
    load_kv(1);

    {
        const int row = tid >> 3;
        const int ch  = (tid & 7) * 16;
#pragma unroll
        for (int i = 0; i < 8; i++) {
            int rr = row + i * 16;
            *(uint4*)(smf + PS_OFF + rr * KROW_B + ch) =
                *(const uint4*)((const char*)(Qg + (size_t)rr * HD) + ch);
        }
    }
    __syncthreads();
    uint32_t qf[2][4][4];
#pragma unroll
    for (int mt = 0; mt < 2; mt++) {
        int row = warp * 32 + mt * 16 + (lane & 15);
#pragma unroll
        for (int t = 0; t < 4; t++)
            ldsm_x4(qf[mt][t], sbase + PS_OFF + row * KROW_B + t * 32 + ((lane >> 4) << 4));
    }
    __syncthreads();

    const int r  = lane >> 2;
    const int cq = lane & 3;
    const uint32_t pw = sbase + PS_OFF + warp * 32 * KROW_B;

    float mrow[2][2] = {{-INFINITY, -INFINITY}, {-INFINITY, -INFINITY}};
    float lrow[2][2] = {{0.0f, 0.0f}, {0.0f, 0.0f}};
    float o[2][8][4];
#pragma unroll
    for (int mt = 0; mt < 2; mt++)
#pragma unroll
        for (int nt = 0; nt < 8; nt++)
#pragma unroll
            for (int j = 0; j < 4; j++) o[mt][nt][j] = 0.0f;

    for (int kt = 0; kt < NSEQ / 64; kt++) {
        const int k0 = kt * 64;
        if (kt + 2 < NSEQ / 64)      { load_kv(kt + 2); CP_WAIT(2); }
        else if (kt + 2 == NSEQ / 64) CP_WAIT(1);
        else                          CP_WAIT(0);
        __syncthreads();   // only barrier per kt (4-buf ring makes tail barrier redundant)

        const uint32_t kbuf = sbase + (kt & 3) * KVBUF_B;
        const uint32_t vbuf = kbuf + 64 * KROW_B;

        // S = Q K^T (log2 domain)
        float s[2][8][4];
#pragma unroll
        for (int mt = 0; mt < 2; mt++)
#pragma unroll
            for (int nt = 0; nt < 8; nt++)
#pragma unroll
                for (int j = 0; j < 4; j++) s[mt][nt][j] = 0.0f;

#pragma unroll
        for (int t = 0; t < 4; t++) {
            uint32_t bb[8][2];
#pragma unroll
            for (int p = 0; p < 4; p++) {
                uint32_t addr = kbuf + (p * 16 + (lane & 7) + ((lane >> 4) << 3)) * KROW_B
                              + t * 32 + (((lane >> 3) & 1) << 4);
                uint32_t r4[4];
                ldsm_x4(r4, addr);
                bb[2 * p][0] = r4[0]; bb[2 * p][1] = r4[1];
                bb[2 * p + 1][0] = r4[2]; bb[2 * p + 1][1] = r4[3];
            }
#pragma unroll
            for (int nt = 0; nt < 8; nt++) {
                mma16h(s[0][nt], qf[0][t], bb[nt]);
                mma16h(s[1][nt], qf[1][t], bb[nt]);
            }
        }

        if (!mnz) {
            // FAST PATH: p = 2^S, no max tracking / rescale
#pragma unroll
            for (int mt = 0; mt < 2; mt++) {
#pragma unroll
                for (int half = 0; half < 2; half++) {
                    float sum = 0.0f;
                    const uint32_t prow = pw + (mt * 16 + r + half * 8) * KROW_B;
#pragma unroll
                    for (int nt = 0; nt < 8; nt++) {
                        float p0 = ex2f(s[mt][nt][half * 2 + 0]);
                        float p1 = ex2f(s[mt][nt][half * 2 + 1]);
                        sum += p0 + p1;
                        __half2 ph;
                        ph.x = __float2half(p0);
                        ph.y = __float2half(p1);
                        *(__half2*)(smf + (prow - sbase) + (nt * 8 + 2 * cq) * 2) = ph;
                    }
                    sum += __shfl_xor_sync(0xffffffffu, sum, 1, 4);
                    sum += __shfl_xor_sync(0xffffffffu, sum, 2, 4);
                    lrow[mt][half] += sum;
                }
            }
        } else {
            // SLOW PATH: online softmax in log2 domain
#pragma unroll
            for (int mt = 0; mt < 2; mt++) {
#pragma unroll
                for (int half = 0; half < 2; half++) {
                    float sim[16];
                    float vmax = -INFINITY;
                    const float* mp = Mg + (size_t)(warp * 32 + mt * 16 + r + half * 8) * NSEQ + k0;
#pragma unroll
                    for (int nt = 0; nt < 8; nt++) {
                        float2 mk = *(const float2*)(mp + nt * 8 + 2 * cq);
                        sim[2 * nt]     = fmaf(mk.x, LOG2E, s[mt][nt][half * 2 + 0]);
                        sim[2 * nt + 1] = fmaf(mk.y, LOG2E, s[mt][nt][half * 2 + 1]);
                        vmax = fmaxf(vmax, fmaxf(sim[2 * nt], sim[2 * nt + 1]));
                    }
                    vmax = fmaxf(vmax, __shfl_xor_sync(0xffffffffu, vmax, 1, 4));
                    vmax = fmaxf(vmax, __shfl_xor_sync(0xffffffffu, vmax, 2, 4));
                    float mnew = fmaxf(mrow[mt][half], vmax);
                    float corr = ex2f(mrow[mt][half] - mnew);
                    float sum = 0.0f;
                    const uint32_t prow = pw + (mt * 16 + r + half * 8) * KROW_B;
#pragma unroll
                    for (int nt = 0; nt < 8; nt++) {
                        float p0 = ex2f(sim[2 * nt]     - mnew);
                        float p1 = ex2f(sim[2 * nt + 1] - mnew);
                        sum += p0 + p1;
                        __half2 ph;
                        ph.x = __float2half(p0);
                        ph.y = __float2half(p1);
                        *(__half2*)(smf + (prow - sbase) + (nt * 8 + 2 * cq) * 2) = ph;
                    }
                    sum += __shfl_xor_sync(0xffffffffu, sum, 1, 4);
                    sum += __shfl_xor_sync(0xffffffffu, sum, 2, 4);
                    lrow[mt][half] = lrow[mt][half] * corr + sum;
                    mrow[mt][half] = mnew;
#pragma unroll
                    for (int nt = 0; nt < 8; nt++) {
                        o[mt][nt][half * 2 + 0] *= corr;
                        o[mt][nt][half * 2 + 1] *= corr;
                    }
                }
            }
        }
        __syncwarp();

        // O += P V
#pragma unroll
        for (int t = 0; t < 4; t++) {
            uint32_t af[2][4];
#pragma unroll
            for (int mt = 0; mt < 2; mt++) {
                uint32_t addr = pw + (mt * 16 + (lane & 15)) * KROW_B
                              + t * 32 + ((lane >> 4) << 4);
                ldsm_x4(af[mt], addr);
            }
            uint32_t bb[8][2];
#pragma unroll
            for (int p = 0; p < 4; p++) {
                uint32_t addr = vbuf + (p * 16 + (lane & 7) + ((lane >> 4) << 3)) * KROW_B
                              + t * 32 + (((lane >> 3) & 1) << 4);
                uint32_t r4[4];
                ldsm_x4(r4, addr);
                bb[2 * p][0] = r4[0]; bb[2 * p][1] = r4[1];
                bb[2 * p + 1][0] = r4[2]; bb[2 * p + 1][1] = r4[3];
            }
#pragma unroll
            for (int nt = 0; nt < 8; nt++) {
                mma16h(o[0][nt], af[0], bb[nt]);
                mma16h(o[1][nt], af[1], bb[nt]);
            }
        }
    }

    // epilogue: single fp16 into gathered layout [b*2048+seq][h*64+d]
#pragma unroll
    for (int mt = 0; mt < 2; mt++) {
        float inv0 = 1.0f / lrow[mt][0], inv1 = 1.0f / lrow[mt][1];
#pragma unroll
        for (int nt = 0; nt < 8; nt++) {
            int col = h * HD + nt * 8 + 2 * cq;
#pragma unroll
            for (int half = 0; half < 2; half++) {
                int m = b * NSEQ + q0 + warp * 32 + mt * 16 + r + half * 8;
                float inv = half ? inv1 : inv0;
                __half2 ph;
                ph.x = __float2half(o[mt][nt][half * 2 + 0] * inv);
                ph.y = __float2half(o[mt][nt][half * 2 + 1] * inv);
                *(__half2*)(g_o16 + (size_t)m * DIMF + col) = ph;
            }
        }
    }
}

// ---------------------------------------------------------------------------
// Launch
// ---------------------------------------------------------------------------
extern "C" void kernel_launch(void* const* d_in, const int* in_sizes, int n_in,
                              void* d_out, int out_size)
{
    const float* x    = (const float*)d_in[0];
    const float* mask = (const float*)d_in[1];
    const float* Wq   = (const float*)d_in[2];
    const float* Wk   = (const float*)d_in[3];
    const float* Wv   = (const float*)d_in[4];
    const float* Wo   = (const float*)d_in[5];
    const float* bo   = (const float*)d_in[6];
    float* out = (float*)d_out;

    cudaFuncSetAttribute(gemm_fp16<0>, cudaFuncAttributeMaxDynamicSharedMemorySize, GEMM_SMEM);
    cudaFuncSetAttribute(gemm_fp16<1>, cudaFuncAttributeMaxDynamicSharedMemorySize, GEMM_SMEM);
    cudaFuncSetAttribute(flash_fp16,   cudaFuncAttributeMaxDynamicSharedMemorySize, FLASH_SMEM_B);

    mask_scan<<<256, 256>>>(mask, (BATCH * NSEQ * NSEQ) / 4);

    conv_split<<<MROWS + 4 * DIMF, 256>>>(x, Wq, Wk, Wv, Wo);

    gemm_fp16<0><<<dim3(8, 32, 3), 256, GEMM_SMEM>>>(nullptr, nullptr);

    flash_fp16<<<dim3(NSEQ / 128, BATCH * NH), 128, FLASH_SMEM_B>>>(mask);

    gemm_fp16<1><<<dim3(8, 32), 256, GEMM_SMEM>>>(bo, out);
}

// round 16
// speedup vs baseline: 7.0087x; 1.0493x over previous
#include <cuda_runtime.h>
#include <cuda_fp16.h>
#include <math.h>
#include <stdint.h>

#define BATCH 2
#define NSEQ  2048
#define DIMF  1024
#define NH    16
#define HD    64
#define MROWS (BATCH * NSEQ)   // 4096

// fp16 attention operands (Q carries log2e/64 factor)
__device__ __half g_q16 [BATCH * NH * NSEQ * HD];
__device__ __half g_k16 [BATCH * NH * NSEQ * HD];
__device__ __half g_vt16[BATCH * NH * HD * NSEQ];   // [b,h,d,seq]

// fp16 GEMM operands
__device__ __half g_x16[(size_t)MROWS * DIMF];
__device__ __half g_o16[(size_t)MROWS * DIMF];      // flash output, gathered
__device__ __half g_wh [(size_t)4 * DIMF * DIMF];

__device__ int g_mask_nz = 0;   // static init; atomicOr is idempotent per fixed mask

#define LOG2E 1.4426950408889634f

// ---------------------------------------------------------------------------
// helpers
// ---------------------------------------------------------------------------
__device__ __forceinline__ uint32_t saddr(const void* p) {
    return (uint32_t)__cvta_generic_to_shared(p);
}
__device__ __forceinline__ float ex2f(float x) {
    float y;
    asm("ex2.approx.ftz.f32 %0, %1;" : "=f"(y) : "f"(x));
    return y;
}
__device__ __forceinline__ uint32_t packh2(float a, float b) {
    __half2 h = __floats2half2_rn(a, b);
    return *(uint32_t*)&h;
}
__device__ __forceinline__ void ldsm_x4(uint32_t r[4], uint32_t a) {
    asm volatile("ldmatrix.sync.aligned.m8n8.x4.shared.b16 {%0,%1,%2,%3}, [%4];"
                 : "=r"(r[0]), "=r"(r[1]), "=r"(r[2]), "=r"(r[3]) : "r"(a));
}
__device__ __forceinline__ void mma16h(float c[4], const uint32_t a[4], const uint32_t b[2]) {
    asm volatile(
        "mma.sync.aligned.m16n8k16.row.col.f32.f16.f16.f32 "
        "{%0,%1,%2,%3}, {%4,%5,%6,%7}, {%8,%9}, {%0,%1,%2,%3};"
        : "+f"(c[0]), "+f"(c[1]), "+f"(c[2]), "+f"(c[3])
        : "r"(a[0]), "r"(a[1]), "r"(a[2]), "r"(a[3]), "r"(b[0]), "r"(b[1]));
}
__device__ __forceinline__ void cpasync16(uint32_t s, const void* g) {
    asm volatile("cp.async.cg.shared.global [%0], [%1], 16;" :: "r"(s), "l"(g) : "memory");
}
#define CP_COMMIT()  asm volatile("cp.async.commit_group;" ::: "memory")
#define CP_WAIT(n)   asm volatile("cp.async.wait_group %0;" :: "n"(n) : "memory")

// ---------------------------------------------------------------------------
// mask scan
// ---------------------------------------------------------------------------
__global__ void __launch_bounds__(256) mask_scan(const float* __restrict__ mask, int n4)
{
    const float4* m4 = (const float4*)mask;
    uint32_t acc = 0;
    for (int i = blockIdx.x * 256 + threadIdx.x; i < n4; i += gridDim.x * 256) {
        float4 v = m4[i];
        acc |= __float_as_uint(v.x) | __float_as_uint(v.y)
             | __float_as_uint(v.z) | __float_as_uint(v.w);
    }
    if (acc) atomicOr(&g_mask_nz, 1);
}

// ---------------------------------------------------------------------------
// Convert: x -> fp16; Wq/Wk/Wv/Wo -> fp16
// ---------------------------------------------------------------------------
__global__ void __launch_bounds__(256) conv_split(
    const float* __restrict__ x,
    const float* __restrict__ Wq, const float* __restrict__ Wk,
    const float* __restrict__ Wv, const float* __restrict__ Wo)
{
    const int row = blockIdx.x;
    const int c = threadIdx.x * 4;
    const float* src;
    __half* dst;
    if (row < MROWS) {
        src = x + (size_t)row * DIMF;
        dst = g_x16 + (size_t)row * DIMF;
    } else {
        int wi = (row - MROWS) >> 10, r = (row - MROWS) & 1023;
        const float* W = (wi == 0) ? Wq : (wi == 1) ? Wk : (wi == 2) ? Wv : Wo;
        src = W + (size_t)r * DIMF;
        dst = g_wh + ((size_t)wi * DIMF + r) * DIMF;
    }
    float4 v = *(const float4*)(src + c);
    __half2 p0; p0.x = __float2half(v.x); p0.y = __float2half(v.y);
    __half2 p1; p1.x = __float2half(v.z); p1.y = __float2half(v.w);
    *(__half2*)(dst + c)     = p0;
    *(__half2*)(dst + c + 2) = p1;
}

// ---------------------------------------------------------------------------
// fp16 GEMM (NT), 3-stage cp.async ring, one __syncthreads per stage.
// OUT=0: z=0/1 epilogue fuses RMSNorm+RoPE -> g_q16/g_k16 (fp16);
//        z=2 stores transposed fp16 V.
// OUT=1: bias add, fp32 out.
// ---------------------------------------------------------------------------
#define TILE_B   10240
#define NKSTAGES 32
#define GEMM_SMEM (3 * 2 * TILE_B)   // 61440 B

template <int OUT>
__global__ void __launch_bounds__(256, 2) gemm_fp16(
    const float* __restrict__ bias, float* __restrict__ Cout)
{
    constexpr int STAGE = 2 * TILE_B;
    extern __shared__ char smem[];
    const uint32_t sbase = saddr(smem);
    const int tid = threadIdx.x, warp = tid >> 5, lane = tid & 31;
    const int m0 = blockIdx.y * 128, n0 = blockIdx.x * 128;
    const int z = OUT ? 3 : blockIdx.z;

    const __half* A  = OUT ? g_o16 : g_x16;
    const __half* Bh = g_wh + (size_t)z * DIMF * DIMF;

    const int lrow = tid >> 1;
    const int lq   = (tid & 1) * 2;

    auto load_stage = [&](int s) {
        const uint32_t d0 = sbase + (s % 3) * STAGE + lrow * 80 + lq * 16;
        const int kc = s * 32 + lq * 8;
        const __half* pa = A  + (size_t)(m0 + lrow) * DIMF + kc;
        const __half* pb = Bh + (size_t)(n0 + lrow) * DIMF + kc;
        cpasync16(d0,          pa);   cpasync16(d0 + 16,          pa + 8);
        cpasync16(d0 + TILE_B, pb);   cpasync16(d0 + TILE_B + 16, pb + 8);
        CP_COMMIT();
    };

    float acc[2][8][4];
#pragma unroll
    for (int i = 0; i < 2; i++)
#pragma unroll
        for (int j = 0; j < 8; j++)
#pragma unroll
            for (int l = 0; l < 4; l++) acc[i][j][l] = 0.0f;

    const int mw = (warp >> 1) * 32;
    const int nw = (warp & 1) * 64;

    load_stage(0);
    load_stage(1);

    for (int s = 0; s < NKSTAGES; s++) {
        if (s == NKSTAGES - 1) CP_WAIT(0); else CP_WAIT(1);
        __syncthreads();

        const uint32_t base = sbase + (s % 3) * STAGE;
#pragma unroll
        for (int t = 0; t < 2; t++) {
            const int kk = t * 16;
            uint32_t a16[2][4];
#pragma unroll
            for (int mt = 0; mt < 2; mt++) {
                uint32_t addr = base + (mw + mt * 16 + (lane & 15)) * 80
                              + kk * 2 + ((lane >> 4) << 4);
                ldsm_x4(a16[mt], addr);
            }
#pragma unroll
            for (int p = 0; p < 4; p++) {
                uint32_t baddr = base + TILE_B
                               + (nw + p * 16 + (lane & 7) + ((lane >> 4) << 3)) * 80
                               + kk * 2 + (((lane >> 3) & 1) << 4);
                uint32_t bh4[4];
                ldsm_x4(bh4, baddr);
#pragma unroll
                for (int mt = 0; mt < 2; mt++) {
                    mma16h(acc[mt][2 * p],     a16[mt], bh4);
                    mma16h(acc[mt][2 * p + 1], a16[mt], bh4 + 2);
                }
            }
        }
        if (s + 2 < NKSTAGES) load_stage(s + 2);
    }

    // ---------------- epilogue ----------------
    const int cq = lane & 3;
    if (OUT) {
#pragma unroll
        for (int mt = 0; mt < 2; mt++)
#pragma unroll
            for (int nt = 0; nt < 8; nt++)
#pragma unroll
                for (int half = 0; half < 2; half++) {
                    int m = m0 + mw + mt * 16 + (lane >> 2) + half * 8;
                    int c = n0 + nw + nt * 8 + (cq << 1);
                    const float2 bb2 = *(const float2*)(bias + c);
                    float2 v = make_float2(acc[mt][nt][half * 2 + 0] + bb2.x,
                                           acc[mt][nt][half * 2 + 1] + bb2.y);
                    *(float2*)(Cout + (size_t)m * DIMF + c) = v;
                }
    } else if (z == 2) {
#pragma unroll
        for (int mt = 0; mt < 2; mt++)
#pragma unroll
            for (int nt = 0; nt < 8; nt++)
#pragma unroll
                for (int half = 0; half < 2; half++) {
                    int m = m0 + mw + mt * 16 + (lane >> 2) + half * 8;
                    int bb = m >> 11, n = m & (NSEQ - 1);
                    int c = n0 + nw + nt * 8 + (cq << 1);
                    int h = c >> 6, d = c & (HD - 1);
                    __half* basep = g_vt16 + (((size_t)(bb * NH + h) * HD + d) * NSEQ) + n;
                    basep[0]    = __float2half(acc[mt][nt][half * 2 + 0]);
                    basep[NSEQ] = __float2half(acc[mt][nt][half * 2 + 1]);
                }
    } else {
        // fused RMSNorm + RoPE (z=0 -> Q with log2e/64, z=1 -> K)
        __half* dstbase = (z == 0) ? g_q16 : g_k16;
        const float post = (z == 0) ? (LOG2E / 64.0f) : 1.0f;
        const int head = (n0 + nw) >> 6;   // warp's 64-col slice = one head
#pragma unroll
        for (int mt = 0; mt < 2; mt++) {
#pragma unroll
            for (int half = 0; half < 2; half++) {
                int m = m0 + mw + mt * 16 + (lane >> 2) + half * 8;
                int bb = m >> 11, n = m & (NSEQ - 1);
                float ss = 0.0f;
#pragma unroll
                for (int nt = 0; nt < 8; nt++) {
                    float v0 = acc[mt][nt][half * 2 + 0];
                    float v1 = acc[mt][nt][half * 2 + 1];
                    ss += v0 * v0 + v1 * v1;
                }
                ss += __shfl_xor_sync(0xffffffffu, ss, 1, 4);
                ss += __shfl_xor_sync(0xffffffffu, ss, 2, 4);
                float rn = rsqrtf(ss * (1.0f / 64.0f) + 1e-5f);
                __half* dst = dstbase + (((size_t)(bb * NH + head) * NSEQ + n) << 6);
#pragma unroll
                for (int nt = 0; nt < 8; nt++) {
                    int i = nt * 4 + cq;   // rope pair index (d = 2i)
                    float ifr = exp2f((float)i * (-2.0f / 64.0f) * 13.287712379549449f);
                    float ang = (float)n * ifr;
                    float sn, cs;
                    sincosf(ang, &sn, &cs);
                    float x0 = acc[mt][nt][half * 2 + 0] * rn;
                    float x1 = acc[mt][nt][half * 2 + 1] * rn;
                    __half2 y;
                    y.x = __float2half((x0 * cs - x1 * sn) * post);
                    y.y = __float2half((x1 * cs + x0 * sn) * post);
                    *(__half2*)(dst + nt * 8 + (cq << 1)) = y;
                }
            }
        }
    }
}

// ---------------------------------------------------------------------------
// Flash attention, fp16 m16n8k16. 128 threads (4 warps), 32 q-rows/warp.
// 4-buffer KV ring, 2-stage-ahead cp.async prefetch, ONE barrier per kt.
// REGISTER-RESIDENT P: S accumulator fragments convert in-register to the
// PV A-operand (FA-2 layout identity) -> no P smem roundtrip at all.
// Q stages through ring buf 2 (free until kt=2 prefetch, post-barrier).
// ---------------------------------------------------------------------------
#define KROW_B   144
#define KVBUF_B  (2 * 64 * KROW_B)            // 18432
#define FLASH_SMEM_B (4 * KVBUF_B)            // 73728

__global__ void __launch_bounds__(128) flash_fp16(const float* __restrict__ mask)
{
    extern __shared__ char smf[];
    const uint32_t sbase = saddr(smf);

    const int tid = threadIdx.x, warp = tid >> 5, lane = tid & 31;
    const int bh = blockIdx.y, b = bh >> 4, h = bh & 15;
    const int q0 = blockIdx.x * 128;
    const int mnz = g_mask_nz;

    const __half* Qg  = g_q16  + ((size_t)bh * NSEQ + q0) * HD;
    const __half* Kg  = g_k16  + (size_t)bh * NSEQ * HD;
    const __half* Vtg = g_vt16 + (size_t)bh * HD * NSEQ;
    const float*  Mg  = mask + (size_t)b * NSEQ * NSEQ + (size_t)q0 * NSEQ;

    auto load_kv = [&](int kt) {
        const int k0 = kt * 64;
        const uint32_t kb = sbase + (kt & 3) * KVBUF_B;
        const int row = tid >> 3;
        const int ch  = (tid & 7) * 16;
#pragma unroll
        for (int i = 0; i < 4; i++) {
            int rr = row + i * 16;
            cpasync16(kb + rr * KROW_B + ch,
                      (const char*)(Kg + (size_t)(k0 + rr) * HD) + ch);
            cpasync16(kb + 64 * KROW_B + rr * KROW_B + ch,
                      (const char*)(Vtg + (size_t)rr * NSEQ + k0) + ch);
        }
        CP_COMMIT();
    };

    load_kv(0);
    load_kv(1);

    // stage Q through ring buffer 2 (128 rows x 128B, stride 144)
    const uint32_t qstage = sbase + 2 * KVBUF_B;
    {
        const int row = tid >> 3;
        const int ch  = (tid & 7) * 16;
#pragma unroll
        for (int i = 0; i < 8; i++) {
            int rr = row + i * 16;
            *(uint4*)(smf + 2 * KVBUF_B + rr * KROW_B + ch) =
                *(const uint4*)((const char*)(Qg + (size_t)rr * HD) + ch);
        }
    }
    __syncthreads();
    uint32_t qf[2][4][4];
#pragma unroll
    for (int mt = 0; mt < 2; mt++) {
        int row = warp * 32 + mt * 16 + (lane & 15);
#pragma unroll
        for (int t = 0; t < 4; t++)
            ldsm_x4(qf[mt][t], qstage + row * KROW_B + t * 32 + ((lane >> 4) << 4));
    }
    __syncthreads();   // all warps done with Q before kt=2 prefetch overwrites buf 2

    const int r  = lane >> 2;
    const int cq = lane & 3;

    float mrow[2][2] = {{-INFINITY, -INFINITY}, {-INFINITY, -INFINITY}};
    float lrow[2][2] = {{0.0f, 0.0f}, {0.0f, 0.0f}};
    float o[2][8][4];
#pragma unroll
    for (int mt = 0; mt < 2; mt++)
#pragma unroll
        for (int nt = 0; nt < 8; nt++)
#pragma unroll
            for (int j = 0; j < 4; j++) o[mt][nt][j] = 0.0f;

    for (int kt = 0; kt < NSEQ / 64; kt++) {
        const int k0 = kt * 64;
        if (kt + 2 < NSEQ / 64)      { load_kv(kt + 2); CP_WAIT(2); }
        else if (kt + 2 == NSEQ / 64) CP_WAIT(1);
        else                          CP_WAIT(0);
        __syncthreads();

        const uint32_t kbuf = sbase + (kt & 3) * KVBUF_B;
        const uint32_t vbuf = kbuf + 64 * KROW_B;

        // S = Q K^T (log2 domain)
        float s[2][8][4];
#pragma unroll
        for (int mt = 0; mt < 2; mt++)
#pragma unroll
            for (int nt = 0; nt < 8; nt++)
#pragma unroll
                for (int j = 0; j < 4; j++) s[mt][nt][j] = 0.0f;

#pragma unroll
        for (int t = 0; t < 4; t++) {
            uint32_t bb[8][2];
#pragma unroll
            for (int p = 0; p < 4; p++) {
                uint32_t addr = kbuf + (p * 16 + (lane & 7) + ((lane >> 4) << 3)) * KROW_B
                              + t * 32 + (((lane >> 3) & 1) << 4);
                uint32_t r4[4];
                ldsm_x4(r4, addr);
                bb[2 * p][0] = r4[0]; bb[2 * p][1] = r4[1];
                bb[2 * p + 1][0] = r4[2]; bb[2 * p + 1][1] = r4[3];
            }
#pragma unroll
            for (int nt = 0; nt < 8; nt++) {
                mma16h(s[0][nt], qf[0][t], bb[nt]);
                mma16h(s[1][nt], qf[1][t], bb[nt]);
            }
        }

        // softmax -> register-resident P fragments pf[mt][t][4]
        uint32_t pf[2][4][4];
        if (!mnz) {
            // FAST PATH: p = 2^S (|S| <= log2e), no max tracking / rescale
#pragma unroll
            for (int mt = 0; mt < 2; mt++) {
                float sum0 = 0.0f, sum1 = 0.0f;
#pragma unroll
                for (int nt = 0; nt < 8; nt++) {
                    float p0 = ex2f(s[mt][nt][0]);
                    float p1 = ex2f(s[mt][nt][1]);
                    float p2 = ex2f(s[mt][nt][2]);
                    float p3 = ex2f(s[mt][nt][3]);
                    sum0 += p0 + p1;
                    sum1 += p2 + p3;
                    pf[mt][nt >> 1][(nt & 1) * 2 + 0] = packh2(p0, p1);
                    pf[mt][nt >> 1][(nt & 1) * 2 + 1] = packh2(p2, p3);
                }
                sum0 += __shfl_xor_sync(0xffffffffu, sum0, 1, 4);
                sum0 += __shfl_xor_sync(0xffffffffu, sum0, 2, 4);
                sum1 += __shfl_xor_sync(0xffffffffu, sum1, 1, 4);
                sum1 += __shfl_xor_sync(0xffffffffu, sum1, 2, 4);
                lrow[mt][0] += sum0;
                lrow[mt][1] += sum1;
            }
        } else {
            // SLOW PATH: online softmax in log2 domain
#pragma unroll
            for (int mt = 0; mt < 2; mt++) {
                float p01[8][2], p23[8][2];
#pragma unroll
                for (int half = 0; half < 2; half++) {
                    float sim[16];
                    float vmax = -INFINITY;
                    const float* mp = Mg + (size_t)(warp * 32 + mt * 16 + r + half * 8) * NSEQ + k0;
#pragma unroll
                    for (int nt = 0; nt < 8; nt++) {
                        float2 mk = *(const float2*)(mp + nt * 8 + 2 * cq);
                        sim[2 * nt]     = fmaf(mk.x, LOG2E, s[mt][nt][half * 2 + 0]);
                        sim[2 * nt + 1] = fmaf(mk.y, LOG2E, s[mt][nt][half * 2 + 1]);
                        vmax = fmaxf(vmax, fmaxf(sim[2 * nt], sim[2 * nt + 1]));
                    }
                    vmax = fmaxf(vmax, __shfl_xor_sync(0xffffffffu, vmax, 1, 4));
                    vmax = fmaxf(vmax, __shfl_xor_sync(0xffffffffu, vmax, 2, 4));
                    float mnew = fmaxf(mrow[mt][half], vmax);
                    float corr = ex2f(mrow[mt][half] - mnew);
                    float sum = 0.0f;
#pragma unroll
                    for (int nt = 0; nt < 8; nt++) {
                        float p0 = ex2f(sim[2 * nt]     - mnew);
                        float p1 = ex2f(sim[2 * nt + 1] - mnew);
                        sum += p0 + p1;
                        if (half == 0) { p01[nt][0] = p0; p01[nt][1] = p1; }
                        else           { p23[nt][0] = p0; p23[nt][1] = p1; }
                    }
                    sum += __shfl_xor_sync(0xffffffffu, sum, 1, 4);
                    sum += __shfl_xor_sync(0xffffffffu, sum, 2, 4);
                    lrow[mt][half] = lrow[mt][half] * corr + sum;
                    mrow[mt][half] = mnew;
#pragma unroll
                    for (int nt = 0; nt < 8; nt++) {
                        o[mt][nt][half * 2 + 0] *= corr;
                        o[mt][nt][half * 2 + 1] *= corr;
                    }
                }
#pragma unroll
                for (int nt = 0; nt < 8; nt++) {
                    pf[mt][nt >> 1][(nt & 1) * 2 + 0] = packh2(p01[nt][0], p01[nt][1]);
                    pf[mt][nt >> 1][(nt & 1) * 2 + 1] = packh2(p23[nt][0], p23[nt][1]);
                }
            }
        }

        // O += P V  (P straight from registers)
#pragma unroll
        for (int t = 0; t < 4; t++) {
            uint32_t bb[8][2];
#pragma unroll
            for (int p = 0; p < 4; p++) {
                uint32_t addr = vbuf + (p * 16 + (lane & 7) + ((lane >> 4) << 3)) * KROW_B
                              + t * 32 + (((lane >> 3) & 1) << 4);
                uint32_t r4[4];
                ldsm_x4(r4, addr);
                bb[2 * p][0] = r4[0]; bb[2 * p][1] = r4[1];
                bb[2 * p + 1][0] = r4[2]; bb[2 * p + 1][1] = r4[3];
            }
#pragma unroll
            for (int nt = 0; nt < 8; nt++) {
                mma16h(o[0][nt], pf[0][t], bb[nt]);
                mma16h(o[1][nt], pf[1][t], bb[nt]);
            }
        }
    }

    // epilogue: single fp16 into gathered layout [b*2048+seq][h*64+d]
#pragma unroll
    for (int mt = 0; mt < 2; mt++) {
        float inv0 = 1.0f / lrow[mt][0], inv1 = 1.0f / lrow[mt][1];
#pragma unroll
        for (int nt = 0; nt < 8; nt++) {
            int col = h * HD + nt * 8 + 2 * cq;
#pragma unroll
            for (int half = 0; half < 2; half++) {
                int m = b * NSEQ + q0 + warp * 32 + mt * 16 + r + half * 8;
                float inv = half ? inv1 : inv0;
                __half2 ph;
                ph.x = __float2half(o[mt][nt][half * 2 + 0] * inv);
                ph.y = __float2half(o[mt][nt][half * 2 + 1] * inv);
                *(__half2*)(g_o16 + (size_t)m * DIMF + col) = ph;
            }
        }
    }
}

// ---------------------------------------------------------------------------
// Launch
// ---------------------------------------------------------------------------
extern "C" void kernel_launch(void* const* d_in, const int* in_sizes, int n_in,
                              void* d_out, int out_size)
{
    const float* x    = (const float*)d_in[0];
    const float* mask = (const float*)d_in[1];
    const float* Wq   = (const float*)d_in[2];
    const float* Wk   = (const float*)d_in[3];
    const float* Wv   = (const float*)d_in[4];
    const float* Wo   = (const float*)d_in[5];
    const float* bo   = (const float*)d_in[6];
    float* out = (float*)d_out;

    cudaFuncSetAttribute(gemm_fp16<0>, cudaFuncAttributeMaxDynamicSharedMemorySize, GEMM_SMEM);
    cudaFuncSetAttribute(gemm_fp16<1>, cudaFuncAttributeMaxDynamicSharedMemorySize, GEMM_SMEM);
    cudaFuncSetAttribute(flash_fp16,   cudaFuncAttributeMaxDynamicSharedMemorySize, FLASH_SMEM_B);

    mask_scan<<<256, 256>>>(mask, (BATCH * NSEQ * NSEQ) / 4);

    conv_split<<<MROWS + 4 * DIMF, 256>>>(x, Wq, Wk, Wv, Wo);

    gemm_fp16<0><<<dim3(8, 32, 3), 256, GEMM_SMEM>>>(nullptr, nullptr);

    flash_fp16<<<dim3(NSEQ / 128, BATCH * NH), 128, FLASH_SMEM_B>>>(mask);

    gemm_fp16<1><<<dim3(8, 32), 256, GEMM_SMEM>>>(bo, out);
}